// round 4
// baseline (speedup 1.0000x reference)
#include <cuda_runtime.h>
#include <cuda_bf16.h>
#include <math.h>
#include <stdint.h>

// ---------------- Problem constants ----------------
#define DIMV    512
#define HEADS   16
#define DHEAD   32
#define NWIN    512          // B * RH * RW
#define NTOK    65           // 1 region + 64 local
#define NROWS   (NWIN*NTOK)  // 33280 (= 260 * 128)
#define NB      8
#define DEPTH   4
#define QSCALE  0.17677669529663687f
#define LOCAL_ELEMS (8*64*64*512)

// ---------------- helpers ----------------
__device__ __forceinline__ uint32_t smem_to_u32(const void* p) {
    uint32_t a;
    asm("{ .reg .u64 t; cvta.to.shared.u64 t, %1; cvt.u32.u64 %0, t; }" : "=r"(a) : "l"(p));
    return a;
}
__device__ __forceinline__ void cp16(uint32_t dst, const void* src) {
    asm volatile("cp.async.cg.shared.global [%0], [%1], 16;\n" :: "r"(dst), "l"(src));
}
__device__ __forceinline__ void cp_commit() { asm volatile("cp.async.commit_group;\n" ::: "memory"); }

__device__ __forceinline__ void split_bf16(float x, __nv_bfloat16& h, __nv_bfloat16& l) {
    h = __float2bfloat16(x);
    l = __float2bfloat16(x - __bfloat162float(h));
}
__device__ __forceinline__ float gelu_exact(float x) {
    return 0.5f * x * (1.0f + erff(x * 0.70710678118654752f));
}

// ================= Scratch (device globals) =================
// Activations with hi/lo split stored as [row][2K]: hi in [0,K), lo in [K,2K)
__device__ __align__(16) float         g_xw  [NROWS*DIMV];
__device__ __align__(16) __nv_bfloat16 g_h   [NROWS*2*DIMV];
__device__ __align__(16) float         g_qkv [NROWS*3*DIMV];
__device__ __align__(16) __nv_bfloat16 g_o   [NROWS*2*DIMV];
__device__ __align__(16) __nv_bfloat16 g_m1  [NROWS*2*4*DIMV];
__device__ __align__(16) float         g_bias[HEADS*NTOK*NTOK];
__device__ __align__(16) float         g_xr  [NWIN*DIMV];
__device__ __align__(16) __nv_bfloat16 g_hr  [NWIN*2*DIMV];
__device__ __align__(16) float         g_qkvr[NWIN*3*DIMV];
__device__ __align__(16) __nv_bfloat16 g_or  [NWIN*2*DIMV];
// Weights transposed+split: [N][2K] (hi [0,K), lo [K,2K))
__device__ __align__(16) __nv_bfloat16 g_Wqkv[DEPTH*3*DIMV*2*DIMV];
__device__ __align__(16) __nv_bfloat16 g_Wout[DEPTH*DIMV*2*DIMV];
__device__ __align__(16) __nv_bfloat16 g_W1  [DEPTH*4*DIMV*2*DIMV];
__device__ __align__(16) __nv_bfloat16 g_W2  [DEPTH*DIMV*2*4*DIMV];

// ================= small kernels =================
__global__ void pack_kernel(const float* __restrict__ local_t, const float* __restrict__ region_t) {
    int idx = blockIdx.x * blockDim.x + threadIdx.x;
    if (idx >= NROWS*DIMV) return;
    int d = idx & 511, row = idx >> 9;
    int win = row / NTOK, t = row - win*NTOK;
    float v;
    if (t == 0) v = region_t[win*DIMV + d];
    else {
        int a = t - 1, p1 = a >> 3, p2 = a & 7;
        int b = win >> 6, rh = (win >> 3) & 7, rw = win & 7;
        v = local_t[(((b*64) + (rh*8 + p1))*64 + (rw*8 + p2))*DIMV + d];
    }
    g_xw[idx] = v;
}

__global__ void unpack_kernel(float* __restrict__ out) {
    int idx = blockIdx.x * blockDim.x + threadIdx.x;
    if (idx >= NROWS*DIMV) return;
    if (idx < LOCAL_ELEMS) {
        int d = idx & 511, p = idx >> 9;
        int col = p & 63, rowi = (p >> 6) & 63, b = p >> 12;
        int rh = rowi >> 3, p1 = rowi & 7, rw = col >> 3, p2 = col & 7;
        int win = b*64 + rh*8 + rw, t = 1 + p1*8 + p2;
        out[idx] = g_xw[(win*NTOK + t)*DIMV + d];
    } else {
        int r = idx - LOCAL_ELEMS, w = r >> 9, d = r & 511;
        out[idx] = g_xw[(w*NTOK)*DIMV + d];
    }
}

__global__ void bias_kernel(const float* __restrict__ emb) {
    int idx = blockIdx.x * blockDim.x + threadIdx.x;
    if (idx >= HEADS*NTOK*NTOK) return;
    int h = idx / (NTOK*NTOK);
    int r = idx - h*NTOK*NTOK;
    int i = r / NTOK, j = r - i*NTOK;
    float v = 0.f;
    if (i > 0 && j > 0) {
        int a = i - 1, b = j - 1;
        int r0 = (a >> 3) - (b >> 3) + 7;
        int r1 = (a & 7) - (b & 7) + 7;
        v = emb[(r0 + r1*15)*HEADS + h];
    }
    g_bias[idx] = v;
}

__global__ void gather_region() {
    int idx = blockIdx.x * blockDim.x + threadIdx.x;
    if (idx >= NWIN*DIMV) return;
    int w = idx >> 9, d = idx & 511;
    g_xr[idx] = g_xw[(w*NTOK)*DIMV + d];
}
__global__ void scatter_region() {
    int idx = blockIdx.x * blockDim.x + threadIdx.x;
    if (idx >= NWIN*DIMV) return;
    int w = idx >> 9, d = idx & 511;
    g_xw[(w*NTOK)*DIMV + d] = g_xr[idx];
}

// transpose + split weights: W[K,N] fp32 -> out[n][2K] bf16 (hi then lo)
__global__ void wsplit(const float* __restrict__ W, __nv_bfloat16* __restrict__ OutW, int K, int N) {
    int idx = blockIdx.x * blockDim.x + threadIdx.x;
    if (idx >= K*N) return;
    int n = idx / K, k = idx - n*K;
    float v = W[(size_t)k*N + n];
    __nv_bfloat16 h, l; split_bf16(v, h, l);
    OutW[(size_t)n*2*K + k]     = h;
    OutW[(size_t)n*2*K + K + k] = l;
}

// LayerNorm: 128 threads per 512-wide row, emits split bf16 into [row][1024]
__global__ void ln_kernel(const float* __restrict__ x, const float* __restrict__ g,
                          const float* __restrict__ b, __nv_bfloat16* __restrict__ y) {
    int row = blockIdx.x;
    int t = threadIdx.x;
    const float4* xv = (const float4*)(x + (size_t)row*DIMV);
    float4 v = xv[t];
    float s  = v.x + v.y + v.z + v.w;
    float s2 = v.x*v.x + v.y*v.y + v.z*v.z + v.w*v.w;
    #pragma unroll
    for (int off = 16; off; off >>= 1) {
        s  += __shfl_xor_sync(0xffffffffu, s,  off);
        s2 += __shfl_xor_sync(0xffffffffu, s2, off);
    }
    __shared__ float sh[8];
    int wid = t >> 5, lane = t & 31;
    if (lane == 0) { sh[wid] = s; sh[4 + wid] = s2; }
    __syncthreads();
    float st  = sh[0] + sh[1] + sh[2] + sh[3];
    float s2t = sh[4] + sh[5] + sh[6] + sh[7];
    float mean = st * (1.f/512.f);
    float var  = s2t * (1.f/512.f) - mean*mean;
    float rstd = rsqrtf(var + 1e-3f);
    float4 gg = ((const float4*)g)[t];
    float4 bb = ((const float4*)b)[t];
    float o0 = (v.x - mean)*rstd*gg.x + bb.x;
    float o1 = (v.y - mean)*rstd*gg.y + bb.y;
    float o2 = (v.z - mean)*rstd*gg.z + bb.z;
    float o3 = (v.w - mean)*rstd*gg.w + bb.w;
    __nv_bfloat16 h0,h1,h2,h3,l0,l1,l2,l3;
    split_bf16(o0,h0,l0); split_bf16(o1,h1,l1); split_bf16(o2,h2,l2); split_bf16(o3,h3,l3);
    __nv_bfloat162* pH = (__nv_bfloat162*)(y + (size_t)row*1024 + 4*t);
    __nv_bfloat162* pL = (__nv_bfloat162*)(y + (size_t)row*1024 + 512 + 4*t);
    __nv_bfloat162 a0; a0.x = h0; a0.y = h1;
    __nv_bfloat162 a1; a1.x = h2; a1.y = h3;
    __nv_bfloat162 c0; c0.x = l0; c0.y = l1;
    __nv_bfloat162 c1; c1.x = l2; c1.y = l3;
    pH[0] = a0; pH[1] = a1;
    pL[0] = c0; pL[1] = c1;
}

// ================= Attention (fp32 in smem) =================
template<int NT>
__global__ __launch_bounds__(256) void attn_kernel(const float* __restrict__ qkv,
                                                   const float* __restrict__ biasTab,
                                                   __nv_bfloat16* __restrict__ o) {
    __shared__ float qs[NT][33];
    __shared__ float ks[NT][33];
    __shared__ float vs[NT][33];
    __shared__ float ss[NT][NT + 1];
    const int grp = blockIdx.x;
    const int h   = blockIdx.y;
    const int base = grp * NT;
    const int tid = threadIdx.x;

    for (int p = tid; p < NT * DHEAD; p += 256) {
        int i = p >> 5, d = p & 31;
        const float* row = qkv + (size_t)(base + i) * (3*DIMV) + h*DHEAD + d;
        qs[i][d] = row[0] * QSCALE;
        ks[i][d] = row[DIMV];
        vs[i][d] = row[2*DIMV];
    }
    __syncthreads();

    for (int p = tid; p < NT * NT; p += 256) {
        int i = p / NT, j = p - i*NT;
        float acc = 0.f;
        #pragma unroll
        for (int d = 0; d < 32; d++) acc += qs[i][d] * ks[j][d];
        if (biasTab) acc += biasTab[(h*NT + i)*NT + j];
        ss[i][j] = acc;
    }
    __syncthreads();

    int wid = tid >> 5, lane = tid & 31;
    for (int i = wid; i < NT; i += 8) {
        float m = -1e30f;
        for (int j = lane; j < NT; j += 32) m = fmaxf(m, ss[i][j]);
        #pragma unroll
        for (int off = 16; off; off >>= 1) m = fmaxf(m, __shfl_xor_sync(0xffffffffu, m, off));
        float sum = 0.f;
        for (int j = lane; j < NT; j += 32) { float e = __expf(ss[i][j] - m); ss[i][j] = e; sum += e; }
        #pragma unroll
        for (int off = 16; off; off >>= 1) sum += __shfl_xor_sync(0xffffffffu, sum, off);
        float inv = 1.f / sum;
        for (int j = lane; j < NT; j += 32) ss[i][j] *= inv;
    }
    __syncthreads();

    for (int p = tid; p < NT * DHEAD; p += 256) {
        int i = p >> 5, d = p & 31;
        float acc = 0.f;
        #pragma unroll 5
        for (int j = 0; j < NT; j++) acc += ss[i][j] * vs[j][d];
        __nv_bfloat16 hh, ll; split_bf16(acc, hh, ll);
        size_t ob = (size_t)(base + i) * 1024 + h*DHEAD + d;
        o[ob] = hh; o[ob + 512] = ll;
    }
}

// ================= bf16 split GEMM via mma.sync =================
// C[M,N] = sum_k A[m,k]*B[n,k] with fp32-level accuracy via 3-term bf16 split.
// CTA tile 128x256, BK=32, 4-stage cp.async, 8 warps each 64x64 (m16n8k16 atoms).
#define BM 128
#define BN 256
#define BK 32
#define NSTG 4
#define ROWB 80                         // padded smem row bytes (64B data + 16B pad)
#define STG_BYTES ((BM + BN) * ROWB)    // 30720
#define SMEM_GEMM (NSTG * STG_BYTES)    // 122880

__global__ __launch_bounds__(256, 1) void gemm_mma(
    const __nv_bfloat16* __restrict__ A, const __nv_bfloat16* __restrict__ B,
    const float* __restrict__ bias, float* __restrict__ C,
    __nv_bfloat16* __restrict__ O, int N, int K, int epi)
{
    extern __shared__ char smem[];
    const uint32_t sb = smem_to_u32(smem);
    const int tid = threadIdx.x;
    const int bm = blockIdx.y * BM;
    const int bn = blockIdx.x * BN;
    const int lda = 2*K;
    const int cpt = K / BK;
    const int total = 3 * cpt;

    const int wid = tid >> 5, lane = tid & 31;
    const int wm = wid & 1, wn = wid >> 1;     // warp grid 2(M) x 4(N), warp tile 64x64

    float acc[4][8][4];
    #pragma unroll
    for (int mi = 0; mi < 4; mi++)
        #pragma unroll
        for (int ni = 0; ni < 8; ni++)
            #pragma unroll
            for (int r = 0; r < 4; r++) acc[mi][ni][r] = 0.f;

    // chunk loader: A 128 rows x 64B, B 256 rows x 64B
    auto load_chunk = [&](int c) {
        int t  = c / cpt, kk = c - t*cpt;
        int a_col = ((t == 2) ? K : 0) + kk*BK;
        int b_col = ((t == 1) ? K : 0) + kk*BK;
        uint32_t stA = sb + (c % NSTG) * STG_BYTES;
        uint32_t stB = stA + BM * ROWB;
        #pragma unroll
        for (int i = 0; i < 2; i++) {          // A: 512 segments
            int s = tid + i*256;
            int row = s >> 2, seg = s & 3;
            cp16(stA + row*ROWB + seg*16, A + (size_t)(bm + row)*lda + a_col + seg*8);
        }
        #pragma unroll
        for (int i = 0; i < 4; i++) {          // B: 1024 segments
            int s = tid + i*256;
            int row = s >> 2, seg = s & 3;
            cp16(stB + row*ROWB + seg*16, B + (size_t)(bn + row)*lda + b_col + seg*8);
        }
        cp_commit();
    };

    load_chunk(0); load_chunk(1); load_chunk(2);

    for (int c = 0; c < total; c++) {
        if (c <= total - 3)      asm volatile("cp.async.wait_group 2;\n" ::: "memory");
        else if (c == total - 2) asm volatile("cp.async.wait_group 1;\n" ::: "memory");
        else                     asm volatile("cp.async.wait_group 0;\n" ::: "memory");
        __syncthreads();
        if (c + 3 < total) load_chunk(c + 3);

        uint32_t stA = sb + (c % NSTG) * STG_BYTES;
        uint32_t stB = stA + BM * ROWB;
        #pragma unroll
        for (int ks = 0; ks < 2; ks++) {
            uint32_t a[4][4];
            #pragma unroll
            for (int mi = 0; mi < 4; mi++) {
                uint32_t addr = stA + (wm*64 + mi*16 + (lane & 15))*ROWB + ((lane >> 4)*16 + ks*32);
                asm volatile("ldmatrix.sync.aligned.m8n8.x4.shared.b16 {%0,%1,%2,%3}, [%4];"
                    : "=r"(a[mi][0]), "=r"(a[mi][1]), "=r"(a[mi][2]), "=r"(a[mi][3]) : "r"(addr));
            }
            uint32_t b[8][2];
            #pragma unroll
            for (int ni = 0; ni < 8; ni++) {
                uint32_t addr = stB + (wn*64 + ni*8 + (lane & 7))*ROWB + (((lane >> 3) & 1)*16 + ks*32);
                asm volatile("ldmatrix.sync.aligned.m8n8.x2.shared.b16 {%0,%1}, [%2];"
                    : "=r"(b[ni][0]), "=r"(b[ni][1]) : "r"(addr));
            }
            #pragma unroll
            for (int mi = 0; mi < 4; mi++)
                #pragma unroll
                for (int ni = 0; ni < 8; ni++) {
                    asm volatile(
                        "mma.sync.aligned.m16n8k16.row.col.f32.bf16.bf16.f32 "
                        "{%0,%1,%2,%3}, {%4,%5,%6,%7}, {%8,%9}, {%0,%1,%2,%3};"
                        : "+f"(acc[mi][ni][0]), "+f"(acc[mi][ni][1]),
                          "+f"(acc[mi][ni][2]), "+f"(acc[mi][ni][3])
                        : "r"(a[mi][0]), "r"(a[mi][1]), "r"(a[mi][2]), "r"(a[mi][3]),
                          "r"(b[ni][0]), "r"(b[ni][1]));
                }
        }
    }

    // ---- epilogue ----
    const int g = lane >> 2, tig = lane & 3;
    #pragma unroll
    for (int mi = 0; mi < 4; mi++) {
        #pragma unroll
        for (int ni = 0; ni < 8; ni++) {
            int r0 = bm + wm*64 + mi*16 + g;
            int cc = bn + wn*64 + ni*8 + tig*2;
            #pragma unroll
            for (int half = 0; half < 2; half++) {
                int r = r0 + half*8;
                float v0 = acc[mi][ni][half*2 + 0];
                float v1 = acc[mi][ni][half*2 + 1];
                if (epi == 0) {
                    float2 st; st.x = v0; st.y = v1;
                    *(float2*)&C[(size_t)r*N + cc] = st;
                } else if (epi == 1) {
                    float2 bi  = *(const float2*)&bias[cc];
                    float2 res = *(const float2*)&C[(size_t)r*N + cc];
                    float2 st; st.x = v0 + bi.x + res.x; st.y = v1 + bi.y + res.y;
                    *(float2*)&C[(size_t)r*N + cc] = st;
                } else {
                    float2 bi = *(const float2*)&bias[cc];
                    float g0 = gelu_exact(v0 + bi.x);
                    float g1 = gelu_exact(v1 + bi.y);
                    __nv_bfloat16 h0,h1,l0,l1;
                    split_bf16(g0, h0, l0); split_bf16(g1, h1, l1);
                    __nv_bfloat162 sh; sh.x = h0; sh.y = h1;
                    __nv_bfloat162 sl; sl.x = l0; sl.y = l1;
                    *(__nv_bfloat162*)&O[(size_t)r*2*N + cc]     = sh;
                    *(__nv_bfloat162*)&O[(size_t)r*2*N + N + cc] = sl;
                }
            }
        }
    }
}

// ================= Host driver =================
extern "C" void kernel_launch(void* const* d_in, const int* in_sizes, int n_in,
                              void* d_out, int out_size) {
    const float* local_t  = (const float*)d_in[0];
    const float* region_t = (const float*)d_in[1];
    const float* emb      = (const float*)d_in[2];
    const float* attn_g   = (const float*)d_in[3];
    const float* attn_b   = (const float*)d_in[4];
    const float* wqkv     = (const float*)d_in[5];
    const float* wout     = (const float*)d_in[6];
    const float* bout     = (const float*)d_in[7];
    const float* mlp_g    = (const float*)d_in[8];
    const float* mlp_b    = (const float*)d_in[9];
    const float* w1       = (const float*)d_in[10];
    const float* b1       = (const float*)d_in[11];
    const float* w2       = (const float*)d_in[12];
    const float* b2       = (const float*)d_in[13];
    float* out = (float*)d_out;

    cudaFuncSetAttribute(gemm_mma, cudaFuncAttributeMaxDynamicSharedMemorySize, SMEM_GEMM);

    float *xw, *qkv, *biasT, *xr, *qkvr;
    __nv_bfloat16 *h, *o, *m1, *hr, *orr;
    __nv_bfloat16 *Wqkv, *Wout, *W1, *W2;
    cudaGetSymbolAddress((void**)&xw,   g_xw);
    cudaGetSymbolAddress((void**)&h,    g_h);
    cudaGetSymbolAddress((void**)&qkv,  g_qkv);
    cudaGetSymbolAddress((void**)&o,    g_o);
    cudaGetSymbolAddress((void**)&m1,   g_m1);
    cudaGetSymbolAddress((void**)&biasT,g_bias);
    cudaGetSymbolAddress((void**)&xr,   g_xr);
    cudaGetSymbolAddress((void**)&hr,   g_hr);
    cudaGetSymbolAddress((void**)&qkvr, g_qkvr);
    cudaGetSymbolAddress((void**)&orr,  g_or);
    cudaGetSymbolAddress((void**)&Wqkv, g_Wqkv);
    cudaGetSymbolAddress((void**)&Wout, g_Wout);
    cudaGetSymbolAddress((void**)&W1,   g_W1);
    cudaGetSymbolAddress((void**)&W2,   g_W2);

    pack_kernel<<<(NROWS*DIMV + 255)/256, 256>>>(local_t, region_t);
    bias_kernel<<<(HEADS*NTOK*NTOK + 255)/256, 256>>>(emb);

    for (int l = 0; l < DEPTH; l++) {
        wsplit<<<(DIMV*3*DIMV + 255)/256, 256>>>(wqkv + (size_t)l*DIMV*3*DIMV,
            Wqkv + (size_t)l*3*DIMV*2*DIMV, DIMV, 3*DIMV);
        wsplit<<<(DIMV*DIMV + 255)/256, 256>>>(wout + (size_t)l*DIMV*DIMV,
            Wout + (size_t)l*DIMV*2*DIMV, DIMV, DIMV);
        wsplit<<<(DIMV*4*DIMV + 255)/256, 256>>>(w1 + (size_t)l*DIMV*4*DIMV,
            W1 + (size_t)l*4*DIMV*2*DIMV, DIMV, 4*DIMV);
        wsplit<<<(4*DIMV*DIMV + 255)/256, 256>>>(w2 + (size_t)l*4*DIMV*DIMV,
            W2 + (size_t)l*DIMV*2*4*DIMV, 4*DIMV, DIMV);
    }

    for (int l = 0; l < DEPTH; l++) {
        __nv_bfloat16* WqT = Wqkv + (size_t)l*3*DIMV*2*DIMV;
        __nv_bfloat16* WoT = Wout + (size_t)l*DIMV*2*DIMV;
        __nv_bfloat16* W1T = W1   + (size_t)l*4*DIMV*2*DIMV;
        __nv_bfloat16* W2T = W2   + (size_t)l*DIMV*2*4*DIMV;
        const float* Bout = bout + (size_t)l*DIMV;
        const float* B1   = b1   + (size_t)l*4*DIMV;
        const float* B2   = b2   + (size_t)l*DIMV;
        const float* Ag   = attn_g + (size_t)l*DIMV;
        const float* Ab   = attn_b + (size_t)l*DIMV;
        const float* Mg   = mlp_g  + (size_t)l*DIMV;
        const float* Mb   = mlp_b  + (size_t)l*DIMV;

        // ---- region self-attention ----
        gather_region<<<(NWIN*DIMV + 255)/256, 256>>>();
        ln_kernel<<<NWIN, 128>>>(xr, Ag, Ab, hr);
        gemm_mma<<<dim3(3*DIMV/BN, NWIN/BM), 256, SMEM_GEMM>>>(hr, WqT, nullptr, qkvr, nullptr, 3*DIMV, DIMV, 0);
        attn_kernel<64><<<dim3(NB, HEADS), 256>>>(qkvr, nullptr, orr);
        gemm_mma<<<dim3(DIMV/BN, NWIN/BM), 256, SMEM_GEMM>>>(orr, WoT, Bout, xr, nullptr, DIMV, DIMV, 1);
        scatter_region<<<(NWIN*DIMV + 255)/256, 256>>>();

        // ---- window attention ----
        ln_kernel<<<NROWS, 128>>>(xw, Ag, Ab, h);
        gemm_mma<<<dim3(3*DIMV/BN, NROWS/BM), 256, SMEM_GEMM>>>(h, WqT, nullptr, qkv, nullptr, 3*DIMV, DIMV, 0);
        attn_kernel<NTOK><<<dim3(NWIN, HEADS), 256>>>(qkv, biasT, o);
        gemm_mma<<<dim3(DIMV/BN, NROWS/BM), 256, SMEM_GEMM>>>(o, WoT, Bout, xw, nullptr, DIMV, DIMV, 1);

        // ---- MLP ----
        ln_kernel<<<NROWS, 128>>>(xw, Mg, Mb, h);
        gemm_mma<<<dim3(4*DIMV/BN, NROWS/BM), 256, SMEM_GEMM>>>(h, W1T, B1, nullptr, m1, 4*DIMV, DIMV, 2);
        gemm_mma<<<dim3(DIMV/BN, NROWS/BM), 256, SMEM_GEMM>>>(m1, W2T, B2, xw, nullptr, DIMV, 4*DIMV, 1);
    }

    unpack_kernel<<<(NROWS*DIMV + 255)/256, 256>>>(out);
}

// round 5
// speedup vs baseline: 1.1536x; 1.1536x over previous
#include <cuda_runtime.h>
#include <cuda_bf16.h>
#include <math.h>
#include <stdint.h>

// ---------------- Problem constants ----------------
#define DIMV    512
#define HEADS   16
#define DHEAD   32
#define NWIN    512          // B * RH * RW
#define NTOK    65           // 1 region + 64 local
#define NROWS   (NWIN*NTOK)  // 33280 (= 260 * 128)
#define NB      8
#define DEPTH   4
#define QSCALE  0.17677669529663687f
#define LOCAL_ELEMS (8*64*64*512)

// ---------------- helpers ----------------
__device__ __forceinline__ uint32_t smem_to_u32(const void* p) {
    uint32_t a;
    asm("{ .reg .u64 t; cvta.to.shared.u64 t, %1; cvt.u32.u64 %0, t; }" : "=r"(a) : "l"(p));
    return a;
}
__device__ __forceinline__ void cp16(uint32_t dst, const void* src) {
    asm volatile("cp.async.cg.shared.global [%0], [%1], 16;\n" :: "r"(dst), "l"(src));
}
__device__ __forceinline__ void cp_commit() { asm volatile("cp.async.commit_group;\n" ::: "memory"); }

__device__ __forceinline__ void split_bf16(float x, __nv_bfloat16& h, __nv_bfloat16& l) {
    h = __float2bfloat16(x);
    l = __float2bfloat16(x - __bfloat162float(h));
}
__device__ __forceinline__ float gelu_exact(float x) {
    return 0.5f * x * (1.0f + erff(x * 0.70710678118654752f));
}

// ================= Scratch (device globals) =================
// Activations with hi/lo split stored as [row][2K]: hi in [0,K), lo in [K,2K)
__device__ __align__(16) float         g_xw  [NROWS*DIMV];
__device__ __align__(16) __nv_bfloat16 g_h   [NROWS*2*DIMV];
__device__ __align__(16) float         g_qkv [NROWS*3*DIMV];
__device__ __align__(16) __nv_bfloat16 g_o   [NROWS*2*DIMV];
__device__ __align__(16) __nv_bfloat16 g_m1  [NROWS*2*4*DIMV];
__device__ __align__(16) float         g_bias[HEADS*NTOK*NTOK];
__device__ __align__(16) float         g_xr  [NWIN*DIMV];
__device__ __align__(16) __nv_bfloat16 g_hr  [NWIN*2*DIMV];
__device__ __align__(16) float         g_qkvr[NWIN*3*DIMV];
__device__ __align__(16) __nv_bfloat16 g_or  [NWIN*2*DIMV];
// Weights transposed+split: [N][2K] (hi [0,K), lo [K,2K))
__device__ __align__(16) __nv_bfloat16 g_Wqkv[DEPTH*3*DIMV*2*DIMV];
__device__ __align__(16) __nv_bfloat16 g_Wout[DEPTH*DIMV*2*DIMV];
__device__ __align__(16) __nv_bfloat16 g_W1  [DEPTH*4*DIMV*2*DIMV];
__device__ __align__(16) __nv_bfloat16 g_W2  [DEPTH*DIMV*2*4*DIMV];

// ================= small kernels =================
__global__ void pack_kernel(const float* __restrict__ local_t, const float* __restrict__ region_t) {
    int idx = blockIdx.x * blockDim.x + threadIdx.x;
    if (idx >= NROWS*DIMV) return;
    int d = idx & 511, row = idx >> 9;
    int win = row / NTOK, t = row - win*NTOK;
    float v;
    if (t == 0) v = region_t[win*DIMV + d];
    else {
        int a = t - 1, p1 = a >> 3, p2 = a & 7;
        int b = win >> 6, rh = (win >> 3) & 7, rw = win & 7;
        v = local_t[(((b*64) + (rh*8 + p1))*64 + (rw*8 + p2))*DIMV + d];
    }
    g_xw[idx] = v;
}

__global__ void unpack_kernel(float* __restrict__ out) {
    int idx = blockIdx.x * blockDim.x + threadIdx.x;
    if (idx >= NROWS*DIMV) return;
    if (idx < LOCAL_ELEMS) {
        int d = idx & 511, p = idx >> 9;
        int col = p & 63, rowi = (p >> 6) & 63, b = p >> 12;
        int rh = rowi >> 3, p1 = rowi & 7, rw = col >> 3, p2 = col & 7;
        int win = b*64 + rh*8 + rw, t = 1 + p1*8 + p2;
        out[idx] = g_xw[(win*NTOK + t)*DIMV + d];
    } else {
        int r = idx - LOCAL_ELEMS, w = r >> 9, d = r & 511;
        out[idx] = g_xw[(w*NTOK)*DIMV + d];
    }
}

__global__ void bias_kernel(const float* __restrict__ emb) {
    int idx = blockIdx.x * blockDim.x + threadIdx.x;
    if (idx >= HEADS*NTOK*NTOK) return;
    int h = idx / (NTOK*NTOK);
    int r = idx - h*NTOK*NTOK;
    int i = r / NTOK, j = r - i*NTOK;
    float v = 0.f;
    if (i > 0 && j > 0) {
        int a = i - 1, b = j - 1;
        int r0 = (a >> 3) - (b >> 3) + 7;
        int r1 = (a & 7) - (b & 7) + 7;
        v = emb[(r0 + r1*15)*HEADS + h];
    }
    g_bias[idx] = v;
}

__global__ void gather_region() {
    int idx = blockIdx.x * blockDim.x + threadIdx.x;
    if (idx >= NWIN*DIMV) return;
    int w = idx >> 9, d = idx & 511;
    g_xr[idx] = g_xw[(w*NTOK)*DIMV + d];
}
__global__ void scatter_region() {
    int idx = blockIdx.x * blockDim.x + threadIdx.x;
    if (idx >= NWIN*DIMV) return;
    int w = idx >> 9, d = idx & 511;
    g_xw[(w*NTOK)*DIMV + d] = g_xr[idx];
}

// ---- fused weight transpose+split for ALL layers in ONE launch ----
// (keeps the pre-GEMM launch count at 5 so ncu -s 5 -c 1 profiles gemm_mma)
#define SEG_QKV (3*DIMV*DIMV)   // 786432
#define SEG_OUT (DIMV*DIMV)     // 262144
#define SEG_W1  (DIMV*4*DIMV)   // 1048576
#define SEG_W2  (4*DIMV*DIMV)   // 1048576
#define SEG_TOT (SEG_QKV+SEG_OUT+SEG_W1+SEG_W2)  // 3145728

__global__ void wsplit_all(const float* __restrict__ wqkv, const float* __restrict__ wout,
                           const float* __restrict__ w1, const float* __restrict__ w2) {
    int idx = blockIdx.x * blockDim.x + threadIdx.x;
    if (idx >= DEPTH*SEG_TOT) return;
    int l = idx / SEG_TOT;
    int r = idx - l*SEG_TOT;
    const float* W; __nv_bfloat16* O; int K, N;
    if (r < SEG_QKV) {
        W = wqkv + (size_t)l*SEG_QKV; O = g_Wqkv + (size_t)l*2*SEG_QKV; K = DIMV; N = 3*DIMV;
    } else if (r < SEG_QKV + SEG_OUT) {
        r -= SEG_QKV;
        W = wout + (size_t)l*SEG_OUT; O = g_Wout + (size_t)l*2*SEG_OUT; K = DIMV; N = DIMV;
    } else if (r < SEG_QKV + SEG_OUT + SEG_W1) {
        r -= SEG_QKV + SEG_OUT;
        W = w1 + (size_t)l*SEG_W1; O = g_W1 + (size_t)l*2*SEG_W1; K = DIMV; N = 4*DIMV;
    } else {
        r -= SEG_QKV + SEG_OUT + SEG_W1;
        W = w2 + (size_t)l*SEG_W2; O = g_W2 + (size_t)l*2*SEG_W2; K = 4*DIMV; N = DIMV;
    }
    int n = r / K, k = r - n*K;
    float v = W[(size_t)k*N + n];
    __nv_bfloat16 h, l2; split_bf16(v, h, l2);
    O[(size_t)n*2*K + k]     = h;
    O[(size_t)n*2*K + K + k] = l2;
}

// LayerNorm: 128 threads per 512-wide row, emits split bf16 into [row][1024]
__global__ void ln_kernel(const float* __restrict__ x, const float* __restrict__ g,
                          const float* __restrict__ b, __nv_bfloat16* __restrict__ y) {
    int row = blockIdx.x;
    int t = threadIdx.x;
    const float4* xv = (const float4*)(x + (size_t)row*DIMV);
    float4 v = xv[t];
    float s  = v.x + v.y + v.z + v.w;
    float s2 = v.x*v.x + v.y*v.y + v.z*v.z + v.w*v.w;
    #pragma unroll
    for (int off = 16; off; off >>= 1) {
        s  += __shfl_xor_sync(0xffffffffu, s,  off);
        s2 += __shfl_xor_sync(0xffffffffu, s2, off);
    }
    __shared__ float sh[8];
    int wid = t >> 5, lane = t & 31;
    if (lane == 0) { sh[wid] = s; sh[4 + wid] = s2; }
    __syncthreads();
    float st  = sh[0] + sh[1] + sh[2] + sh[3];
    float s2t = sh[4] + sh[5] + sh[6] + sh[7];
    float mean = st * (1.f/512.f);
    float var  = s2t * (1.f/512.f) - mean*mean;
    float rstd = rsqrtf(var + 1e-3f);
    float4 gg = ((const float4*)g)[t];
    float4 bb = ((const float4*)b)[t];
    float o0 = (v.x - mean)*rstd*gg.x + bb.x;
    float o1 = (v.y - mean)*rstd*gg.y + bb.y;
    float o2 = (v.z - mean)*rstd*gg.z + bb.z;
    float o3 = (v.w - mean)*rstd*gg.w + bb.w;
    __nv_bfloat16 h0,h1,h2,h3,l0,l1,l2,l3;
    split_bf16(o0,h0,l0); split_bf16(o1,h1,l1); split_bf16(o2,h2,l2); split_bf16(o3,h3,l3);
    __nv_bfloat162* pH = (__nv_bfloat162*)(y + (size_t)row*1024 + 4*t);
    __nv_bfloat162* pL = (__nv_bfloat162*)(y + (size_t)row*1024 + 512 + 4*t);
    __nv_bfloat162 a0; a0.x = h0; a0.y = h1;
    __nv_bfloat162 a1; a1.x = h2; a1.y = h3;
    __nv_bfloat162 c0; c0.x = l0; c0.y = l1;
    __nv_bfloat162 c1; c1.x = l2; c1.y = l3;
    pH[0] = a0; pH[1] = a1;
    pL[0] = c0; pL[1] = c1;
}

// ================= Attention (float4-vectorized) =================
template<int NT>
__global__ __launch_bounds__(256) void attn_kernel(const float* __restrict__ qkv,
                                                   const float* __restrict__ biasTab,
                                                   __nv_bfloat16* __restrict__ o) {
    __shared__ float qs[NT][36];     // padded: 9 float4 per row, gcd(9,32)=1 -> conflict-free
    __shared__ float ks[NT][36];
    __shared__ float vs[NT][36];
    __shared__ float ss[NT][NT + 1];
    const int grp = blockIdx.x;
    const int h   = blockIdx.y;
    const int base = grp * NT;
    const int tid = threadIdx.x;
    constexpr int JB = (NT + 3) / 4;  // j-blocks of 4

    for (int p = tid; p < NT * DHEAD; p += 256) {
        int i = p >> 5, d = p & 31;
        const float* row = qkv + (size_t)(base + i) * (3*DIMV) + h*DHEAD + d;
        qs[i][d] = row[0] * QSCALE;
        ks[i][d] = row[DIMV];
        vs[i][d] = row[2*DIMV];
    }
    __syncthreads();

    // sim = q @ k^T (+ bias), 4 j's per item, float4 over d
    for (int p = tid; p < NT * JB; p += 256) {
        int i = p / JB, jb = p - i*JB;
        int j0 = jb*4;
        float a0 = 0.f, a1 = 0.f, a2 = 0.f, a3 = 0.f;
        const float4* q4 = (const float4*)qs[i];
        const float4* k0 = (const float4*)ks[j0];
        const float4* k1 = (const float4*)ks[(j0+1 < NT) ? j0+1 : j0];
        const float4* k2 = (const float4*)ks[(j0+2 < NT) ? j0+2 : j0];
        const float4* k3 = (const float4*)ks[(j0+3 < NT) ? j0+3 : j0];
        #pragma unroll
        for (int d4 = 0; d4 < 8; d4++) {
            float4 q = q4[d4];
            float4 x0 = k0[d4], x1 = k1[d4], x2 = k2[d4], x3 = k3[d4];
            a0 += q.x*x0.x + q.y*x0.y + q.z*x0.z + q.w*x0.w;
            a1 += q.x*x1.x + q.y*x1.y + q.z*x1.z + q.w*x1.w;
            a2 += q.x*x2.x + q.y*x2.y + q.z*x2.z + q.w*x2.w;
            a3 += q.x*x3.x + q.y*x3.y + q.z*x3.z + q.w*x3.w;
        }
        float acc[4] = {a0, a1, a2, a3};
        #pragma unroll
        for (int u = 0; u < 4; u++) {
            int j = j0 + u;
            if (j < NT) {
                float v = acc[u];
                if (biasTab) v += biasTab[(h*NT + i)*NT + j];
                ss[i][j] = v;
            }
        }
    }
    __syncthreads();

    // softmax per row (warp per row)
    int wid = tid >> 5, lane = tid & 31;
    for (int i = wid; i < NT; i += 8) {
        float m = -1e30f;
        for (int j = lane; j < NT; j += 32) m = fmaxf(m, ss[i][j]);
        #pragma unroll
        for (int off = 16; off; off >>= 1) m = fmaxf(m, __shfl_xor_sync(0xffffffffu, m, off));
        float sum = 0.f;
        for (int j = lane; j < NT; j += 32) { float e = __expf(ss[i][j] - m); ss[i][j] = e; sum += e; }
        #pragma unroll
        for (int off = 16; off; off >>= 1) sum += __shfl_xor_sync(0xffffffffu, sum, off);
        float inv = 1.f / sum;
        for (int j = lane; j < NT; j += 32) ss[i][j] *= inv;
    }
    __syncthreads();

    // out = attn @ v : each item = (i, 4 output dims), float4 over v
    for (int p = tid; p < NT * 8; p += 256) {
        int i = p >> 3, d4 = p & 7;
        float4 acc; acc.x = 0.f; acc.y = 0.f; acc.z = 0.f; acc.w = 0.f;
        const float* srow = ss[i];
        #pragma unroll 5
        for (int j = 0; j < NT; j++) {
            float a = srow[j];
            float4 v = *(const float4*)&vs[j][d4*4];
            acc.x += a*v.x; acc.y += a*v.y; acc.z += a*v.z; acc.w += a*v.w;
        }
        __nv_bfloat16 h0,h1,h2,h3,l0,l1,l2,l3;
        split_bf16(acc.x,h0,l0); split_bf16(acc.y,h1,l1);
        split_bf16(acc.z,h2,l2); split_bf16(acc.w,h3,l3);
        size_t ob = (size_t)(base + i) * 1024 + h*DHEAD + d4*4;
        __nv_bfloat162 sh0; sh0.x = h0; sh0.y = h1;
        __nv_bfloat162 sh1; sh1.x = h2; sh1.y = h3;
        __nv_bfloat162 sl0; sl0.x = l0; sl0.y = l1;
        __nv_bfloat162 sl1; sl1.x = l2; sl1.y = l3;
        *(__nv_bfloat162*)&o[ob]       = sh0;
        *(__nv_bfloat162*)&o[ob+2]     = sh1;
        *(__nv_bfloat162*)&o[ob+512]   = sl0;
        *(__nv_bfloat162*)&o[ob+514]   = sl1;
    }
}

// ================= bf16 split GEMM via mma.sync (R3 config) =================
#define BM 128
#define BN 128
#define BK 32
#define NSTG 4
#define ROWB 80                         // padded smem row bytes (64B data + 16B pad)
#define STG_BYTES ((BM + BN) * ROWB)    // 20480
#define SMEM_GEMM (NSTG * STG_BYTES)    // 81920

__global__ __launch_bounds__(256, 2) void gemm_mma(
    const __nv_bfloat16* __restrict__ A, const __nv_bfloat16* __restrict__ B,
    const float* __restrict__ bias, float* __restrict__ C,
    __nv_bfloat16* __restrict__ O, int N, int K, int epi)
{
    extern __shared__ char smem[];
    const uint32_t sb = smem_to_u32(smem);
    const int tid = threadIdx.x;
    const int bm = blockIdx.y * BM;
    const int bn = blockIdx.x * BN;
    const int lda = 2*K;
    const int cpt = K / BK;
    const int total = 3 * cpt;

    const int wid = tid >> 5, lane = tid & 31;
    const int wm = wid & 1, wn = wid >> 1;     // warp grid 2(M) x 4(N)

    float acc[4][4][4];
    #pragma unroll
    for (int mi = 0; mi < 4; mi++)
        #pragma unroll
        for (int ni = 0; ni < 4; ni++)
            #pragma unroll
            for (int r = 0; r < 4; r++) acc[mi][ni][r] = 0.f;

    auto load_chunk = [&](int c) {
        int t  = c / cpt, kk = c - t*cpt;
        int a_col = ((t == 2) ? K : 0) + kk*BK;
        int b_col = ((t == 1) ? K : 0) + kk*BK;
        uint32_t stA = sb + (c % NSTG) * STG_BYTES;
        uint32_t stB = stA + BM * ROWB;
        #pragma unroll
        for (int i = 0; i < 2; i++) {
            int s = tid + i*256;        // 512 segments: 128 rows x 4
            int row = s >> 2, seg = s & 3;
            cp16(stA + row*ROWB + seg*16, A + (size_t)(bm + row)*lda + a_col + seg*8);
            cp16(stB + row*ROWB + seg*16, B + (size_t)(bn + row)*lda + b_col + seg*8);
        }
        cp_commit();
    };

    load_chunk(0); load_chunk(1); load_chunk(2);

    for (int c = 0; c < total; c++) {
        if (c <= total - 3)      asm volatile("cp.async.wait_group 2;\n" ::: "memory");
        else if (c == total - 2) asm volatile("cp.async.wait_group 1;\n" ::: "memory");
        else                     asm volatile("cp.async.wait_group 0;\n" ::: "memory");
        __syncthreads();
        if (c + 3 < total) load_chunk(c + 3);

        uint32_t stA = sb + (c % NSTG) * STG_BYTES;
        uint32_t stB = stA + BM * ROWB;
        #pragma unroll
        for (int ks = 0; ks < 2; ks++) {
            uint32_t a[4][4];
            #pragma unroll
            for (int mi = 0; mi < 4; mi++) {
                uint32_t addr = stA + (wm*64 + mi*16 + (lane & 15))*ROWB + ((lane >> 4)*16 + ks*32);
                asm volatile("ldmatrix.sync.aligned.m8n8.x4.shared.b16 {%0,%1,%2,%3}, [%4];"
                    : "=r"(a[mi][0]), "=r"(a[mi][1]), "=r"(a[mi][2]), "=r"(a[mi][3]) : "r"(addr));
            }
            uint32_t b[4][2];
            #pragma unroll
            for (int ni = 0; ni < 4; ni++) {
                uint32_t addr = stB + (wn*32 + ni*8 + (lane & 7))*ROWB + (((lane >> 3) & 1)*16 + ks*32);
                asm volatile("ldmatrix.sync.aligned.m8n8.x2.shared.b16 {%0,%1}, [%2];"
                    : "=r"(b[ni][0]), "=r"(b[ni][1]) : "r"(addr));
            }
            #pragma unroll
            for (int mi = 0; mi < 4; mi++)
                #pragma unroll
                for (int ni = 0; ni < 4; ni++) {
                    asm volatile(
                        "mma.sync.aligned.m16n8k16.row.col.f32.bf16.bf16.f32 "
                        "{%0,%1,%2,%3}, {%4,%5,%6,%7}, {%8,%9}, {%0,%1,%2,%3};"
                        : "+f"(acc[mi][ni][0]), "+f"(acc[mi][ni][1]),
                          "+f"(acc[mi][ni][2]), "+f"(acc[mi][ni][3])
                        : "r"(a[mi][0]), "r"(a[mi][1]), "r"(a[mi][2]), "r"(a[mi][3]),
                          "r"(b[ni][0]), "r"(b[ni][1]));
                }
        }
    }

    // ---- epilogue ----
    const int g = lane >> 2, tig = lane & 3;
    #pragma unroll
    for (int mi = 0; mi < 4; mi++) {
        #pragma unroll
        for (int ni = 0; ni < 4; ni++) {
            int r0 = bm + wm*64 + mi*16 + g;
            int cc = bn + wn*32 + ni*8 + tig*2;
            #pragma unroll
            for (int half = 0; half < 2; half++) {
                int r = r0 + half*8;
                float v0 = acc[mi][ni][half*2 + 0];
                float v1 = acc[mi][ni][half*2 + 1];
                if (epi == 0) {
                    float2 st; st.x = v0; st.y = v1;
                    *(float2*)&C[(size_t)r*N + cc] = st;
                } else if (epi == 1) {
                    float2 bi  = *(const float2*)&bias[cc];
                    float2 res = *(const float2*)&C[(size_t)r*N + cc];
                    float2 st; st.x = v0 + bi.x + res.x; st.y = v1 + bi.y + res.y;
                    *(float2*)&C[(size_t)r*N + cc] = st;
                } else {
                    float2 bi = *(const float2*)&bias[cc];
                    float g0 = gelu_exact(v0 + bi.x);
                    float g1 = gelu_exact(v1 + bi.y);
                    __nv_bfloat16 h0,h1,l0,l1;
                    split_bf16(g0, h0, l0); split_bf16(g1, h1, l1);
                    __nv_bfloat162 sh; sh.x = h0; sh.y = h1;
                    __nv_bfloat162 sl; sl.x = l0; sl.y = l1;
                    *(__nv_bfloat162*)&O[(size_t)r*2*N + cc]     = sh;
                    *(__nv_bfloat162*)&O[(size_t)r*2*N + N + cc] = sl;
                }
            }
        }
    }
}

// ================= Host driver =================
extern "C" void kernel_launch(void* const* d_in, const int* in_sizes, int n_in,
                              void* d_out, int out_size) {
    const float* local_t  = (const float*)d_in[0];
    const float* region_t = (const float*)d_in[1];
    const float* emb      = (const float*)d_in[2];
    const float* attn_g   = (const float*)d_in[3];
    const float* attn_b   = (const float*)d_in[4];
    const float* wqkv     = (const float*)d_in[5];
    const float* wout     = (const float*)d_in[6];
    const float* bout     = (const float*)d_in[7];
    const float* mlp_g    = (const float*)d_in[8];
    const float* mlp_b    = (const float*)d_in[9];
    const float* w1       = (const float*)d_in[10];
    const float* b1       = (const float*)d_in[11];
    const float* w2       = (const float*)d_in[12];
    const float* b2       = (const float*)d_in[13];
    float* out = (float*)d_out;

    cudaFuncSetAttribute(gemm_mma, cudaFuncAttributeMaxDynamicSharedMemorySize, SMEM_GEMM);

    float *xw, *qkv, *biasT, *xr, *qkvr;
    __nv_bfloat16 *h, *o, *m1, *hr, *orr;
    __nv_bfloat16 *Wqkv, *Wout, *W1, *W2;
    cudaGetSymbolAddress((void**)&xw,   g_xw);
    cudaGetSymbolAddress((void**)&h,    g_h);
    cudaGetSymbolAddress((void**)&qkv,  g_qkv);
    cudaGetSymbolAddress((void**)&o,    g_o);
    cudaGetSymbolAddress((void**)&m1,   g_m1);
    cudaGetSymbolAddress((void**)&biasT,g_bias);
    cudaGetSymbolAddress((void**)&xr,   g_xr);
    cudaGetSymbolAddress((void**)&hr,   g_hr);
    cudaGetSymbolAddress((void**)&qkvr, g_qkvr);
    cudaGetSymbolAddress((void**)&orr,  g_or);
    cudaGetSymbolAddress((void**)&Wqkv, g_Wqkv);
    cudaGetSymbolAddress((void**)&Wout, g_Wout);
    cudaGetSymbolAddress((void**)&W1,   g_W1);
    cudaGetSymbolAddress((void**)&W2,   g_W2);

    // launches 1-3 (keeps gemm_mma as launch #6 for ncu -s 5 -c 1)
    pack_kernel<<<(NROWS*DIMV + 255)/256, 256>>>(local_t, region_t);
    bias_kernel<<<(HEADS*NTOK*NTOK + 255)/256, 256>>>(emb);
    wsplit_all<<<(DEPTH*SEG_TOT + 255)/256, 256>>>(wqkv, wout, w1, w2);

    for (int l = 0; l < DEPTH; l++) {
        __nv_bfloat16* WqT = Wqkv + (size_t)l*3*DIMV*2*DIMV;
        __nv_bfloat16* WoT = Wout + (size_t)l*DIMV*2*DIMV;
        __nv_bfloat16* W1T = W1   + (size_t)l*4*DIMV*2*DIMV;
        __nv_bfloat16* W2T = W2   + (size_t)l*DIMV*2*4*DIMV;
        const float* Bout = bout + (size_t)l*DIMV;
        const float* B1   = b1   + (size_t)l*4*DIMV;
        const float* B2   = b2   + (size_t)l*DIMV;
        const float* Ag   = attn_g + (size_t)l*DIMV;
        const float* Ab   = attn_b + (size_t)l*DIMV;
        const float* Mg   = mlp_g  + (size_t)l*DIMV;
        const float* Mb   = mlp_b  + (size_t)l*DIMV;

        // ---- region self-attention ----
        gather_region<<<(NWIN*DIMV + 255)/256, 256>>>();
        ln_kernel<<<NWIN, 128>>>(xr, Ag, Ab, hr);
        gemm_mma<<<dim3(3*DIMV/BN, NWIN/BM), 256, SMEM_GEMM>>>(hr, WqT, nullptr, qkvr, nullptr, 3*DIMV, DIMV, 0);
        attn_kernel<64><<<dim3(NB, HEADS), 256>>>(qkvr, nullptr, orr);
        gemm_mma<<<dim3(DIMV/BN, NWIN/BM), 256, SMEM_GEMM>>>(orr, WoT, Bout, xr, nullptr, DIMV, DIMV, 1);
        scatter_region<<<(NWIN*DIMV + 255)/256, 256>>>();

        // ---- window attention ----
        ln_kernel<<<NROWS, 128>>>(xw, Ag, Ab, h);
        gemm_mma<<<dim3(3*DIMV/BN, NROWS/BM), 256, SMEM_GEMM>>>(h, WqT, nullptr, qkv, nullptr, 3*DIMV, DIMV, 0);
        attn_kernel<NTOK><<<dim3(NWIN, HEADS), 256>>>(qkv, biasT, o);
        gemm_mma<<<dim3(DIMV/BN, NROWS/BM), 256, SMEM_GEMM>>>(o, WoT, Bout, xw, nullptr, DIMV, DIMV, 1);

        // ---- MLP ----
        ln_kernel<<<NROWS, 128>>>(xw, Mg, Mb, h);
        gemm_mma<<<dim3(4*DIMV/BN, NROWS/BM), 256, SMEM_GEMM>>>(h, W1T, B1, nullptr, m1, 4*DIMV, DIMV, 2);
        gemm_mma<<<dim3(DIMV/BN, NROWS/BM), 256, SMEM_GEMM>>>(m1, W2T, B2, xw, nullptr, DIMV, 4*DIMV, 1);
    }

    unpack_kernel<<<(NROWS*DIMV + 255)/256, 256>>>(out);
}

// round 6
// speedup vs baseline: 1.7830x; 1.5456x over previous
#include <cuda_runtime.h>
#include <cuda_bf16.h>
#include <cuda_fp16.h>
#include <math.h>
#include <stdint.h>

// ---------------- Problem constants ----------------
#define DIMV    512
#define HEADS   16
#define DHEAD   32
#define NWIN    512          // B * RH * RW
#define NTOK    65           // 1 region + 64 local
#define NROWS   (NWIN*NTOK)  // 33280 (= 260 * 128)
#define NB      8
#define DEPTH   4
#define QSCALE  0.17677669529663687f
#define LOCAL_ELEMS (8*64*64*512)

// ---------------- helpers ----------------
__device__ __forceinline__ uint32_t smem_to_u32(const void* p) {
    uint32_t a;
    asm("{ .reg .u64 t; cvta.to.shared.u64 t, %1; cvt.u32.u64 %0, t; }" : "=r"(a) : "l"(p));
    return a;
}
__device__ __forceinline__ void cp16(uint32_t dst, const void* src) {
    asm volatile("cp.async.cg.shared.global [%0], [%1], 16;\n" :: "r"(dst), "l"(src));
}
__device__ __forceinline__ void cp_commit() { asm volatile("cp.async.commit_group;\n" ::: "memory"); }

__device__ __forceinline__ void split_bf16(float x, __nv_bfloat16& h, __nv_bfloat16& l) {
    h = __float2bfloat16(x);
    l = __float2bfloat16(x - __bfloat162float(h));
}
__device__ __forceinline__ float gelu_exact(float x) {
    return 0.5f * x * (1.0f + erff(x * 0.70710678118654752f));
}

// ================= Scratch (device globals) =================
__device__ __align__(16) float         g_xw  [NROWS*DIMV];       // residual stream (windowed)
__device__ __align__(16) __nv_bfloat16 g_h   [NROWS*2*DIMV];     // attn-LN out, split bf16 [row][1024]
__device__ __align__(16) __half        g_hh  [NROWS*DIMV];       // mlp-LN out, fp16 [row][512]
__device__ __align__(16) float         g_qkv [NROWS*3*DIMV];
__device__ __align__(16) __nv_bfloat16 g_o   [NROWS*2*DIMV];     // attn out, split bf16
__device__ __align__(16) __half        g_m1  [NROWS*4*DIMV];     // MLP hidden, fp16 [row][2048]
__device__ __align__(16) float         g_bias[HEADS*NTOK*NTOK];
__device__ __align__(16) __nv_bfloat16 g_hr  [NWIN*2*DIMV];
__device__ __align__(16) float         g_qkvr[NWIN*3*DIMV];
__device__ __align__(16) __nv_bfloat16 g_or  [NWIN*2*DIMV];
// Weights: qkv/out transposed+split bf16 [N][2K]; w1/w2 transposed fp16 [N][K]
__device__ __align__(16) __nv_bfloat16 g_Wqkv[DEPTH*3*DIMV*2*DIMV];
__device__ __align__(16) __nv_bfloat16 g_Wout[DEPTH*DIMV*2*DIMV];
__device__ __align__(16) __half        g_W1h [DEPTH*4*DIMV*DIMV];
__device__ __align__(16) __half        g_W2h [DEPTH*DIMV*4*DIMV];

// ================= pack =================
__global__ void pack_kernel(const float* __restrict__ local_t, const float* __restrict__ region_t) {
    int idx = blockIdx.x * blockDim.x + threadIdx.x;
    if (idx >= NROWS*DIMV) return;
    int d = idx & 511, row = idx >> 9;
    int win = row / NTOK, t = row - win*NTOK;
    float v;
    if (t == 0) v = region_t[win*DIMV + d];
    else {
        int a = t - 1, p1 = a >> 3, p2 = a & 7;
        int b = win >> 6, rh = (win >> 3) & 7, rw = win & 7;
        v = local_t[(((b*64) + (rh*8 + p1))*64 + (rw*8 + p2))*DIMV + d];
    }
    g_xw[idx] = v;
}

__global__ void unpack_kernel(float* __restrict__ out) {
    int idx = blockIdx.x * blockDim.x + threadIdx.x;
    if (idx >= NROWS*DIMV) return;
    if (idx < LOCAL_ELEMS) {
        int d = idx & 511, p = idx >> 9;
        int col = p & 63, rowi = (p >> 6) & 63, b = p >> 12;
        int rh = rowi >> 3, p1 = rowi & 7, rw = col >> 3, p2 = col & 7;
        int win = b*64 + rh*8 + rw, t = 1 + p1*8 + p2;
        out[idx] = g_xw[(win*NTOK + t)*DIMV + d];
    } else {
        int r = idx - LOCAL_ELEMS, w = r >> 9, d = r & 511;
        out[idx] = g_xw[(w*NTOK)*DIMV + d];
    }
}

// ---- fused weight conversion (all layers) + rel-pos bias table, ONE launch ----
#define SEG_QKV (3*DIMV*DIMV)
#define SEG_OUT (DIMV*DIMV)
#define SEG_W1  (DIMV*4*DIMV)
#define SEG_W2  (4*DIMV*DIMV)
#define SEG_TOT (SEG_QKV+SEG_OUT+SEG_W1+SEG_W2)
#define WTOT    (DEPTH*SEG_TOT)
#define BIAS_N  (HEADS*NTOK*NTOK)

__global__ void wconv_all(const float* __restrict__ wqkv, const float* __restrict__ wout,
                          const float* __restrict__ w1, const float* __restrict__ w2,
                          const float* __restrict__ emb) {
    int idx = blockIdx.x * blockDim.x + threadIdx.x;
    if (idx < WTOT) {
        int l = idx / SEG_TOT;
        int r = idx - l*SEG_TOT;
        if (r < SEG_QKV) {
            const float* W = wqkv + (size_t)l*SEG_QKV;
            __nv_bfloat16* O = g_Wqkv + (size_t)l*2*SEG_QKV;
            int K = DIMV, N = 3*DIMV;
            int n = r / K, k = r - n*K;
            float v = W[(size_t)k*N + n];
            __nv_bfloat16 h, lo; split_bf16(v, h, lo);
            O[(size_t)n*2*K + k] = h; O[(size_t)n*2*K + K + k] = lo;
        } else if (r < SEG_QKV + SEG_OUT) {
            r -= SEG_QKV;
            const float* W = wout + (size_t)l*SEG_OUT;
            __nv_bfloat16* O = g_Wout + (size_t)l*2*SEG_OUT;
            int K = DIMV, N = DIMV;
            int n = r / K, k = r - n*K;
            float v = W[(size_t)k*N + n];
            __nv_bfloat16 h, lo; split_bf16(v, h, lo);
            O[(size_t)n*2*K + k] = h; O[(size_t)n*2*K + K + k] = lo;
        } else if (r < SEG_QKV + SEG_OUT + SEG_W1) {
            r -= SEG_QKV + SEG_OUT;
            const float* W = w1 + (size_t)l*SEG_W1;
            __half* O = g_W1h + (size_t)l*SEG_W1;
            int K = DIMV, N = 4*DIMV;
            int n = r / K, k = r - n*K;
            O[(size_t)n*K + k] = __float2half_rn(W[(size_t)k*N + n]);
        } else {
            r -= SEG_QKV + SEG_OUT + SEG_W1;
            const float* W = w2 + (size_t)l*SEG_W2;
            __half* O = g_W2h + (size_t)l*SEG_W2;
            int K = 4*DIMV, N = DIMV;
            int n = r / K, k = r - n*K;
            O[(size_t)n*K + k] = __float2half_rn(W[(size_t)k*N + n]);
        }
    } else {
        int r = idx - WTOT;
        if (r >= BIAS_N) return;
        int h = r / (NTOK*NTOK);
        int q = r - h*NTOK*NTOK;
        int i = q / NTOK, j = q - i*NTOK;
        float v = 0.f;
        if (i > 0 && j > 0) {
            int a = i - 1, b = j - 1;
            int r0 = (a >> 3) - (b >> 3) + 7;
            int r1 = (a & 7) - (b & 7) + 7;
            v = emb[(r0 + r1*15)*HEADS + h];
        }
        g_bias[r] = v;
    }
}

// ================= LayerNorm variants =================
// split-bf16 output [row][1024]; input rows at stride `instr` floats
__global__ void ln_split(const float* __restrict__ x, int instr, const float* __restrict__ g,
                         const float* __restrict__ b, __nv_bfloat16* __restrict__ y) {
    int row = blockIdx.x;
    int t = threadIdx.x;
    const float4* xv = (const float4*)(x + (size_t)row*instr);
    float4 v = xv[t];
    float s  = v.x + v.y + v.z + v.w;
    float s2 = v.x*v.x + v.y*v.y + v.z*v.z + v.w*v.w;
    #pragma unroll
    for (int off = 16; off; off >>= 1) {
        s  += __shfl_xor_sync(0xffffffffu, s,  off);
        s2 += __shfl_xor_sync(0xffffffffu, s2, off);
    }
    __shared__ float sh[8];
    int wid = t >> 5, lane = t & 31;
    if (lane == 0) { sh[wid] = s; sh[4 + wid] = s2; }
    __syncthreads();
    float st  = sh[0] + sh[1] + sh[2] + sh[3];
    float s2t = sh[4] + sh[5] + sh[6] + sh[7];
    float mean = st * (1.f/512.f);
    float var  = s2t * (1.f/512.f) - mean*mean;
    float rstd = rsqrtf(var + 1e-3f);
    float4 gg = ((const float4*)g)[t];
    float4 bb = ((const float4*)b)[t];
    float o0 = (v.x - mean)*rstd*gg.x + bb.x;
    float o1 = (v.y - mean)*rstd*gg.y + bb.y;
    float o2 = (v.z - mean)*rstd*gg.z + bb.z;
    float o3 = (v.w - mean)*rstd*gg.w + bb.w;
    __nv_bfloat16 h0,h1,h2,h3,l0,l1,l2,l3;
    split_bf16(o0,h0,l0); split_bf16(o1,h1,l1); split_bf16(o2,h2,l2); split_bf16(o3,h3,l3);
    __nv_bfloat162* pH = (__nv_bfloat162*)(y + (size_t)row*1024 + 4*t);
    __nv_bfloat162* pL = (__nv_bfloat162*)(y + (size_t)row*1024 + 512 + 4*t);
    __nv_bfloat162 a0; a0.x = h0; a0.y = h1;
    __nv_bfloat162 a1; a1.x = h2; a1.y = h3;
    __nv_bfloat162 c0; c0.x = l0; c0.y = l1;
    __nv_bfloat162 c1; c1.x = l2; c1.y = l3;
    pH[0] = a0; pH[1] = a1;
    pL[0] = c0; pL[1] = c1;
}

// fp16-single output [row][512]
__global__ void ln_half(const float* __restrict__ x, const float* __restrict__ g,
                        const float* __restrict__ b, __half* __restrict__ y) {
    int row = blockIdx.x;
    int t = threadIdx.x;
    const float4* xv = (const float4*)(x + (size_t)row*DIMV);
    float4 v = xv[t];
    float s  = v.x + v.y + v.z + v.w;
    float s2 = v.x*v.x + v.y*v.y + v.z*v.z + v.w*v.w;
    #pragma unroll
    for (int off = 16; off; off >>= 1) {
        s  += __shfl_xor_sync(0xffffffffu, s,  off);
        s2 += __shfl_xor_sync(0xffffffffu, s2, off);
    }
    __shared__ float sh[8];
    int wid = t >> 5, lane = t & 31;
    if (lane == 0) { sh[wid] = s; sh[4 + wid] = s2; }
    __syncthreads();
    float st  = sh[0] + sh[1] + sh[2] + sh[3];
    float s2t = sh[4] + sh[5] + sh[6] + sh[7];
    float mean = st * (1.f/512.f);
    float var  = s2t * (1.f/512.f) - mean*mean;
    float rstd = rsqrtf(var + 1e-3f);
    float4 gg = ((const float4*)g)[t];
    float4 bb = ((const float4*)b)[t];
    __half2 o01, o23;
    o01 = __floats2half2_rn((v.x - mean)*rstd*gg.x + bb.x, (v.y - mean)*rstd*gg.y + bb.y);
    o23 = __floats2half2_rn((v.z - mean)*rstd*gg.z + bb.z, (v.w - mean)*rstd*gg.w + bb.w);
    __half2* p = (__half2*)(y + (size_t)row*DIMV + 4*t);
    p[0] = o01; p[1] = o23;
}

// ================= Attention (R3 scalar version, known-good) =================
template<int NT>
__global__ __launch_bounds__(256) void attn_kernel(const float* __restrict__ qkv,
                                                   const float* __restrict__ biasTab,
                                                   __nv_bfloat16* __restrict__ o) {
    __shared__ float qs[NT][33];
    __shared__ float ks[NT][33];
    __shared__ float vs[NT][33];
    __shared__ float ss[NT][NT + 1];
    const int grp = blockIdx.x;
    const int h   = blockIdx.y;
    const int base = grp * NT;
    const int tid = threadIdx.x;

    for (int p = tid; p < NT * DHEAD; p += 256) {
        int i = p >> 5, d = p & 31;
        const float* row = qkv + (size_t)(base + i) * (3*DIMV) + h*DHEAD + d;
        qs[i][d] = row[0] * QSCALE;
        ks[i][d] = row[DIMV];
        vs[i][d] = row[2*DIMV];
    }
    __syncthreads();

    for (int p = tid; p < NT * NT; p += 256) {
        int i = p / NT, j = p - i*NT;
        float acc = 0.f;
        #pragma unroll
        for (int d = 0; d < 32; d++) acc += qs[i][d] * ks[j][d];
        if (biasTab) acc += biasTab[(h*NT + i)*NT + j];
        ss[i][j] = acc;
    }
    __syncthreads();

    int wid = tid >> 5, lane = tid & 31;
    for (int i = wid; i < NT; i += 8) {
        float m = -1e30f;
        for (int j = lane; j < NT; j += 32) m = fmaxf(m, ss[i][j]);
        #pragma unroll
        for (int off = 16; off; off >>= 1) m = fmaxf(m, __shfl_xor_sync(0xffffffffu, m, off));
        float sum = 0.f;
        for (int j = lane; j < NT; j += 32) { float e = __expf(ss[i][j] - m); ss[i][j] = e; sum += e; }
        #pragma unroll
        for (int off = 16; off; off >>= 1) sum += __shfl_xor_sync(0xffffffffu, sum, off);
        float inv = 1.f / sum;
        for (int j = lane; j < NT; j += 32) ss[i][j] *= inv;
    }
    __syncthreads();

    for (int p = tid; p < NT * DHEAD; p += 256) {
        int i = p >> 5, d = p & 31;
        float acc = 0.f;
        #pragma unroll 5
        for (int j = 0; j < NT; j++) acc += ss[i][j] * vs[j][d];
        __nv_bfloat16 hh, ll; split_bf16(acc, hh, ll);
        size_t ob = (size_t)(base + i) * 1024 + h*DHEAD + d;
        o[ob] = hh; o[ob + 512] = ll;
    }
}

// ================= GEMM via mma.sync =================
// TERMS=3: bf16 hi/lo split, A/B are [row][2K] bf16 (fp32-accurate)
// TERMS=1: plain fp16, A/B are [row][K] half
// epi 0: C = AB (fp32, row stride cs)
// epi 1: C = AB + bias + C (fp32 residual in place, row stride cs)
// epi 2: Oh = gelu(AB + bias) (fp16, row stride cs)
#define BM 128
#define BN 128
#define BK 32
#define NSTG 4
#define ROWB 80
#define STG_BYTES ((BM + BN) * ROWB)
#define SMEM_GEMM (NSTG * STG_BYTES)

template<int TERMS>
__global__ __launch_bounds__(256, 2) void gemm_mma(
    const uint16_t* __restrict__ A, const uint16_t* __restrict__ B,
    const float* __restrict__ bias, float* __restrict__ C,
    __half* __restrict__ Oh, int N, int K, int epi, int cs)
{
    extern __shared__ char smem[];
    const uint32_t sb = smem_to_u32(smem);
    const int tid = threadIdx.x;
    const int bm = blockIdx.y * BM;
    const int bn = blockIdx.x * BN;
    const int lda = (TERMS == 3) ? 2*K : K;
    const int cpt = K / BK;
    const int total = TERMS * cpt;

    const int wid = tid >> 5, lane = tid & 31;
    const int wm = wid & 1, wn = wid >> 1;

    float acc[4][4][4];
    #pragma unroll
    for (int mi = 0; mi < 4; mi++)
        #pragma unroll
        for (int ni = 0; ni < 4; ni++)
            #pragma unroll
            for (int r = 0; r < 4; r++) acc[mi][ni][r] = 0.f;

    auto load_chunk = [&](int c) {
        int a_col, b_col;
        if (TERMS == 3) {
            int t = c / cpt, kk = c - t*cpt;
            a_col = ((t == 2) ? K : 0) + kk*BK;
            b_col = ((t == 1) ? K : 0) + kk*BK;
        } else {
            a_col = c*BK; b_col = c*BK;
        }
        uint32_t stA = sb + (c % NSTG) * STG_BYTES;
        uint32_t stB = stA + BM * ROWB;
        #pragma unroll
        for (int i = 0; i < 2; i++) {
            int s = tid + i*256;
            int row = s >> 2, seg = s & 3;
            cp16(stA + row*ROWB + seg*16, A + (size_t)(bm + row)*lda + a_col + seg*8);
            cp16(stB + row*ROWB + seg*16, B + (size_t)(bn + row)*lda + b_col + seg*8);
        }
        cp_commit();
    };

    load_chunk(0); load_chunk(1); load_chunk(2);

    for (int c = 0; c < total; c++) {
        if (c <= total - 3)      asm volatile("cp.async.wait_group 2;\n" ::: "memory");
        else if (c == total - 2) asm volatile("cp.async.wait_group 1;\n" ::: "memory");
        else                     asm volatile("cp.async.wait_group 0;\n" ::: "memory");
        __syncthreads();
        if (c + 3 < total) load_chunk(c + 3);

        uint32_t stA = sb + (c % NSTG) * STG_BYTES;
        uint32_t stB = stA + BM * ROWB;
        #pragma unroll
        for (int ks = 0; ks < 2; ks++) {
            uint32_t a[4][4];
            #pragma unroll
            for (int mi = 0; mi < 4; mi++) {
                uint32_t addr = stA + (wm*64 + mi*16 + (lane & 15))*ROWB + ((lane >> 4)*16 + ks*32);
                asm volatile("ldmatrix.sync.aligned.m8n8.x4.shared.b16 {%0,%1,%2,%3}, [%4];"
                    : "=r"(a[mi][0]), "=r"(a[mi][1]), "=r"(a[mi][2]), "=r"(a[mi][3]) : "r"(addr));
            }
            uint32_t b[4][2];
            #pragma unroll
            for (int ni = 0; ni < 4; ni++) {
                uint32_t addr = stB + (wn*32 + ni*8 + (lane & 7))*ROWB + (((lane >> 3) & 1)*16 + ks*32);
                asm volatile("ldmatrix.sync.aligned.m8n8.x2.shared.b16 {%0,%1}, [%2];"
                    : "=r"(b[ni][0]), "=r"(b[ni][1]) : "r"(addr));
            }
            #pragma unroll
            for (int mi = 0; mi < 4; mi++)
                #pragma unroll
                for (int ni = 0; ni < 4; ni++) {
                    if (TERMS == 3) {
                        asm volatile(
                            "mma.sync.aligned.m16n8k16.row.col.f32.bf16.bf16.f32 "
                            "{%0,%1,%2,%3}, {%4,%5,%6,%7}, {%8,%9}, {%0,%1,%2,%3};"
                            : "+f"(acc[mi][ni][0]), "+f"(acc[mi][ni][1]),
                              "+f"(acc[mi][ni][2]), "+f"(acc[mi][ni][3])
                            : "r"(a[mi][0]), "r"(a[mi][1]), "r"(a[mi][2]), "r"(a[mi][3]),
                              "r"(b[ni][0]), "r"(b[ni][1]));
                    } else {
                        asm volatile(
                            "mma.sync.aligned.m16n8k16.row.col.f32.f16.f16.f32 "
                            "{%0,%1,%2,%3}, {%4,%5,%6,%7}, {%8,%9}, {%0,%1,%2,%3};"
                            : "+f"(acc[mi][ni][0]), "+f"(acc[mi][ni][1]),
                              "+f"(acc[mi][ni][2]), "+f"(acc[mi][ni][3])
                            : "r"(a[mi][0]), "r"(a[mi][1]), "r"(a[mi][2]), "r"(a[mi][3]),
                              "r"(b[ni][0]), "r"(b[ni][1]));
                    }
                }
        }
    }

    // ---- epilogue ----
    const int g = lane >> 2, tig = lane & 3;
    #pragma unroll
    for (int mi = 0; mi < 4; mi++) {
        #pragma unroll
        for (int ni = 0; ni < 4; ni++) {
            int r0 = bm + wm*64 + mi*16 + g;
            int cc = bn + wn*32 + ni*8 + tig*2;
            #pragma unroll
            for (int half = 0; half < 2; half++) {
                int r = r0 + half*8;
                float v0 = acc[mi][ni][half*2 + 0];
                float v1 = acc[mi][ni][half*2 + 1];
                if (epi == 0) {
                    float2 st; st.x = v0; st.y = v1;
                    *(float2*)&C[(size_t)r*cs + cc] = st;
                } else if (epi == 1) {
                    float2 bi  = *(const float2*)&bias[cc];
                    float2 res = *(const float2*)&C[(size_t)r*cs + cc];
                    float2 st; st.x = v0 + bi.x + res.x; st.y = v1 + bi.y + res.y;
                    *(float2*)&C[(size_t)r*cs + cc] = st;
                } else {
                    float2 bi = *(const float2*)&bias[cc];
                    float g0 = gelu_exact(v0 + bi.x);
                    float g1 = gelu_exact(v1 + bi.y);
                    *(__half2*)&Oh[(size_t)r*cs + cc] = __floats2half2_rn(g0, g1);
                }
            }
        }
    }
}

// ================= Host driver =================
extern "C" void kernel_launch(void* const* d_in, const int* in_sizes, int n_in,
                              void* d_out, int out_size) {
    const float* local_t  = (const float*)d_in[0];
    const float* region_t = (const float*)d_in[1];
    const float* emb      = (const float*)d_in[2];
    const float* attn_g   = (const float*)d_in[3];
    const float* attn_b   = (const float*)d_in[4];
    const float* wqkv     = (const float*)d_in[5];
    const float* wout     = (const float*)d_in[6];
    const float* bout     = (const float*)d_in[7];
    const float* mlp_g    = (const float*)d_in[8];
    const float* mlp_b    = (const float*)d_in[9];
    const float* w1       = (const float*)d_in[10];
    const float* b1       = (const float*)d_in[11];
    const float* w2       = (const float*)d_in[12];
    const float* b2       = (const float*)d_in[13];
    float* out = (float*)d_out;

    cudaFuncSetAttribute(gemm_mma<3>, cudaFuncAttributeMaxDynamicSharedMemorySize, SMEM_GEMM);
    cudaFuncSetAttribute(gemm_mma<1>, cudaFuncAttributeMaxDynamicSharedMemorySize, SMEM_GEMM);

    float *xw, *qkv, *biasT, *qkvr;
    __nv_bfloat16 *h, *o, *hr, *orr;
    __half *hh, *m1, *W1h, *W2h;
    __nv_bfloat16 *Wqkv, *Wout;
    cudaGetSymbolAddress((void**)&xw,   g_xw);
    cudaGetSymbolAddress((void**)&h,    g_h);
    cudaGetSymbolAddress((void**)&hh,   g_hh);
    cudaGetSymbolAddress((void**)&qkv,  g_qkv);
    cudaGetSymbolAddress((void**)&o,    g_o);
    cudaGetSymbolAddress((void**)&m1,   g_m1);
    cudaGetSymbolAddress((void**)&biasT,g_bias);
    cudaGetSymbolAddress((void**)&hr,   g_hr);
    cudaGetSymbolAddress((void**)&qkvr, g_qkvr);
    cudaGetSymbolAddress((void**)&orr,  g_or);
    cudaGetSymbolAddress((void**)&Wqkv, g_Wqkv);
    cudaGetSymbolAddress((void**)&Wout, g_Wout);
    cudaGetSymbolAddress((void**)&W1h,  g_W1h);
    cudaGetSymbolAddress((void**)&W2h,  g_W2h);

    // launch 1: pack, launch 2: weight conversion + bias table
    pack_kernel<<<(NROWS*DIMV + 255)/256, 256>>>(local_t, region_t);
    wconv_all<<<(WTOT + BIAS_N + 255)/256, 256>>>(wqkv, wout, w1, w2, emb);

    for (int l = 0; l < DEPTH; l++) {
        __nv_bfloat16* WqT = Wqkv + (size_t)l*3*DIMV*2*DIMV;
        __nv_bfloat16* WoT = Wout + (size_t)l*DIMV*2*DIMV;
        __half* W1T = W1h + (size_t)l*SEG_W1;
        __half* W2T = W2h + (size_t)l*SEG_W2;
        const float* Bout = bout + (size_t)l*DIMV;
        const float* B1   = b1   + (size_t)l*4*DIMV;
        const float* B2   = b2   + (size_t)l*DIMV;
        const float* Ag   = attn_g + (size_t)l*DIMV;
        const float* Ab   = attn_b + (size_t)l*DIMV;
        const float* Mg   = mlp_g  + (size_t)l*DIMV;
        const float* Mb   = mlp_b  + (size_t)l*DIMV;

        // ---- region self-attention (strided LN in / strided residual out; no gather/scatter) ----
        ln_split<<<NWIN, 128>>>(xw, NTOK*DIMV, Ag, Ab, hr);   // launch 3 (layer 0)
        gemm_mma<3><<<dim3(3*DIMV/BN, NWIN/BM), 256, SMEM_GEMM>>>(     // launch 4 <- profiled
            (const uint16_t*)hr, (const uint16_t*)WqT, nullptr, qkvr, nullptr, 3*DIMV, DIMV, 0, 3*DIMV);
        attn_kernel<64><<<dim3(NB, HEADS), 256>>>(qkvr, nullptr, orr);
        gemm_mma<3><<<dim3(DIMV/BN, NWIN/BM), 256, SMEM_GEMM>>>(
            (const uint16_t*)orr, (const uint16_t*)WoT, Bout, xw, nullptr, DIMV, DIMV, 1, NTOK*DIMV);

        // ---- window attention ----
        ln_split<<<NROWS, 128>>>(xw, DIMV, Ag, Ab, h);
        gemm_mma<3><<<dim3(3*DIMV/BN, NROWS/BM), 256, SMEM_GEMM>>>(
            (const uint16_t*)h, (const uint16_t*)WqT, nullptr, qkv, nullptr, 3*DIMV, DIMV, 0, 3*DIMV);
        attn_kernel<NTOK><<<dim3(NWIN, HEADS), 256>>>(qkv, biasT, o);
        gemm_mma<3><<<dim3(DIMV/BN, NROWS/BM), 256, SMEM_GEMM>>>(
            (const uint16_t*)o, (const uint16_t*)WoT, Bout, xw, nullptr, DIMV, DIMV, 1, DIMV);

        // ---- MLP (fp16 single-precision GEMMs) ----
        ln_half<<<NROWS, 128>>>(xw, Mg, Mb, hh);
        gemm_mma<1><<<dim3(4*DIMV/BN, NROWS/BM), 256, SMEM_GEMM>>>(
            (const uint16_t*)hh, (const uint16_t*)W1T, B1, nullptr, m1, 4*DIMV, DIMV, 2, 4*DIMV);
        gemm_mma<1><<<dim3(DIMV/BN, NROWS/BM), 256, SMEM_GEMM>>>(
            (const uint16_t*)m1, (const uint16_t*)W2T, B2, xw, nullptr, DIMV, 4*DIMV, 1, DIMV);
    }

    unpack_kernel<<<(NROWS*DIMV + 255)/256, 256>>>(out);
}

// round 7
// speedup vs baseline: 2.3353x; 1.3097x over previous
#include <cuda_runtime.h>
#include <cuda_fp16.h>
#include <math.h>
#include <stdint.h>

// ---------------- Problem constants ----------------
#define DIMV    512
#define HEADS   16
#define DHEAD   32
#define NWIN    512          // B * RH * RW
#define NTOK    65           // 1 region + 64 local
#define NROWS   (NWIN*NTOK)  // 33280 (= 260 * 128)
#define NB      8
#define DEPTH   4
#define QSCALE  0.17677669529663687f
#define LOCAL_ELEMS (8*64*64*512)

// ---------------- helpers ----------------
__device__ __forceinline__ uint32_t smem_to_u32(const void* p) {
    uint32_t a;
    asm("{ .reg .u64 t; cvta.to.shared.u64 t, %1; cvt.u32.u64 %0, t; }" : "=r"(a) : "l"(p));
    return a;
}
__device__ __forceinline__ void cp16(uint32_t dst, const void* src) {
    asm volatile("cp.async.cg.shared.global [%0], [%1], 16;\n" :: "r"(dst), "l"(src));
}
__device__ __forceinline__ void cp_commit() { asm volatile("cp.async.commit_group;\n" ::: "memory"); }
__device__ __forceinline__ float gelu_exact(float x) {
    return 0.5f * x * (1.0f + erff(x * 0.70710678118654752f));
}

// ================= Scratch (device globals) =================
__device__ __align__(16) float  g_xw  [NROWS*DIMV];     // residual stream (windowed, fp32)
__device__ __align__(16) __half g_h   [NROWS*DIMV];     // LN out (attn or mlp), fp16
__device__ __align__(16) float  g_qkv [NROWS*3*DIMV];
__device__ __align__(16) __half g_o   [NROWS*DIMV];     // attn out, fp16
__device__ __align__(16) __half g_m1  [NROWS*4*DIMV];   // MLP hidden, fp16
__device__ __align__(16) float  g_bias[HEADS*NTOK*NTOK];
__device__ __align__(16) __half g_hr  [NWIN*DIMV];
__device__ __align__(16) float  g_qkvr[NWIN*3*DIMV];
__device__ __align__(16) __half g_or  [NWIN*DIMV];
// Weights transposed fp16 [N][K]
__device__ __align__(16) __half g_Wqkv[DEPTH*3*DIMV*DIMV];
__device__ __align__(16) __half g_Wout[DEPTH*DIMV*DIMV];
__device__ __align__(16) __half g_W1h [DEPTH*4*DIMV*DIMV];
__device__ __align__(16) __half g_W2h [DEPTH*DIMV*4*DIMV];

// ================= pack / unpack =================
__global__ void pack_kernel(const float* __restrict__ local_t, const float* __restrict__ region_t) {
    int idx = blockIdx.x * blockDim.x + threadIdx.x;
    if (idx >= NROWS*DIMV) return;
    int d = idx & 511, row = idx >> 9;
    int win = row / NTOK, t = row - win*NTOK;
    float v;
    if (t == 0) v = region_t[win*DIMV + d];
    else {
        int a = t - 1, p1 = a >> 3, p2 = a & 7;
        int b = win >> 6, rh = (win >> 3) & 7, rw = win & 7;
        v = local_t[(((b*64) + (rh*8 + p1))*64 + (rw*8 + p2))*DIMV + d];
    }
    g_xw[idx] = v;
}

__global__ void unpack_kernel(float* __restrict__ out) {
    int idx = blockIdx.x * blockDim.x + threadIdx.x;
    if (idx >= NROWS*DIMV) return;
    if (idx < LOCAL_ELEMS) {
        int d = idx & 511, p = idx >> 9;
        int col = p & 63, rowi = (p >> 6) & 63, b = p >> 12;
        int rh = rowi >> 3, p1 = rowi & 7, rw = col >> 3, p2 = col & 7;
        int win = b*64 + rh*8 + rw, t = 1 + p1*8 + p2;
        out[idx] = g_xw[(win*NTOK + t)*DIMV + d];
    } else {
        int r = idx - LOCAL_ELEMS, w = r >> 9, d = r & 511;
        out[idx] = g_xw[(w*NTOK)*DIMV + d];
    }
}

// ---- fused weight conversion (all layers, all fp16) + rel-pos bias, ONE launch ----
#define SEG_QKV (3*DIMV*DIMV)
#define SEG_OUT (DIMV*DIMV)
#define SEG_W1  (DIMV*4*DIMV)
#define SEG_W2  (4*DIMV*DIMV)
#define SEG_TOT (SEG_QKV+SEG_OUT+SEG_W1+SEG_W2)
#define WTOT    (DEPTH*SEG_TOT)
#define BIAS_N  (HEADS*NTOK*NTOK)

__global__ void wconv_all(const float* __restrict__ wqkv, const float* __restrict__ wout,
                          const float* __restrict__ w1, const float* __restrict__ w2,
                          const float* __restrict__ emb) {
    int idx = blockIdx.x * blockDim.x + threadIdx.x;
    if (idx < WTOT) {
        int l = idx / SEG_TOT;
        int r = idx - l*SEG_TOT;
        const float* W; __half* O; int K, N;
        if (r < SEG_QKV) {
            W = wqkv + (size_t)l*SEG_QKV; O = g_Wqkv + (size_t)l*SEG_QKV; K = DIMV; N = 3*DIMV;
        } else if (r < SEG_QKV + SEG_OUT) {
            r -= SEG_QKV;
            W = wout + (size_t)l*SEG_OUT; O = g_Wout + (size_t)l*SEG_OUT; K = DIMV; N = DIMV;
        } else if (r < SEG_QKV + SEG_OUT + SEG_W1) {
            r -= SEG_QKV + SEG_OUT;
            W = w1 + (size_t)l*SEG_W1; O = g_W1h + (size_t)l*SEG_W1; K = DIMV; N = 4*DIMV;
        } else {
            r -= SEG_QKV + SEG_OUT + SEG_W1;
            W = w2 + (size_t)l*SEG_W2; O = g_W2h + (size_t)l*SEG_W2; K = 4*DIMV; N = DIMV;
        }
        int n = r / K, k = r - n*K;
        O[(size_t)n*K + k] = __float2half_rn(W[(size_t)k*N + n]);
    } else {
        int r = idx - WTOT;
        if (r >= BIAS_N) return;
        int h = r / (NTOK*NTOK);
        int q = r - h*NTOK*NTOK;
        int i = q / NTOK, j = q - i*NTOK;
        float v = 0.f;
        if (i > 0 && j > 0) {
            int a = i - 1, b = j - 1;
            int r0 = (a >> 3) - (b >> 3) + 7;
            int r1 = (a & 7) - (b & 7) + 7;
            v = emb[(r0 + r1*15)*HEADS + h];
        }
        g_bias[r] = v;
    }
}

// ================= LayerNorm -> fp16 (strided input) =================
__global__ void ln_half(const float* __restrict__ x, int instr, const float* __restrict__ g,
                        const float* __restrict__ b, __half* __restrict__ y) {
    int row = blockIdx.x;
    int t = threadIdx.x;
    const float4* xv = (const float4*)(x + (size_t)row*instr);
    float4 v = xv[t];
    float s  = v.x + v.y + v.z + v.w;
    float s2 = v.x*v.x + v.y*v.y + v.z*v.z + v.w*v.w;
    #pragma unroll
    for (int off = 16; off; off >>= 1) {
        s  += __shfl_xor_sync(0xffffffffu, s,  off);
        s2 += __shfl_xor_sync(0xffffffffu, s2, off);
    }
    __shared__ float sh[8];
    int wid = t >> 5, lane = t & 31;
    if (lane == 0) { sh[wid] = s; sh[4 + wid] = s2; }
    __syncthreads();
    float st  = sh[0] + sh[1] + sh[2] + sh[3];
    float s2t = sh[4] + sh[5] + sh[6] + sh[7];
    float mean = st * (1.f/512.f);
    float var  = s2t * (1.f/512.f) - mean*mean;
    float rstd = rsqrtf(var + 1e-3f);
    float4 gg = ((const float4*)g)[t];
    float4 bb = ((const float4*)b)[t];
    __half2 o01 = __floats2half2_rn((v.x - mean)*rstd*gg.x + bb.x, (v.y - mean)*rstd*gg.y + bb.y);
    __half2 o23 = __floats2half2_rn((v.z - mean)*rstd*gg.z + bb.z, (v.w - mean)*rstd*gg.w + bb.w);
    __half2* p = (__half2*)(y + (size_t)row*DIMV + 4*t);
    p[0] = o01; p[1] = o23;
}

// ================= Attention (fp32 math, fp16 output) =================
template<int NT>
__global__ __launch_bounds__(256) void attn_kernel(const float* __restrict__ qkv,
                                                   const float* __restrict__ biasTab,
                                                   __half* __restrict__ o) {
    __shared__ float qs[NT][33];
    __shared__ float ks[NT][33];
    __shared__ float vs[NT][33];
    __shared__ float ss[NT][NT + 1];
    const int grp = blockIdx.x;
    const int h   = blockIdx.y;
    const int base = grp * NT;
    const int tid = threadIdx.x;

    for (int p = tid; p < NT * DHEAD; p += 256) {
        int i = p >> 5, d = p & 31;
        const float* row = qkv + (size_t)(base + i) * (3*DIMV) + h*DHEAD + d;
        qs[i][d] = row[0] * QSCALE;
        ks[i][d] = row[DIMV];
        vs[i][d] = row[2*DIMV];
    }
    __syncthreads();

    for (int p = tid; p < NT * NT; p += 256) {
        int i = p / NT, j = p - i*NT;
        float acc = 0.f;
        #pragma unroll
        for (int d = 0; d < 32; d++) acc += qs[i][d] * ks[j][d];
        if (biasTab) acc += biasTab[(h*NT + i)*NT + j];
        ss[i][j] = acc;
    }
    __syncthreads();

    int wid = tid >> 5, lane = tid & 31;
    for (int i = wid; i < NT; i += 8) {
        float m = -1e30f;
        for (int j = lane; j < NT; j += 32) m = fmaxf(m, ss[i][j]);
        #pragma unroll
        for (int off = 16; off; off >>= 1) m = fmaxf(m, __shfl_xor_sync(0xffffffffu, m, off));
        float sum = 0.f;
        for (int j = lane; j < NT; j += 32) { float e = __expf(ss[i][j] - m); ss[i][j] = e; sum += e; }
        #pragma unroll
        for (int off = 16; off; off >>= 1) sum += __shfl_xor_sync(0xffffffffu, sum, off);
        float inv = 1.f / sum;
        for (int j = lane; j < NT; j += 32) ss[i][j] *= inv;
    }
    __syncthreads();

    for (int p = tid; p < NT * DHEAD; p += 256) {
        int i = p >> 5, d = p & 31;
        float acc = 0.f;
        #pragma unroll 5
        for (int j = 0; j < NT; j++) acc += ss[i][j] * vs[j][d];
        o[(size_t)(base + i) * DIMV + h*DHEAD + d] = __float2half_rn(acc);
    }
}

// ================= fp16 GEMM via mma.sync =================
// C[M,N] = sum_k A[m,k]*B[n,k]; A [row][K] fp16, B [n][K] fp16.
// epi 0: C = AB (fp32, row stride cs)
// epi 1: C = AB + bias + C (fp32 residual in place, row stride cs)
// epi 2: Oh = gelu(AB + bias) (fp16, row stride cs)
#define BM 128
#define BN 128
#define BK 32
#define NSTG 4
#define ROWB 80
#define STG_BYTES ((BM + BN) * ROWB)
#define SMEM_GEMM (NSTG * STG_BYTES)

__global__ __launch_bounds__(256, 2) void gemm_mma(
    const __half* __restrict__ A, const __half* __restrict__ B,
    const float* __restrict__ bias, float* __restrict__ C,
    __half* __restrict__ Oh, int N, int K, int epi, int cs)
{
    extern __shared__ char smem[];
    const uint32_t sb = smem_to_u32(smem);
    const int tid = threadIdx.x;
    const int bm = blockIdx.y * BM;
    const int bn = blockIdx.x * BN;
    const int total = K / BK;

    const int wid = tid >> 5, lane = tid & 31;
    const int wm = wid & 1, wn = wid >> 1;

    float acc[4][4][4];
    #pragma unroll
    for (int mi = 0; mi < 4; mi++)
        #pragma unroll
        for (int ni = 0; ni < 4; ni++)
            #pragma unroll
            for (int r = 0; r < 4; r++) acc[mi][ni][r] = 0.f;

    auto load_chunk = [&](int c) {
        int col = c*BK;
        uint32_t stA = sb + (c % NSTG) * STG_BYTES;
        uint32_t stB = stA + BM * ROWB;
        #pragma unroll
        for (int i = 0; i < 2; i++) {
            int s = tid + i*256;
            int row = s >> 2, seg = s & 3;
            cp16(stA + row*ROWB + seg*16, A + (size_t)(bm + row)*K + col + seg*8);
            cp16(stB + row*ROWB + seg*16, B + (size_t)(bn + row)*K + col + seg*8);
        }
        cp_commit();
    };

    load_chunk(0);
    if (total > 1) load_chunk(1);
    if (total > 2) load_chunk(2);

    for (int c = 0; c < total; c++) {
        if (c <= total - 3)      asm volatile("cp.async.wait_group 2;\n" ::: "memory");
        else if (c == total - 2) asm volatile("cp.async.wait_group 1;\n" ::: "memory");
        else                     asm volatile("cp.async.wait_group 0;\n" ::: "memory");
        __syncthreads();
        if (c + 3 < total) load_chunk(c + 3);

        uint32_t stA = sb + (c % NSTG) * STG_BYTES;
        uint32_t stB = stA + BM * ROWB;
        #pragma unroll
        for (int ks = 0; ks < 2; ks++) {
            uint32_t a[4][4];
            #pragma unroll
            for (int mi = 0; mi < 4; mi++) {
                uint32_t addr = stA + (wm*64 + mi*16 + (lane & 15))*ROWB + ((lane >> 4)*16 + ks*32);
                asm volatile("ldmatrix.sync.aligned.m8n8.x4.shared.b16 {%0,%1,%2,%3}, [%4];"
                    : "=r"(a[mi][0]), "=r"(a[mi][1]), "=r"(a[mi][2]), "=r"(a[mi][3]) : "r"(addr));
            }
            uint32_t b[4][2];
            #pragma unroll
            for (int ni = 0; ni < 4; ni++) {
                uint32_t addr = stB + (wn*32 + ni*8 + (lane & 7))*ROWB + (((lane >> 3) & 1)*16 + ks*32);
                asm volatile("ldmatrix.sync.aligned.m8n8.x2.shared.b16 {%0,%1}, [%2];"
                    : "=r"(b[ni][0]), "=r"(b[ni][1]) : "r"(addr));
            }
            #pragma unroll
            for (int mi = 0; mi < 4; mi++)
                #pragma unroll
                for (int ni = 0; ni < 4; ni++) {
                    asm volatile(
                        "mma.sync.aligned.m16n8k16.row.col.f32.f16.f16.f32 "
                        "{%0,%1,%2,%3}, {%4,%5,%6,%7}, {%8,%9}, {%0,%1,%2,%3};"
                        : "+f"(acc[mi][ni][0]), "+f"(acc[mi][ni][1]),
                          "+f"(acc[mi][ni][2]), "+f"(acc[mi][ni][3])
                        : "r"(a[mi][0]), "r"(a[mi][1]), "r"(a[mi][2]), "r"(a[mi][3]),
                          "r"(b[ni][0]), "r"(b[ni][1]));
                }
        }
    }

    // ---- epilogue ----
    const int g = lane >> 2, tig = lane & 3;
    #pragma unroll
    for (int mi = 0; mi < 4; mi++) {
        #pragma unroll
        for (int ni = 0; ni < 4; ni++) {
            int r0 = bm + wm*64 + mi*16 + g;
            int cc = bn + wn*32 + ni*8 + tig*2;
            #pragma unroll
            for (int half = 0; half < 2; half++) {
                int r = r0 + half*8;
                float v0 = acc[mi][ni][half*2 + 0];
                float v1 = acc[mi][ni][half*2 + 1];
                if (epi == 0) {
                    float2 st; st.x = v0; st.y = v1;
                    *(float2*)&C[(size_t)r*cs + cc] = st;
                } else if (epi == 1) {
                    float2 bi  = *(const float2*)&bias[cc];
                    float2 res = *(const float2*)&C[(size_t)r*cs + cc];
                    float2 st; st.x = v0 + bi.x + res.x; st.y = v1 + bi.y + res.y;
                    *(float2*)&C[(size_t)r*cs + cc] = st;
                } else {
                    float2 bi = *(const float2*)&bias[cc];
                    float g0 = gelu_exact(v0 + bi.x);
                    float g1 = gelu_exact(v1 + bi.y);
                    *(__half2*)&Oh[(size_t)r*cs + cc] = __floats2half2_rn(g0, g1);
                }
            }
        }
    }
}

// ================= Host driver =================
extern "C" void kernel_launch(void* const* d_in, const int* in_sizes, int n_in,
                              void* d_out, int out_size) {
    const float* local_t  = (const float*)d_in[0];
    const float* region_t = (const float*)d_in[1];
    const float* emb      = (const float*)d_in[2];
    const float* attn_g   = (const float*)d_in[3];
    const float* attn_b   = (const float*)d_in[4];
    const float* wqkv     = (const float*)d_in[5];
    const float* wout     = (const float*)d_in[6];
    const float* bout     = (const float*)d_in[7];
    const float* mlp_g    = (const float*)d_in[8];
    const float* mlp_b    = (const float*)d_in[9];
    const float* w1       = (const float*)d_in[10];
    const float* b1       = (const float*)d_in[11];
    const float* w2       = (const float*)d_in[12];
    const float* b2       = (const float*)d_in[13];
    float* out = (float*)d_out;

    cudaFuncSetAttribute(gemm_mma, cudaFuncAttributeMaxDynamicSharedMemorySize, SMEM_GEMM);

    float *xw, *qkv, *biasT, *qkvr;
    __half *h, *o, *m1, *hr, *orr, *Wqkv, *Wout, *W1h, *W2h;
    cudaGetSymbolAddress((void**)&xw,   g_xw);
    cudaGetSymbolAddress((void**)&h,    g_h);
    cudaGetSymbolAddress((void**)&qkv,  g_qkv);
    cudaGetSymbolAddress((void**)&o,    g_o);
    cudaGetSymbolAddress((void**)&m1,   g_m1);
    cudaGetSymbolAddress((void**)&biasT,g_bias);
    cudaGetSymbolAddress((void**)&hr,   g_hr);
    cudaGetSymbolAddress((void**)&qkvr, g_qkvr);
    cudaGetSymbolAddress((void**)&orr,  g_or);
    cudaGetSymbolAddress((void**)&Wqkv, g_Wqkv);
    cudaGetSymbolAddress((void**)&Wout, g_Wout);
    cudaGetSymbolAddress((void**)&W1h,  g_W1h);
    cudaGetSymbolAddress((void**)&W2h,  g_W2h);

    pack_kernel<<<(NROWS*DIMV + 255)/256, 256>>>(local_t, region_t);
    wconv_all<<<(WTOT + BIAS_N + 255)/256, 256>>>(wqkv, wout, w1, w2, emb);

    for (int l = 0; l < DEPTH; l++) {
        __half* WqT = Wqkv + (size_t)l*SEG_QKV;
        __half* WoT = Wout + (size_t)l*SEG_OUT;
        __half* W1T = W1h + (size_t)l*SEG_W1;
        __half* W2T = W2h + (size_t)l*SEG_W2;
        const float* Bout = bout + (size_t)l*DIMV;
        const float* B1   = b1   + (size_t)l*4*DIMV;
        const float* B2   = b2   + (size_t)l*DIMV;
        const float* Ag   = attn_g + (size_t)l*DIMV;
        const float* Ab   = attn_b + (size_t)l*DIMV;
        const float* Mg   = mlp_g  + (size_t)l*DIMV;
        const float* Mb   = mlp_b  + (size_t)l*DIMV;

        // ---- region self-attention (strided LN in / strided residual out) ----
        ln_half<<<NWIN, 128>>>(xw, NTOK*DIMV, Ag, Ab, hr);
        gemm_mma<<<dim3(3*DIMV/BN, NWIN/BM), 256, SMEM_GEMM>>>(
            hr, WqT, nullptr, qkvr, nullptr, 3*DIMV, DIMV, 0, 3*DIMV);
        attn_kernel<64><<<dim3(NB, HEADS), 256>>>(qkvr, nullptr, orr);
        gemm_mma<<<dim3(DIMV/BN, NWIN/BM), 256, SMEM_GEMM>>>(
            orr, WoT, Bout, xw, nullptr, DIMV, DIMV, 1, NTOK*DIMV);

        // ---- window attention ----
        ln_half<<<NROWS, 128>>>(xw, DIMV, Ag, Ab, h);
        gemm_mma<<<dim3(3*DIMV/BN, NROWS/BM), 256, SMEM_GEMM>>>(
            h, WqT, nullptr, qkv, nullptr, 3*DIMV, DIMV, 0, 3*DIMV);
        attn_kernel<NTOK><<<dim3(NWIN, HEADS), 256>>>(qkv, biasT, o);
        gemm_mma<<<dim3(DIMV/BN, NROWS/BM), 256, SMEM_GEMM>>>(
            o, WoT, Bout, xw, nullptr, DIMV, DIMV, 1, DIMV);

        // ---- MLP ----
        ln_half<<<NROWS, 128>>>(xw, DIMV, Mg, Mb, h);
        gemm_mma<<<dim3(4*DIMV/BN, NROWS/BM), 256, SMEM_GEMM>>>(
            h, W1T, B1, nullptr, m1, 4*DIMV, DIMV, 2, 4*DIMV);
        gemm_mma<<<dim3(DIMV/BN, NROWS/BM), 256, SMEM_GEMM>>>(
            m1, W2T, B2, xw, nullptr, DIMV, 4*DIMV, 1, DIMV);
    }

    unpack_kernel<<<(NROWS*DIMV + 255)/256, 256>>>(out);
}

// round 9
// speedup vs baseline: 2.5837x; 1.1064x over previous
#include <cuda_runtime.h>
#include <cuda_fp16.h>
#include <math.h>
#include <stdint.h>

// ---------------- Problem constants ----------------
#define DIMV    512
#define HEADS   16
#define DHEAD   32
#define NWIN    512          // B * RH * RW
#define NTOK    65           // 1 region + 64 local
#define NROWS   (NWIN*NTOK)  // 33280 (= 260 * 128)
#define NB      8
#define DEPTH   4
#define QSCALE  0.17677669529663687f
#define LOCAL_ELEMS (8*64*64*512)

// ---------------- helpers ----------------
__device__ __forceinline__ uint32_t smem_to_u32(const void* p) {
    uint32_t a;
    asm("{ .reg .u64 t; cvta.to.shared.u64 t, %1; cvt.u32.u64 %0, t; }" : "=r"(a) : "l"(p));
    return a;
}
__device__ __forceinline__ void cp16(uint32_t dst, const void* src) {
    asm volatile("cp.async.cg.shared.global [%0], [%1], 16;\n" :: "r"(dst), "l"(src));
}
__device__ __forceinline__ void cp_commit() { asm volatile("cp.async.commit_group;\n" ::: "memory"); }
__device__ __forceinline__ float gelu_exact(float x) {
    return 0.5f * x * (1.0f + erff(x * 0.70710678118654752f));
}

// ================= Scratch (device globals) =================
__device__ __align__(16) float  g_xw  [NROWS*DIMV];     // residual stream (windowed, fp32)
__device__ __align__(16) __half g_h   [NROWS*DIMV];     // LN out, fp16
__device__ __align__(16) __half g_qkv [NROWS*3*DIMV];   // qkv, fp16
__device__ __align__(16) __half g_o   [NROWS*DIMV];     // attn out, fp16
__device__ __align__(16) __half g_m1  [NROWS*4*DIMV];   // MLP hidden, fp16
__device__ __align__(16) float  g_bias[HEADS*NTOK*NTOK];
__device__ __align__(16) __half g_hr  [NWIN*DIMV];
__device__ __align__(16) __half g_qkvr[NWIN*3*DIMV];
__device__ __align__(16) __half g_or  [NWIN*DIMV];
// Weights transposed fp16 [N][K]
__device__ __align__(16) __half g_Wqkv[DEPTH*3*DIMV*DIMV];
__device__ __align__(16) __half g_Wout[DEPTH*DIMV*DIMV];
__device__ __align__(16) __half g_W1h [DEPTH*4*DIMV*DIMV];
__device__ __align__(16) __half g_W2h [DEPTH*DIMV*4*DIMV];

// ================= pack / unpack =================
__global__ void pack_kernel(const float* __restrict__ local_t, const float* __restrict__ region_t) {
    int idx = blockIdx.x * blockDim.x + threadIdx.x;
    if (idx >= NROWS*DIMV) return;
    int d = idx & 511, row = idx >> 9;
    int win = row / NTOK, t = row - win*NTOK;
    float v;
    if (t == 0) v = region_t[win*DIMV + d];
    else {
        int a = t - 1, p1 = a >> 3, p2 = a & 7;
        int b = win >> 6, rh = (win >> 3) & 7, rw = win & 7;
        v = local_t[(((b*64) + (rh*8 + p1))*64 + (rw*8 + p2))*DIMV + d];
    }
    g_xw[idx] = v;
}

__global__ void unpack_kernel(float* __restrict__ out) {
    int idx = blockIdx.x * blockDim.x + threadIdx.x;
    if (idx >= NROWS*DIMV) return;
    if (idx < LOCAL_ELEMS) {
        int d = idx & 511, p = idx >> 9;
        int col = p & 63, rowi = (p >> 6) & 63, b = p >> 12;
        int rh = rowi >> 3, p1 = rowi & 7, rw = col >> 3, p2 = col & 7;
        int win = b*64 + rh*8 + rw, t = 1 + p1*8 + p2;
        out[idx] = g_xw[(win*NTOK + t)*DIMV + d];
    } else {
        int r = idx - LOCAL_ELEMS, w = r >> 9, d = r & 511;
        out[idx] = g_xw[(w*NTOK)*DIMV + d];
    }
}

// ---- fused weight conversion (all layers, all fp16) + rel-pos bias, ONE launch ----
#define SEG_QKV (3*DIMV*DIMV)
#define SEG_OUT (DIMV*DIMV)
#define SEG_W1  (DIMV*4*DIMV)
#define SEG_W2  (4*DIMV*DIMV)
#define SEG_TOT (SEG_QKV+SEG_OUT+SEG_W1+SEG_W2)
#define WTOT    (DEPTH*SEG_TOT)
#define BIAS_N  (HEADS*NTOK*NTOK)

__global__ void wconv_all(const float* __restrict__ wqkv, const float* __restrict__ wout,
                          const float* __restrict__ w1, const float* __restrict__ w2,
                          const float* __restrict__ emb) {
    int idx = blockIdx.x * blockDim.x + threadIdx.x;
    if (idx < WTOT) {
        int l = idx / SEG_TOT;
        int r = idx - l*SEG_TOT;
        const float* W; __half* O; int K, N;
        if (r < SEG_QKV) {
            W = wqkv + (size_t)l*SEG_QKV; O = g_Wqkv + (size_t)l*SEG_QKV; K = DIMV; N = 3*DIMV;
        } else if (r < SEG_QKV + SEG_OUT) {
            r -= SEG_QKV;
            W = wout + (size_t)l*SEG_OUT; O = g_Wout + (size_t)l*SEG_OUT; K = DIMV; N = DIMV;
        } else if (r < SEG_QKV + SEG_OUT + SEG_W1) {
            r -= SEG_QKV + SEG_OUT;
            W = w1 + (size_t)l*SEG_W1; O = g_W1h + (size_t)l*SEG_W1; K = DIMV; N = 4*DIMV;
        } else {
            r -= SEG_QKV + SEG_OUT + SEG_W1;
            W = w2 + (size_t)l*SEG_W2; O = g_W2h + (size_t)l*SEG_W2; K = 4*DIMV; N = DIMV;
        }
        int n = r / K, k = r - n*K;
        O[(size_t)n*K + k] = __float2half_rn(W[(size_t)k*N + n]);
    } else {
        int r = idx - WTOT;
        if (r >= BIAS_N) return;
        int h = r / (NTOK*NTOK);
        int q = r - h*NTOK*NTOK;
        int i = q / NTOK, j = q - i*NTOK;
        float v = 0.f;
        if (i > 0 && j > 0) {
            int a = i - 1, b = j - 1;
            int r0 = (a >> 3) - (b >> 3) + 7;
            int r1 = (a & 7) - (b & 7) + 7;
            v = emb[(r0 + r1*15)*HEADS + h];
        }
        g_bias[r] = v;
    }
}

// ================= LayerNorm -> fp16 (strided input) =================
__global__ void ln_half(const float* __restrict__ x, int instr, const float* __restrict__ g,
                        const float* __restrict__ b, __half* __restrict__ y) {
    int row = blockIdx.x;
    int t = threadIdx.x;
    const float4* xv = (const float4*)(x + (size_t)row*instr);
    float4 v = xv[t];
    float s  = v.x + v.y + v.z + v.w;
    float s2 = v.x*v.x + v.y*v.y + v.z*v.z + v.w*v.w;
    #pragma unroll
    for (int off = 16; off; off >>= 1) {
        s  += __shfl_xor_sync(0xffffffffu, s,  off);
        s2 += __shfl_xor_sync(0xffffffffu, s2, off);
    }
    __shared__ float sh[8];
    int wid = t >> 5, lane = t & 31;
    if (lane == 0) { sh[wid] = s; sh[4 + wid] = s2; }
    __syncthreads();
    float st  = sh[0] + sh[1] + sh[2] + sh[3];
    float s2t = sh[4] + sh[5] + sh[6] + sh[7];
    float mean = st * (1.f/512.f);
    float var  = s2t * (1.f/512.f) - mean*mean;
    float rstd = rsqrtf(var + 1e-3f);
    float4 gg = ((const float4*)g)[t];
    float4 bb = ((const float4*)b)[t];
    __half2 o01 = __floats2half2_rn((v.x - mean)*rstd*gg.x + bb.x, (v.y - mean)*rstd*gg.y + bb.y);
    __half2 o23 = __floats2half2_rn((v.z - mean)*rstd*gg.z + bb.z, (v.w - mean)*rstd*gg.w + bb.w);
    __half2* p = (__half2*)(y + (size_t)row*DIMV + 4*t);
    p[0] = o01; p[1] = o23;
}

// ================= Attention v2 (fp16 in, transposed K, conflict-free float4) =================
#define KSW 68   // ks_t row width in floats (17 float4s)
template<int NT>
__global__ __launch_bounds__(256) void attn_kernel(const __half* __restrict__ qkv,
                                                   const float* __restrict__ biasTab,
                                                   __half* __restrict__ o) {
    __shared__ __align__(16) float qs[NT][33];
    __shared__ __align__(16) float ks_t[32][KSW];   // K transposed: [d][token]
    __shared__ __align__(16) float vs[NT][36];      // 9 float4 per row
    __shared__ __align__(16) float ss[NT][NT + 1];
    const int grp = blockIdx.x;
    const int h   = blockIdx.y;
    const int base = grp * NT;
    const int tid = threadIdx.x;
    constexpr int JB = (NT + 3) / 4;     // 17 for 65, 16 for 64

    for (int p = tid; p < NT * DHEAD; p += 256) {
        int i = p >> 5, d = p & 31;
        const __half* row = qkv + (size_t)(base + i) * (3*DIMV) + h*DHEAD + d;
        qs[i][d]   = __half2float(row[0]) * QSCALE;
        ks_t[d][i] = __half2float(row[DIMV]);
        vs[i][d]   = __half2float(row[2*DIMV]);
    }
    // zero the ks_t padding columns so tail float4 reads are clean
    for (int p = tid; p < 32*(KSW - NT); p += 256) {
        int d = p / (KSW - NT), c = p - d*(KSW - NT);
        ks_t[d][NT + c] = 0.f;
    }
    __syncthreads();

    // sim = q @ k^T (+ bias): each item covers (i, 4 j's); K reads are consecutive float4s
    for (int p = tid; p < NT * JB; p += 256) {
        int i = p / JB, jb = p - i*JB;
        float4 acc; acc.x = 0.f; acc.y = 0.f; acc.z = 0.f; acc.w = 0.f;
        const float*  qrow = qs[i];
        const float4* kt4  = (const float4*)ks_t;   // row stride KSW/4 = 17
        #pragma unroll
        for (int d = 0; d < 32; d++) {
            float qv = qrow[d];
            float4 kv = kt4[d*(KSW/4) + jb];
            acc.x += qv*kv.x; acc.y += qv*kv.y; acc.z += qv*kv.z; acc.w += qv*kv.w;
        }
        int j0 = jb*4;
        float a[4] = {acc.x, acc.y, acc.z, acc.w};
        #pragma unroll
        for (int u = 0; u < 4; u++) {
            int j = j0 + u;
            if (j < NT) {
                float v = a[u];
                if (biasTab) v += biasTab[(h*NT + i)*NT + j];
                ss[i][j] = v;
            }
        }
    }
    __syncthreads();

    // softmax per row (warp per row)
    int wid = tid >> 5, lane = tid & 31;
    for (int i = wid; i < NT; i += 8) {
        float m = -1e30f;
        for (int j = lane; j < NT; j += 32) m = fmaxf(m, ss[i][j]);
        #pragma unroll
        for (int off = 16; off; off >>= 1) m = fmaxf(m, __shfl_xor_sync(0xffffffffu, m, off));
        float sum = 0.f;
        for (int j = lane; j < NT; j += 32) { float e = __expf(ss[i][j] - m); ss[i][j] = e; sum += e; }
        #pragma unroll
        for (int off = 16; off; off >>= 1) sum += __shfl_xor_sync(0xffffffffu, sum, off);
        float inv = 1.f / sum;
        for (int j = lane; j < NT; j += 32) ss[i][j] *= inv;
    }
    __syncthreads();

    // out = attn @ v : item = (i, 4 output dims); V reads consecutive float4s per lane
    for (int p = tid; p < NT * 8; p += 256) {
        int i = p >> 3, d4 = p & 7;
        float4 acc; acc.x = 0.f; acc.y = 0.f; acc.z = 0.f; acc.w = 0.f;
        const float*  srow = ss[i];
        const float4* v4   = (const float4*)vs;     // row stride 9
        #pragma unroll 5
        for (int j = 0; j < NT; j++) {
            float a = srow[j];
            float4 v = v4[j*9 + d4];
            acc.x += a*v.x; acc.y += a*v.y; acc.z += a*v.z; acc.w += a*v.w;
        }
        size_t ob = (size_t)(base + i) * DIMV + h*DHEAD + d4*4;
        *(__half2*)&o[ob]     = __floats2half2_rn(acc.x, acc.y);
        *(__half2*)&o[ob + 2] = __floats2half2_rn(acc.z, acc.w);
    }
}

// ================= fp16 GEMM via mma.sync =================
// epi 0: C = AB (fp32, stride cs)
// epi 1: C = AB + bias + C (fp32 residual in place, stride cs)
// epi 2: Oh = gelu(AB + bias) (fp16, stride cs)
// epi 3: Oh = AB (fp16, stride cs)
#define BM 128
#define BN 128
#define BK 32
#define NSTG 4
#define ROWB 80
#define STG_BYTES ((BM + BN) * ROWB)
#define SMEM_GEMM (NSTG * STG_BYTES)

__global__ __launch_bounds__(256, 2) void gemm_mma(
    const __half* __restrict__ A, const __half* __restrict__ B,
    const float* __restrict__ bias, float* __restrict__ C,
    __half* __restrict__ Oh, int N, int K, int epi, int cs)
{
    extern __shared__ char smem[];
    const uint32_t sb = smem_to_u32(smem);
    const int tid = threadIdx.x;
    const int bm = blockIdx.y * BM;
    const int bn = blockIdx.x * BN;
    const int total = K / BK;

    const int wid = tid >> 5, lane = tid & 31;
    const int wm = wid & 1, wn = wid >> 1;

    float acc[4][4][4];
    #pragma unroll
    for (int mi = 0; mi < 4; mi++)
        #pragma unroll
        for (int ni = 0; ni < 4; ni++)
            #pragma unroll
            for (int r = 0; r < 4; r++) acc[mi][ni][r] = 0.f;

    auto load_chunk = [&](int c) {
        int col = c*BK;
        uint32_t stA = sb + (c % NSTG) * STG_BYTES;
        uint32_t stB = stA + BM * ROWB;
        #pragma unroll
        for (int i = 0; i < 2; i++) {
            int s = tid + i*256;
            int row = s >> 2, seg = s & 3;
            cp16(stA + row*ROWB + seg*16, A + (size_t)(bm + row)*K + col + seg*8);
            cp16(stB + row*ROWB + seg*16, B + (size_t)(bn + row)*K + col + seg*8);
        }
        cp_commit();
    };

    load_chunk(0);
    if (total > 1) load_chunk(1);
    if (total > 2) load_chunk(2);

    for (int c = 0; c < total; c++) {
        if (c <= total - 3)      asm volatile("cp.async.wait_group 2;\n" ::: "memory");
        else if (c == total - 2) asm volatile("cp.async.wait_group 1;\n" ::: "memory");
        else                     asm volatile("cp.async.wait_group 0;\n" ::: "memory");
        __syncthreads();
        if (c + 3 < total) load_chunk(c + 3);

        uint32_t stA = sb + (c % NSTG) * STG_BYTES;
        uint32_t stB = stA + BM * ROWB;
        #pragma unroll
        for (int ks = 0; ks < 2; ks++) {
            uint32_t a[4][4];
            #pragma unroll
            for (int mi = 0; mi < 4; mi++) {
                uint32_t addr = stA + (wm*64 + mi*16 + (lane & 15))*ROWB + ((lane >> 4)*16 + ks*32);
                asm volatile("ldmatrix.sync.aligned.m8n8.x4.shared.b16 {%0,%1,%2,%3}, [%4];"
                    : "=r"(a[mi][0]), "=r"(a[mi][1]), "=r"(a[mi][2]), "=r"(a[mi][3]) : "r"(addr));
            }
            uint32_t b[4][2];
            #pragma unroll
            for (int ni = 0; ni < 4; ni++) {
                uint32_t addr = stB + (wn*32 + ni*8 + (lane & 7))*ROWB + (((lane >> 3) & 1)*16 + ks*32);
                asm volatile("ldmatrix.sync.aligned.m8n8.x2.shared.b16 {%0,%1}, [%2];"
                    : "=r"(b[ni][0]), "=r"(b[ni][1]) : "r"(addr));
            }
            #pragma unroll
            for (int mi = 0; mi < 4; mi++)
                #pragma unroll
                for (int ni = 0; ni < 4; ni++) {
                    asm volatile(
                        "mma.sync.aligned.m16n8k16.row.col.f32.f16.f16.f32 "
                        "{%0,%1,%2,%3}, {%4,%5,%6,%7}, {%8,%9}, {%0,%1,%2,%3};"
                        : "+f"(acc[mi][ni][0]), "+f"(acc[mi][ni][1]),
                          "+f"(acc[mi][ni][2]), "+f"(acc[mi][ni][3])
                        : "r"(a[mi][0]), "r"(a[mi][1]), "r"(a[mi][2]), "r"(a[mi][3]),
                          "r"(b[ni][0]), "r"(b[ni][1]));
                }
        }
    }

    // ---- epilogue ----
    const int g = lane >> 2, tig = lane & 3;
    #pragma unroll
    for (int mi = 0; mi < 4; mi++) {
        #pragma unroll
        for (int ni = 0; ni < 4; ni++) {
            int r0 = bm + wm*64 + mi*16 + g;
            int cc = bn + wn*32 + ni*8 + tig*2;
            #pragma unroll
            for (int half = 0; half < 2; half++) {
                int r = r0 + half*8;
                float v0 = acc[mi][ni][half*2 + 0];
                float v1 = acc[mi][ni][half*2 + 1];
                if (epi == 0) {
                    float2 st; st.x = v0; st.y = v1;
                    *(float2*)&C[(size_t)r*cs + cc] = st;
                } else if (epi == 1) {
                    float2 bi  = *(const float2*)&bias[cc];
                    float2 res = *(const float2*)&C[(size_t)r*cs + cc];
                    float2 st; st.x = v0 + bi.x + res.x; st.y = v1 + bi.y + res.y;
                    *(float2*)&C[(size_t)r*cs + cc] = st;
                } else if (epi == 2) {
                    float2 bi = *(const float2*)&bias[cc];
                    float g0 = gelu_exact(v0 + bi.x);
                    float g1 = gelu_exact(v1 + bi.y);
                    *(__half2*)&Oh[(size_t)r*cs + cc] = __floats2half2_rn(g0, g1);
                } else {
                    *(__half2*)&Oh[(size_t)r*cs + cc] = __floats2half2_rn(v0, v1);
                }
            }
        }
    }
}

// ================= Host driver =================
extern "C" void kernel_launch(void* const* d_in, const int* in_sizes, int n_in,
                              void* d_out, int out_size) {
    const float* local_t  = (const float*)d_in[0];
    const float* region_t = (const float*)d_in[1];
    const float* emb      = (const float*)d_in[2];
    const float* attn_g   = (const float*)d_in[3];
    const float* attn_b   = (const float*)d_in[4];
    const float* wqkv     = (const float*)d_in[5];
    const float* wout     = (const float*)d_in[6];
    const float* bout     = (const float*)d_in[7];
    const float* mlp_g    = (const float*)d_in[8];
    const float* mlp_b    = (const float*)d_in[9];
    const float* w1       = (const float*)d_in[10];
    const float* b1       = (const float*)d_in[11];
    const float* w2       = (const float*)d_in[12];
    const float* b2       = (const float*)d_in[13];
    float* out = (float*)d_out;

    cudaFuncSetAttribute(gemm_mma, cudaFuncAttributeMaxDynamicSharedMemorySize, SMEM_GEMM);

    float *xw, *biasT;
    __half *h, *o, *m1, *hr, *orr, *qkv, *qkvr, *Wqkv, *Wout, *W1h, *W2h;
    cudaGetSymbolAddress((void**)&xw,   g_xw);
    cudaGetSymbolAddress((void**)&h,    g_h);
    cudaGetSymbolAddress((void**)&qkv,  g_qkv);
    cudaGetSymbolAddress((void**)&o,    g_o);
    cudaGetSymbolAddress((void**)&m1,   g_m1);
    cudaGetSymbolAddress((void**)&biasT,g_bias);
    cudaGetSymbolAddress((void**)&hr,   g_hr);
    cudaGetSymbolAddress((void**)&qkvr, g_qkvr);
    cudaGetSymbolAddress((void**)&orr,  g_or);
    cudaGetSymbolAddress((void**)&Wqkv, g_Wqkv);
    cudaGetSymbolAddress((void**)&Wout, g_Wout);
    cudaGetSymbolAddress((void**)&W1h,  g_W1h);
    cudaGetSymbolAddress((void**)&W2h,  g_W2h);

    pack_kernel<<<(NROWS*DIMV + 255)/256, 256>>>(local_t, region_t);
    wconv_all<<<(WTOT + BIAS_N + 255)/256, 256>>>(wqkv, wout, w1, w2, emb);

    for (int l = 0; l < DEPTH; l++) {
        __half* WqT = Wqkv + (size_t)l*SEG_QKV;
        __half* WoT = Wout + (size_t)l*SEG_OUT;
        __half* W1T = W1h + (size_t)l*SEG_W1;
        __half* W2T = W2h + (size_t)l*SEG_W2;
        const float* Bout = bout + (size_t)l*DIMV;
        const float* B1   = b1   + (size_t)l*4*DIMV;
        const float* B2   = b2   + (size_t)l*DIMV;
        const float* Ag   = attn_g + (size_t)l*DIMV;
        const float* Ab   = attn_b + (size_t)l*DIMV;
        const float* Mg   = mlp_g  + (size_t)l*DIMV;
        const float* Mb   = mlp_b  + (size_t)l*DIMV;

        // ---- region self-attention ----
        ln_half<<<NWIN, 128>>>(xw, NTOK*DIMV, Ag, Ab, hr);
        gemm_mma<<<dim3(3*DIMV/BN, NWIN/BM), 256, SMEM_GEMM>>>(
            hr, WqT, nullptr, nullptr, qkvr, 3*DIMV, DIMV, 3, 3*DIMV);
        attn_kernel<64><<<dim3(NB, HEADS), 256>>>(qkvr, nullptr, orr);
        gemm_mma<<<dim3(DIMV/BN, NWIN/BM), 256, SMEM_GEMM>>>(
            orr, WoT, Bout, xw, nullptr, DIMV, DIMV, 1, NTOK*DIMV);

        // ---- window attention ----
        ln_half<<<NROWS, 128>>>(xw, DIMV, Ag, Ab, h);
        gemm_mma<<<dim3(3*DIMV/BN, NROWS/BM), 256, SMEM_GEMM>>>(
            h, WqT, nullptr, nullptr, qkv, 3*DIMV, DIMV, 3, 3*DIMV);
        attn_kernel<NTOK><<<dim3(NWIN, HEADS), 256>>>(qkv, biasT, o);
        gemm_mma<<<dim3(DIMV/BN, NROWS/BM), 256, SMEM_GEMM>>>(
            o, WoT, Bout, xw, nullptr, DIMV, DIMV, 1, DIMV);

        // ---- MLP ----
        ln_half<<<NROWS, 128>>>(xw, DIMV, Mg, Mb, h);
        gemm_mma<<<dim3(4*DIMV/BN, NROWS/BM), 256, SMEM_GEMM>>>(
            h, W1T, B1, nullptr, m1, 4*DIMV, DIMV, 2, 4*DIMV);
        gemm_mma<<<dim3(DIMV/BN, NROWS/BM), 256, SMEM_GEMM>>>(
            m1, W2T, B2, xw, nullptr, DIMV, 4*DIMV, 1, DIMV);
    }

    unpack_kernel<<<(NROWS*DIMV + 255)/256, 256>>>(out);
}

// round 10
// speedup vs baseline: 2.7330x; 1.0578x over previous
#include <cuda_runtime.h>
#include <cuda_fp16.h>
#include <math.h>
#include <stdint.h>

// ---------------- Problem constants ----------------
#define DIMV    512
#define HEADS   16
#define DHEAD   32
#define NWIN    512          // B * RH * RW
#define NTOK    65           // 1 region + 64 local
#define NROWS   (NWIN*NTOK)  // 33280 (= 260 * 128)
#define NB      8
#define DEPTH   4
#define QSCALE  0.17677669529663687f
#define LOCAL_ELEMS (8*64*64*512)

// ---------------- helpers ----------------
__device__ __forceinline__ uint32_t smem_to_u32(const void* p) {
    uint32_t a;
    asm("{ .reg .u64 t; cvta.to.shared.u64 t, %1; cvt.u32.u64 %0, t; }" : "=r"(a) : "l"(p));
    return a;
}
__device__ __forceinline__ void cp16(uint32_t dst, const void* src) {
    asm volatile("cp.async.cg.shared.global [%0], [%1], 16;\n" :: "r"(dst), "l"(src));
}
__device__ __forceinline__ void cp_commit() { asm volatile("cp.async.commit_group;\n" ::: "memory"); }
__device__ __forceinline__ float gelu_exact(float x) {
    return 0.5f * x * (1.0f + erff(x * 0.70710678118654752f));
}

// ================= Scratch (device globals) =================
__device__ __align__(16) float  g_xw  [NROWS*DIMV];     // residual stream (windowed, fp32)
__device__ __align__(16) __half g_h   [NROWS*DIMV];     // LN out, fp16
__device__ __align__(16) __half g_qkv [NROWS*3*DIMV];   // qkv, fp16
__device__ __align__(16) __half g_o   [NROWS*DIMV];     // attn out, fp16
__device__ __align__(16) __half g_m1  [NROWS*4*DIMV];   // MLP hidden, fp16
__device__ __align__(16) float  g_bias[HEADS*NTOK*NTOK];
__device__ __align__(16) __half g_hr  [NWIN*DIMV];
__device__ __align__(16) __half g_qkvr[NWIN*3*DIMV];
__device__ __align__(16) __half g_or  [NWIN*DIMV];
// Weights transposed fp16 [N][K]
__device__ __align__(16) __half g_Wqkv[DEPTH*3*DIMV*DIMV];
__device__ __align__(16) __half g_Wout[DEPTH*DIMV*DIMV];
__device__ __align__(16) __half g_W1h [DEPTH*4*DIMV*DIMV];
__device__ __align__(16) __half g_W2h [DEPTH*DIMV*4*DIMV];

// ================= pack / unpack =================
__global__ void pack_kernel(const float* __restrict__ local_t, const float* __restrict__ region_t) {
    int idx = blockIdx.x * blockDim.x + threadIdx.x;
    if (idx >= NROWS*DIMV) return;
    int d = idx & 511, row = idx >> 9;
    int win = row / NTOK, t = row - win*NTOK;
    float v;
    if (t == 0) v = region_t[win*DIMV + d];
    else {
        int a = t - 1, p1 = a >> 3, p2 = a & 7;
        int b = win >> 6, rh = (win >> 3) & 7, rw = win & 7;
        v = local_t[(((b*64) + (rh*8 + p1))*64 + (rw*8 + p2))*DIMV + d];
    }
    g_xw[idx] = v;
}

__global__ void unpack_kernel(float* __restrict__ out) {
    int idx = blockIdx.x * blockDim.x + threadIdx.x;
    if (idx >= NROWS*DIMV) return;
    if (idx < LOCAL_ELEMS) {
        int d = idx & 511, p = idx >> 9;
        int col = p & 63, rowi = (p >> 6) & 63, b = p >> 12;
        int rh = rowi >> 3, p1 = rowi & 7, rw = col >> 3, p2 = col & 7;
        int win = b*64 + rh*8 + rw, t = 1 + p1*8 + p2;
        out[idx] = g_xw[(win*NTOK + t)*DIMV + d];
    } else {
        int r = idx - LOCAL_ELEMS, w = r >> 9, d = r & 511;
        out[idx] = g_xw[(w*NTOK)*DIMV + d];
    }
}

// ---- fused weight conversion (all layers, all fp16) + rel-pos bias, ONE launch ----
#define SEG_QKV (3*DIMV*DIMV)
#define SEG_OUT (DIMV*DIMV)
#define SEG_W1  (DIMV*4*DIMV)
#define SEG_W2  (4*DIMV*DIMV)
#define SEG_TOT (SEG_QKV+SEG_OUT+SEG_W1+SEG_W2)
#define WTOT    (DEPTH*SEG_TOT)
#define BIAS_N  (HEADS*NTOK*NTOK)

__global__ void wconv_all(const float* __restrict__ wqkv, const float* __restrict__ wout,
                          const float* __restrict__ w1, const float* __restrict__ w2,
                          const float* __restrict__ emb) {
    int idx = blockIdx.x * blockDim.x + threadIdx.x;
    if (idx < WTOT) {
        int l = idx / SEG_TOT;
        int r = idx - l*SEG_TOT;
        const float* W; __half* O; int K, N;
        if (r < SEG_QKV) {
            W = wqkv + (size_t)l*SEG_QKV; O = g_Wqkv + (size_t)l*SEG_QKV; K = DIMV; N = 3*DIMV;
        } else if (r < SEG_QKV + SEG_OUT) {
            r -= SEG_QKV;
            W = wout + (size_t)l*SEG_OUT; O = g_Wout + (size_t)l*SEG_OUT; K = DIMV; N = DIMV;
        } else if (r < SEG_QKV + SEG_OUT + SEG_W1) {
            r -= SEG_QKV + SEG_OUT;
            W = w1 + (size_t)l*SEG_W1; O = g_W1h + (size_t)l*SEG_W1; K = DIMV; N = 4*DIMV;
        } else {
            r -= SEG_QKV + SEG_OUT + SEG_W1;
            W = w2 + (size_t)l*SEG_W2; O = g_W2h + (size_t)l*SEG_W2; K = 4*DIMV; N = DIMV;
        }
        int n = r / K, k = r - n*K;
        O[(size_t)n*K + k] = __float2half_rn(W[(size_t)k*N + n]);
    } else {
        int r = idx - WTOT;
        if (r >= BIAS_N) return;
        int h = r / (NTOK*NTOK);
        int q = r - h*NTOK*NTOK;
        int i = q / NTOK, j = q - i*NTOK;
        float v = 0.f;
        if (i > 0 && j > 0) {
            int a = i - 1, b = j - 1;
            int r0 = (a >> 3) - (b >> 3) + 7;
            int r1 = (a & 7) - (b & 7) + 7;
            v = emb[(r0 + r1*15)*HEADS + h];
        }
        g_bias[r] = v;
    }
}

// ================= LayerNorm -> fp16 (strided input) =================
__global__ void ln_half(const float* __restrict__ x, int instr, const float* __restrict__ g,
                        const float* __restrict__ b, __half* __restrict__ y) {
    int row = blockIdx.x;
    int t = threadIdx.x;
    const float4* xv = (const float4*)(x + (size_t)row*instr);
    float4 v = xv[t];
    float s  = v.x + v.y + v.z + v.w;
    float s2 = v.x*v.x + v.y*v.y + v.z*v.z + v.w*v.w;
    #pragma unroll
    for (int off = 16; off; off >>= 1) {
        s  += __shfl_xor_sync(0xffffffffu, s,  off);
        s2 += __shfl_xor_sync(0xffffffffu, s2, off);
    }
    __shared__ float sh[8];
    int wid = t >> 5, lane = t & 31;
    if (lane == 0) { sh[wid] = s; sh[4 + wid] = s2; }
    __syncthreads();
    float st  = sh[0] + sh[1] + sh[2] + sh[3];
    float s2t = sh[4] + sh[5] + sh[6] + sh[7];
    float mean = st * (1.f/512.f);
    float var  = s2t * (1.f/512.f) - mean*mean;
    float rstd = rsqrtf(var + 1e-3f);
    float4 gg = ((const float4*)g)[t];
    float4 bb = ((const float4*)b)[t];
    __half2 o01 = __floats2half2_rn((v.x - mean)*rstd*gg.x + bb.x, (v.y - mean)*rstd*gg.y + bb.y);
    __half2 o23 = __floats2half2_rn((v.z - mean)*rstd*gg.z + bb.z, (v.w - mean)*rstd*gg.w + bb.w);
    __half2* p = (__half2*)(y + (size_t)row*DIMV + 4*t);
    p[0] = o01; p[1] = o23;
}

// ================= Attention v2 (fp16 in, transposed K, conflict-free float4) =================
#define KSW 68   // ks_t row width in floats (17 float4s)
template<int NT>
__global__ __launch_bounds__(256) void attn_kernel(const __half* __restrict__ qkv,
                                                   const float* __restrict__ biasTab,
                                                   __half* __restrict__ o) {
    __shared__ __align__(16) float qs[NT][33];
    __shared__ __align__(16) float ks_t[32][KSW];   // K transposed: [d][token]
    __shared__ __align__(16) float vs[NT][36];      // 9 float4 per row
    __shared__ __align__(16) float ss[NT][NT + 1];
    const int grp = blockIdx.x;
    const int h   = blockIdx.y;
    const int base = grp * NT;
    const int tid = threadIdx.x;
    constexpr int JB = (NT + 3) / 4;     // 17 for 65, 16 for 64

    for (int p = tid; p < NT * DHEAD; p += 256) {
        int i = p >> 5, d = p & 31;
        const __half* row = qkv + (size_t)(base + i) * (3*DIMV) + h*DHEAD + d;
        qs[i][d]   = __half2float(row[0]) * QSCALE;
        ks_t[d][i] = __half2float(row[DIMV]);
        vs[i][d]   = __half2float(row[2*DIMV]);
    }
    for (int p = tid; p < 32*(KSW - NT); p += 256) {
        int d = p / (KSW - NT), c = p - d*(KSW - NT);
        ks_t[d][NT + c] = 0.f;
    }
    __syncthreads();

    for (int p = tid; p < NT * JB; p += 256) {
        int i = p / JB, jb = p - i*JB;
        float4 acc; acc.x = 0.f; acc.y = 0.f; acc.z = 0.f; acc.w = 0.f;
        const float*  qrow = qs[i];
        const float4* kt4  = (const float4*)ks_t;   // row stride KSW/4 = 17
        #pragma unroll
        for (int d = 0; d < 32; d++) {
            float qv = qrow[d];
            float4 kv = kt4[d*(KSW/4) + jb];
            acc.x += qv*kv.x; acc.y += qv*kv.y; acc.z += qv*kv.z; acc.w += qv*kv.w;
        }
        int j0 = jb*4;
        float a[4] = {acc.x, acc.y, acc.z, acc.w};
        #pragma unroll
        for (int u = 0; u < 4; u++) {
            int j = j0 + u;
            if (j < NT) {
                float v = a[u];
                if (biasTab) v += biasTab[(h*NT + i)*NT + j];
                ss[i][j] = v;
            }
        }
    }
    __syncthreads();

    int wid = tid >> 5, lane = tid & 31;
    for (int i = wid; i < NT; i += 8) {
        float m = -1e30f;
        for (int j = lane; j < NT; j += 32) m = fmaxf(m, ss[i][j]);
        #pragma unroll
        for (int off = 16; off; off >>= 1) m = fmaxf(m, __shfl_xor_sync(0xffffffffu, m, off));
        float sum = 0.f;
        for (int j = lane; j < NT; j += 32) { float e = __expf(ss[i][j] - m); ss[i][j] = e; sum += e; }
        #pragma unroll
        for (int off = 16; off; off >>= 1) sum += __shfl_xor_sync(0xffffffffu, sum, off);
        float inv = 1.f / sum;
        for (int j = lane; j < NT; j += 32) ss[i][j] *= inv;
    }
    __syncthreads();

    for (int p = tid; p < NT * 8; p += 256) {
        int i = p >> 3, d4 = p & 7;
        float4 acc; acc.x = 0.f; acc.y = 0.f; acc.z = 0.f; acc.w = 0.f;
        const float*  srow = ss[i];
        const float4* v4   = (const float4*)vs;     // row stride 9
        #pragma unroll 5
        for (int j = 0; j < NT; j++) {
            float a = srow[j];
            float4 v = v4[j*9 + d4];
            acc.x += a*v.x; acc.y += a*v.y; acc.z += a*v.z; acc.w += a*v.w;
        }
        size_t ob = (size_t)(base + i) * DIMV + h*DHEAD + d4*4;
        *(__half2*)&o[ob]     = __floats2half2_rn(acc.x, acc.y);
        *(__half2*)&o[ob + 2] = __floats2half2_rn(acc.z, acc.w);
    }
}

// ================= fp16 GEMM via mma.sync (BK=64, 3-stage) =================
// epi 0: C = AB (fp32, stride cs)
// epi 1: C = AB + bias + C (fp32 residual in place, stride cs)
// epi 2: Oh = gelu(AB + bias) (fp16, stride cs)
// epi 3: Oh = AB (fp16, stride cs)
#define BM 128
#define BN 128
#define BK 64
#define NSTG 3
#define ROWB 144                          // 128B data + 16B pad (banks 4r mod 32: conflict-free)
#define STG_BYTES ((BM + BN) * ROWB)      // 36864
#define SMEM_GEMM (NSTG * STG_BYTES)      // 110592

__global__ __launch_bounds__(256, 2) void gemm_mma(
    const __half* __restrict__ A, const __half* __restrict__ B,
    const float* __restrict__ bias, float* __restrict__ C,
    __half* __restrict__ Oh, int N, int K, int epi, int cs)
{
    extern __shared__ char smem[];
    const uint32_t sb = smem_to_u32(smem);
    const int tid = threadIdx.x;
    const int bm = blockIdx.y * BM;
    const int bn = blockIdx.x * BN;
    const int total = K / BK;             // >= 8 for K >= 512

    const int wid = tid >> 5, lane = tid & 31;
    const int wm = wid & 1, wn = wid >> 1;

    float acc[4][4][4];
    #pragma unroll
    for (int mi = 0; mi < 4; mi++)
        #pragma unroll
        for (int ni = 0; ni < 4; ni++)
            #pragma unroll
            for (int r = 0; r < 4; r++) acc[mi][ni][r] = 0.f;

    auto load_chunk = [&](int c) {
        int col = c*BK;
        uint32_t stA = sb + (c % NSTG) * STG_BYTES;
        uint32_t stB = stA + BM * ROWB;
        #pragma unroll
        for (int i = 0; i < 4; i++) {     // 1024 segments each for A and B: 128 rows x 8 x 16B
            int s = tid + i*256;
            int row = s >> 3, seg = s & 7;
            cp16(stA + row*ROWB + seg*16, A + (size_t)(bm + row)*K + col + seg*8);
            cp16(stB + row*ROWB + seg*16, B + (size_t)(bn + row)*K + col + seg*8);
        }
        cp_commit();
    };

    load_chunk(0);
    load_chunk(1);

    for (int c = 0; c < total; c++) {
        if (c == total - 1) asm volatile("cp.async.wait_group 0;\n" ::: "memory");
        else                asm volatile("cp.async.wait_group 1;\n" ::: "memory");
        __syncthreads();
        if (c + 2 < total) load_chunk(c + 2);

        uint32_t stA = sb + (c % NSTG) * STG_BYTES;
        uint32_t stB = stA + BM * ROWB;
        #pragma unroll
        for (int ks = 0; ks < 4; ks++) {
            uint32_t a[4][4];
            #pragma unroll
            for (int mi = 0; mi < 4; mi++) {
                uint32_t addr = stA + (wm*64 + mi*16 + (lane & 15))*ROWB + ((lane >> 4)*16 + ks*32);
                asm volatile("ldmatrix.sync.aligned.m8n8.x4.shared.b16 {%0,%1,%2,%3}, [%4];"
                    : "=r"(a[mi][0]), "=r"(a[mi][1]), "=r"(a[mi][2]), "=r"(a[mi][3]) : "r"(addr));
            }
            uint32_t b[4][2];
            #pragma unroll
            for (int ni = 0; ni < 4; ni++) {
                uint32_t addr = stB + (wn*32 + ni*8 + (lane & 7))*ROWB + (((lane >> 3) & 1)*16 + ks*32);
                asm volatile("ldmatrix.sync.aligned.m8n8.x2.shared.b16 {%0,%1}, [%2];"
                    : "=r"(b[ni][0]), "=r"(b[ni][1]) : "r"(addr));
            }
            #pragma unroll
            for (int mi = 0; mi < 4; mi++)
                #pragma unroll
                for (int ni = 0; ni < 4; ni++) {
                    asm volatile(
                        "mma.sync.aligned.m16n8k16.row.col.f32.f16.f16.f32 "
                        "{%0,%1,%2,%3}, {%4,%5,%6,%7}, {%8,%9}, {%0,%1,%2,%3};"
                        : "+f"(acc[mi][ni][0]), "+f"(acc[mi][ni][1]),
                          "+f"(acc[mi][ni][2]), "+f"(acc[mi][ni][3])
                        : "r"(a[mi][0]), "r"(a[mi][1]), "r"(a[mi][2]), "r"(a[mi][3]),
                          "r"(b[ni][0]), "r"(b[ni][1]));
                }
        }
    }

    // ---- epilogue ----
    const int g = lane >> 2, tig = lane & 3;
    #pragma unroll
    for (int mi = 0; mi < 4; mi++) {
        #pragma unroll
        for (int ni = 0; ni < 4; ni++) {
            int r0 = bm + wm*64 + mi*16 + g;
            int cc = bn + wn*32 + ni*8 + tig*2;
            #pragma unroll
            for (int half = 0; half < 2; half++) {
                int r = r0 + half*8;
                float v0 = acc[mi][ni][half*2 + 0];
                float v1 = acc[mi][ni][half*2 + 1];
                if (epi == 0) {
                    float2 st; st.x = v0; st.y = v1;
                    *(float2*)&C[(size_t)r*cs + cc] = st;
                } else if (epi == 1) {
                    float2 bi  = *(const float2*)&bias[cc];
                    float2 res = *(const float2*)&C[(size_t)r*cs + cc];
                    float2 st; st.x = v0 + bi.x + res.x; st.y = v1 + bi.y + res.y;
                    *(float2*)&C[(size_t)r*cs + cc] = st;
                } else if (epi == 2) {
                    float2 bi = *(const float2*)&bias[cc];
                    float g0 = gelu_exact(v0 + bi.x);
                    float g1 = gelu_exact(v1 + bi.y);
                    *(__half2*)&Oh[(size_t)r*cs + cc] = __floats2half2_rn(g0, g1);
                } else {
                    *(__half2*)&Oh[(size_t)r*cs + cc] = __floats2half2_rn(v0, v1);
                }
            }
        }
    }
}

// ================= Host driver =================
extern "C" void kernel_launch(void* const* d_in, const int* in_sizes, int n_in,
                              void* d_out, int out_size) {
    const float* local_t  = (const float*)d_in[0];
    const float* region_t = (const float*)d_in[1];
    const float* emb      = (const float*)d_in[2];
    const float* attn_g   = (const float*)d_in[3];
    const float* attn_b   = (const float*)d_in[4];
    const float* wqkv     = (const float*)d_in[5];
    const float* wout     = (const float*)d_in[6];
    const float* bout     = (const float*)d_in[7];
    const float* mlp_g    = (const float*)d_in[8];
    const float* mlp_b    = (const float*)d_in[9];
    const float* w1       = (const float*)d_in[10];
    const float* b1       = (const float*)d_in[11];
    const float* w2       = (const float*)d_in[12];
    const float* b2       = (const float*)d_in[13];
    float* out = (float*)d_out;

    cudaFuncSetAttribute(gemm_mma, cudaFuncAttributeMaxDynamicSharedMemorySize, SMEM_GEMM);

    float *xw, *biasT;
    __half *h, *o, *m1, *hr, *orr, *qkv, *qkvr, *Wqkv, *Wout, *W1h, *W2h;
    cudaGetSymbolAddress((void**)&xw,   g_xw);
    cudaGetSymbolAddress((void**)&h,    g_h);
    cudaGetSymbolAddress((void**)&qkv,  g_qkv);
    cudaGetSymbolAddress((void**)&o,    g_o);
    cudaGetSymbolAddress((void**)&m1,   g_m1);
    cudaGetSymbolAddress((void**)&biasT,g_bias);
    cudaGetSymbolAddress((void**)&hr,   g_hr);
    cudaGetSymbolAddress((void**)&qkvr, g_qkvr);
    cudaGetSymbolAddress((void**)&orr,  g_or);
    cudaGetSymbolAddress((void**)&Wqkv, g_Wqkv);
    cudaGetSymbolAddress((void**)&Wout, g_Wout);
    cudaGetSymbolAddress((void**)&W1h,  g_W1h);
    cudaGetSymbolAddress((void**)&W2h,  g_W2h);

    pack_kernel<<<(NROWS*DIMV + 255)/256, 256>>>(local_t, region_t);
    wconv_all<<<(WTOT + BIAS_N + 255)/256, 256>>>(wqkv, wout, w1, w2, emb);

    for (int l = 0; l < DEPTH; l++) {
        __half* WqT = Wqkv + (size_t)l*SEG_QKV;
        __half* WoT = Wout + (size_t)l*SEG_OUT;
        __half* W1T = W1h + (size_t)l*SEG_W1;
        __half* W2T = W2h + (size_t)l*SEG_W2;
        const float* Bout = bout + (size_t)l*DIMV;
        const float* B1   = b1   + (size_t)l*4*DIMV;
        const float* B2   = b2   + (size_t)l*DIMV;
        const float* Ag   = attn_g + (size_t)l*DIMV;
        const float* Ab   = attn_b + (size_t)l*DIMV;
        const float* Mg   = mlp_g  + (size_t)l*DIMV;
        const float* Mb   = mlp_b  + (size_t)l*DIMV;

        // ---- region self-attention ----
        ln_half<<<NWIN, 128>>>(xw, NTOK*DIMV, Ag, Ab, hr);
        gemm_mma<<<dim3(3*DIMV/BN, NWIN/BM), 256, SMEM_GEMM>>>(
            hr, WqT, nullptr, nullptr, qkvr, 3*DIMV, DIMV, 3, 3*DIMV);
        attn_kernel<64><<<dim3(NB, HEADS), 256>>>(qkvr, nullptr, orr);
        gemm_mma<<<dim3(DIMV/BN, NWIN/BM), 256, SMEM_GEMM>>>(
            orr, WoT, Bout, xw, nullptr, DIMV, DIMV, 1, NTOK*DIMV);

        // ---- window attention ----
        ln_half<<<NROWS, 128>>>(xw, DIMV, Ag, Ab, h);
        gemm_mma<<<dim3(3*DIMV/BN, NROWS/BM), 256, SMEM_GEMM>>>(
            h, WqT, nullptr, nullptr, qkv, 3*DIMV, DIMV, 3, 3*DIMV);
        attn_kernel<NTOK><<<dim3(NWIN, HEADS), 256>>>(qkv, biasT, o);
        gemm_mma<<<dim3(DIMV/BN, NROWS/BM), 256, SMEM_GEMM>>>(
            o, WoT, Bout, xw, nullptr, DIMV, DIMV, 1, DIMV);

        // ---- MLP ----
        ln_half<<<NROWS, 128>>>(xw, DIMV, Mg, Mb, h);
        gemm_mma<<<dim3(4*DIMV/BN, NROWS/BM), 256, SMEM_GEMM>>>(
            h, W1T, B1, nullptr, m1, 4*DIMV, DIMV, 2, 4*DIMV);
        gemm_mma<<<dim3(DIMV/BN, NROWS/BM), 256, SMEM_GEMM>>>(
            m1, W2T, B2, xw, nullptr, DIMV, 4*DIMV, 1, DIMV);
    }

    unpack_kernel<<<(NROWS*DIMV + 255)/256, 256>>>(out);
}

// round 11
// speedup vs baseline: 3.4614x; 1.2665x over previous
#include <cuda_runtime.h>
#include <cuda_fp16.h>
#include <math.h>
#include <stdint.h>

// ---------------- Problem constants ----------------
#define DIMV    512
#define HEADS   16
#define DHEAD   32
#define NWIN    512          // B * RH * RW
#define NTOK    65           // 1 region + 64 local
#define NROWS   (NWIN*NTOK)  // 33280 (= 260 * 128)
#define NB      8
#define DEPTH   4
#define QSCALE  0.17677669529663687f
#define LOCAL_ELEMS (8*64*64*512)

// ---------------- helpers ----------------
__device__ __forceinline__ uint32_t smem_to_u32(const void* p) {
    uint32_t a;
    asm("{ .reg .u64 t; cvta.to.shared.u64 t, %1; cvt.u32.u64 %0, t; }" : "=r"(a) : "l"(p));
    return a;
}
__device__ __forceinline__ void cp16(uint32_t dst, const void* src) {
    asm volatile("cp.async.cg.shared.global [%0], [%1], 16;\n" :: "r"(dst), "l"(src));
}
__device__ __forceinline__ void cp_commit() { asm volatile("cp.async.commit_group;\n" ::: "memory"); }
__device__ __forceinline__ float gelu_exact(float x) {
    return 0.5f * x * (1.0f + erff(x * 0.70710678118654752f));
}
__device__ __forceinline__ uint32_t h2_u32(__half2 v) {
    return *(uint32_t*)&v;
}

// ================= Scratch (device globals) =================
__device__ __align__(16) float  g_xw  [NROWS*DIMV];     // residual stream (windowed, fp32)
__device__ __align__(16) __half g_h   [NROWS*DIMV];     // LN out, fp16
__device__ __align__(16) __half g_qkv [NROWS*3*DIMV];   // qkv, fp16
__device__ __align__(16) __half g_o   [NROWS*DIMV];     // attn out, fp16
__device__ __align__(16) __half g_m1  [NROWS*4*DIMV];   // MLP hidden, fp16
__device__ __align__(16) float  g_bias[HEADS*NTOK*NTOK];
__device__ __align__(16) __half g_hr  [NWIN*DIMV];
__device__ __align__(16) __half g_qkvr[NWIN*3*DIMV];
__device__ __align__(16) __half g_or  [NWIN*DIMV];
// Weights transposed fp16 [N][K]
__device__ __align__(16) __half g_Wqkv[DEPTH*3*DIMV*DIMV];
__device__ __align__(16) __half g_Wout[DEPTH*DIMV*DIMV];
__device__ __align__(16) __half g_W1h [DEPTH*4*DIMV*DIMV];
__device__ __align__(16) __half g_W2h [DEPTH*DIMV*4*DIMV];

// ================= pack / unpack =================
__global__ void pack_kernel(const float* __restrict__ local_t, const float* __restrict__ region_t) {
    int idx = blockIdx.x * blockDim.x + threadIdx.x;
    if (idx >= NROWS*DIMV) return;
    int d = idx & 511, row = idx >> 9;
    int win = row / NTOK, t = row - win*NTOK;
    float v;
    if (t == 0) v = region_t[win*DIMV + d];
    else {
        int a = t - 1, p1 = a >> 3, p2 = a & 7;
        int b = win >> 6, rh = (win >> 3) & 7, rw = win & 7;
        v = local_t[(((b*64) + (rh*8 + p1))*64 + (rw*8 + p2))*DIMV + d];
    }
    g_xw[idx] = v;
}

__global__ void unpack_kernel(float* __restrict__ out) {
    int idx = blockIdx.x * blockDim.x + threadIdx.x;
    if (idx >= NROWS*DIMV) return;
    if (idx < LOCAL_ELEMS) {
        int d = idx & 511, p = idx >> 9;
        int col = p & 63, rowi = (p >> 6) & 63, b = p >> 12;
        int rh = rowi >> 3, p1 = rowi & 7, rw = col >> 3, p2 = col & 7;
        int win = b*64 + rh*8 + rw, t = 1 + p1*8 + p2;
        out[idx] = g_xw[(win*NTOK + t)*DIMV + d];
    } else {
        int r = idx - LOCAL_ELEMS, w = r >> 9, d = r & 511;
        out[idx] = g_xw[(w*NTOK)*DIMV + d];
    }
}

// ---- fused weight conversion (all layers, all fp16) + rel-pos bias, ONE launch ----
#define SEG_QKV (3*DIMV*DIMV)
#define SEG_OUT (DIMV*DIMV)
#define SEG_W1  (DIMV*4*DIMV)
#define SEG_W2  (4*DIMV*DIMV)
#define SEG_TOT (SEG_QKV+SEG_OUT+SEG_W1+SEG_W2)
#define WTOT    (DEPTH*SEG_TOT)
#define BIAS_N  (HEADS*NTOK*NTOK)

__global__ void wconv_all(const float* __restrict__ wqkv, const float* __restrict__ wout,
                          const float* __restrict__ w1, const float* __restrict__ w2,
                          const float* __restrict__ emb) {
    int idx = blockIdx.x * blockDim.x + threadIdx.x;
    if (idx < WTOT) {
        int l = idx / SEG_TOT;
        int r = idx - l*SEG_TOT;
        const float* W; __half* O; int K, N;
        if (r < SEG_QKV) {
            W = wqkv + (size_t)l*SEG_QKV; O = g_Wqkv + (size_t)l*SEG_QKV; K = DIMV; N = 3*DIMV;
        } else if (r < SEG_QKV + SEG_OUT) {
            r -= SEG_QKV;
            W = wout + (size_t)l*SEG_OUT; O = g_Wout + (size_t)l*SEG_OUT; K = DIMV; N = DIMV;
        } else if (r < SEG_QKV + SEG_OUT + SEG_W1) {
            r -= SEG_QKV + SEG_OUT;
            W = w1 + (size_t)l*SEG_W1; O = g_W1h + (size_t)l*SEG_W1; K = DIMV; N = 4*DIMV;
        } else {
            r -= SEG_QKV + SEG_OUT + SEG_W1;
            W = w2 + (size_t)l*SEG_W2; O = g_W2h + (size_t)l*SEG_W2; K = 4*DIMV; N = DIMV;
        }
        int n = r / K, k = r - n*K;
        O[(size_t)n*K + k] = __float2half_rn(W[(size_t)k*N + n]);
    } else {
        int r = idx - WTOT;
        if (r >= BIAS_N) return;
        int h = r / (NTOK*NTOK);
        int q = r - h*NTOK*NTOK;
        int i = q / NTOK, j = q - i*NTOK;
        float v = 0.f;
        if (i > 0 && j > 0) {
            int a = i - 1, b = j - 1;
            int r0 = (a >> 3) - (b >> 3) + 7;
            int r1 = (a & 7) - (b & 7) + 7;
            v = emb[(r0 + r1*15)*HEADS + h];
        }
        g_bias[r] = v;
    }
}

// ================= LayerNorm -> fp16 (strided input) =================
__global__ void ln_half(const float* __restrict__ x, int instr, const float* __restrict__ g,
                        const float* __restrict__ b, __half* __restrict__ y) {
    int row = blockIdx.x;
    int t = threadIdx.x;
    const float4* xv = (const float4*)(x + (size_t)row*instr);
    float4 v = xv[t];
    float s  = v.x + v.y + v.z + v.w;
    float s2 = v.x*v.x + v.y*v.y + v.z*v.z + v.w*v.w;
    #pragma unroll
    for (int off = 16; off; off >>= 1) {
        s  += __shfl_xor_sync(0xffffffffu, s,  off);
        s2 += __shfl_xor_sync(0xffffffffu, s2, off);
    }
    __shared__ float sh[8];
    int wid = t >> 5, lane = t & 31;
    if (lane == 0) { sh[wid] = s; sh[4 + wid] = s2; }
    __syncthreads();
    float st  = sh[0] + sh[1] + sh[2] + sh[3];
    float s2t = sh[4] + sh[5] + sh[6] + sh[7];
    float mean = st * (1.f/512.f);
    float var  = s2t * (1.f/512.f) - mean*mean;
    float rstd = rsqrtf(var + 1e-3f);
    float4 gg = ((const float4*)g)[t];
    float4 bb = ((const float4*)b)[t];
    __half2 o01 = __floats2half2_rn((v.x - mean)*rstd*gg.x + bb.x, (v.y - mean)*rstd*gg.y + bb.y);
    __half2 o23 = __floats2half2_rn((v.z - mean)*rstd*gg.z + bb.z, (v.w - mean)*rstd*gg.w + bb.w);
    __half2* p = (__half2*)(y + (size_t)row*DIMV + 4*t);
    p[0] = o01; p[1] = o23;
}

// ================= Tensor-core attention =================
// One CTA per window. 8 warps; warp w handles heads 2w, 2w+1 sequentially.
// Warp-private smem: q [TOK_PAD][80B], k [TOK_PAD][80B], v^T [32][VROWB].
// S = q@k^T (mma, fp32 accum) + bias, in-register quad-shuffle softmax,
// P fp16 re-packed as A-fragments, O = P@V via mma with ldmatrix on v^T.
template<int NT>
__global__ __launch_bounds__(256) void attn_tc(const __half* __restrict__ qkv,
                                               const float* __restrict__ biasTab,
                                               __half* __restrict__ o) {
    constexpr int TOK_PAD = (NT + 15) & ~15;
    constexpr int ST = TOK_PAD / 8;     // 8-col score tiles
    constexpr int QB = TOK_PAD / 16;    // 16-row query blocks
    constexpr int KS = TOK_PAD / 16;    // 16-token AV k-steps
    constexpr int QROWB = 80, KROWB = 80, VROWB = TOK_PAD*2 + 16;
    constexpr int PW = TOK_PAD*QROWB + TOK_PAD*KROWB + 32*VROWB;
    extern __shared__ __align__(16) char smattn[];
    const int w = threadIdx.x >> 5, lane = threadIdx.x & 31;
    char* spq = smattn + w * PW;
    char* spk = spq + TOK_PAD*QROWB;
    char* spv = spk + TOK_PAD*KROWB;
    const uint32_t uq = smem_to_u32(spq);
    const uint32_t uk = smem_to_u32(spk);
    const uint32_t uv = smem_to_u32(spv);
    const int tokbase = blockIdx.x * NT;
    const int g = lane >> 2, tig = lane & 3;

    for (int hh = 0; hh < 2; hh++) {
        const int h = w*2 + hh;
        // ---- load q (scaled), k, v^T into warp-private smem ----
        for (int p = lane; p < NT*16; p += 32) {
            int tok = p >> 4, d2 = p & 15;
            const __half2* src = (const __half2*)(qkv + (size_t)(tokbase + tok)*(3*DIMV) + h*DHEAD + d2*2);
            __half2 qv = src[0];
            float2 qf = __half22float2(qv);
            *(__half2*)(spq + tok*QROWB + d2*4) = __floats2half2_rn(qf.x*QSCALE, qf.y*QSCALE);
            *(__half2*)(spk + tok*KROWB + d2*4) = src[DIMV/2];
            __half2 vv = src[DIMV];
            *(__half*)(spv + (2*d2)*VROWB   + tok*2) = __low2half(vv);
            *(__half*)(spv + (2*d2+1)*VROWB + tok*2) = __high2half(vv);
        }
        if (TOK_PAD > NT) {
            for (int p = lane; p < 32*(TOK_PAD - NT); p += 32) {
                int d = p / (TOK_PAD - NT), c = p - d*(TOK_PAD - NT);
                *(__half*)(spv + d*VROWB + (NT + c)*2) = __ushort_as_half(0);
            }
        }
        __syncwarp();

        for (int qb = 0; qb < QB; qb++) {
            // q A-fragments for the two 16-wide k-chunks of DHEAD=32
            uint32_t afr[2][4];
            #pragma unroll
            for (int kk = 0; kk < 2; kk++) {
                uint32_t addr = uq + (qb*16 + (lane & 15))*QROWB + (lane >> 4)*16 + kk*32;
                asm volatile("ldmatrix.sync.aligned.m8n8.x4.shared.b16 {%0,%1,%2,%3}, [%4];"
                    : "=r"(afr[kk][0]), "=r"(afr[kk][1]), "=r"(afr[kk][2]), "=r"(afr[kk][3]) : "r"(addr));
            }
            float s[ST][4];
            #pragma unroll
            for (int t = 0; t < ST; t++) { s[t][0]=0.f; s[t][1]=0.f; s[t][2]=0.f; s[t][3]=0.f; }
            #pragma unroll
            for (int t = 0; t < ST; t++) {
                #pragma unroll
                for (int kk = 0; kk < 2; kk++) {
                    uint32_t b[2];
                    uint32_t addr = uk + (t*8 + (lane & 7))*KROWB + ((lane >> 3) & 1)*16 + kk*32;
                    asm volatile("ldmatrix.sync.aligned.m8n8.x2.shared.b16 {%0,%1}, [%2];"
                        : "=r"(b[0]), "=r"(b[1]) : "r"(addr));
                    asm volatile(
                        "mma.sync.aligned.m16n8k16.row.col.f32.f16.f16.f32 "
                        "{%0,%1,%2,%3}, {%4,%5,%6,%7}, {%8,%9}, {%0,%1,%2,%3};"
                        : "+f"(s[t][0]), "+f"(s[t][1]), "+f"(s[t][2]), "+f"(s[t][3])
                        : "r"(afr[kk][0]), "r"(afr[kk][1]), "r"(afr[kk][2]), "r"(afr[kk][3]),
                          "r"(b[0]), "r"(b[1]));
                }
            }
            const int row0 = qb*16 + g;
            // bias + column mask
            #pragma unroll
            for (int t = 0; t < ST; t++) {
                int c0 = t*8 + tig*2;
                if (biasTab) {
                    if (row0 < NT) {
                        if (c0 < NT)     s[t][0] += biasTab[(h*NT + row0)*NT + c0];
                        if (c0 + 1 < NT) s[t][1] += biasTab[(h*NT + row0)*NT + c0 + 1];
                    }
                    if (row0 + 8 < NT) {
                        if (c0 < NT)     s[t][2] += biasTab[(h*NT + row0 + 8)*NT + c0];
                        if (c0 + 1 < NT) s[t][3] += biasTab[(h*NT + row0 + 8)*NT + c0 + 1];
                    }
                }
                if (c0 >= NT)     { s[t][0] = -1e30f; s[t][2] = -1e30f; }
                if (c0 + 1 >= NT) { s[t][1] = -1e30f; s[t][3] = -1e30f; }
            }
            // softmax (rows row0 and row0+8; row data lives in a lane-quad)
            float m0 = -1e30f, m1 = -1e30f;
            #pragma unroll
            for (int t = 0; t < ST; t++) {
                m0 = fmaxf(m0, fmaxf(s[t][0], s[t][1]));
                m1 = fmaxf(m1, fmaxf(s[t][2], s[t][3]));
            }
            m0 = fmaxf(m0, __shfl_xor_sync(0xffffffffu, m0, 1));
            m0 = fmaxf(m0, __shfl_xor_sync(0xffffffffu, m0, 2));
            m1 = fmaxf(m1, __shfl_xor_sync(0xffffffffu, m1, 1));
            m1 = fmaxf(m1, __shfl_xor_sync(0xffffffffu, m1, 2));
            float sum0 = 0.f, sum1 = 0.f;
            #pragma unroll
            for (int t = 0; t < ST; t++) {
                s[t][0] = __expf(s[t][0] - m0); s[t][1] = __expf(s[t][1] - m0);
                s[t][2] = __expf(s[t][2] - m1); s[t][3] = __expf(s[t][3] - m1);
                sum0 += s[t][0] + s[t][1];
                sum1 += s[t][2] + s[t][3];
            }
            sum0 += __shfl_xor_sync(0xffffffffu, sum0, 1);
            sum0 += __shfl_xor_sync(0xffffffffu, sum0, 2);
            sum1 += __shfl_xor_sync(0xffffffffu, sum1, 1);
            sum1 += __shfl_xor_sync(0xffffffffu, sum1, 2);
            float inv0 = 1.f / sum0, inv1 = 1.f / sum1;
            // P fp16 A-fragments (accum-pair -> A-frag identity)
            uint32_t pa[KS][4];
            #pragma unroll
            for (int ph = 0; ph < KS; ph++) {
                int t0 = 2*ph, t1 = 2*ph + 1;
                pa[ph][0] = h2_u32(__floats2half2_rn(s[t0][0]*inv0, s[t0][1]*inv0));
                pa[ph][1] = h2_u32(__floats2half2_rn(s[t0][2]*inv1, s[t0][3]*inv1));
                pa[ph][2] = h2_u32(__floats2half2_rn(s[t1][0]*inv0, s[t1][1]*inv0));
                pa[ph][3] = h2_u32(__floats2half2_rn(s[t1][2]*inv1, s[t1][3]*inv1));
            }
            // O = P @ V
            float oa[4][4];
            #pragma unroll
            for (int nt = 0; nt < 4; nt++) { oa[nt][0]=0.f; oa[nt][1]=0.f; oa[nt][2]=0.f; oa[nt][3]=0.f; }
            #pragma unroll
            for (int ksi = 0; ksi < KS; ksi++) {
                #pragma unroll
                for (int nt = 0; nt < 4; nt++) {
                    uint32_t b[2];
                    uint32_t addr = uv + (nt*8 + (lane & 7))*VROWB + (ksi*16 + ((lane >> 3) & 1)*8)*2;
                    asm volatile("ldmatrix.sync.aligned.m8n8.x2.shared.b16 {%0,%1}, [%2];"
                        : "=r"(b[0]), "=r"(b[1]) : "r"(addr));
                    asm volatile(
                        "mma.sync.aligned.m16n8k16.row.col.f32.f16.f16.f32 "
                        "{%0,%1,%2,%3}, {%4,%5,%6,%7}, {%8,%9}, {%0,%1,%2,%3};"
                        : "+f"(oa[nt][0]), "+f"(oa[nt][1]), "+f"(oa[nt][2]), "+f"(oa[nt][3])
                        : "r"(pa[ksi][0]), "r"(pa[ksi][1]), "r"(pa[ksi][2]), "r"(pa[ksi][3]),
                          "r"(b[0]), "r"(b[1]));
                }
            }
            // store
            if (row0 < NT) {
                #pragma unroll
                for (int nt = 0; nt < 4; nt++)
                    *(__half2*)&o[(size_t)(tokbase + row0)*DIMV + h*DHEAD + nt*8 + tig*2] =
                        __floats2half2_rn(oa[nt][0], oa[nt][1]);
            }
            if (row0 + 8 < NT) {
                #pragma unroll
                for (int nt = 0; nt < 4; nt++)
                    *(__half2*)&o[(size_t)(tokbase + row0 + 8)*DIMV + h*DHEAD + nt*8 + tig*2] =
                        __floats2half2_rn(oa[nt][2], oa[nt][3]);
            }
        }
        __syncwarp();
    }
}

// smem sizes for the two instantiations
#define ATTN_SMEM_65 (8 * ((80*80) + (80*80) + 32*(80*2+16)))   // 147456
#define ATTN_SMEM_64 (8 * ((64*80) + (64*80) + 32*(64*2+16)))   // 118784

// ================= fp16 GEMM via mma.sync (BK=64, 3-stage) =================
#define BM 128
#define BN 128
#define BK 64
#define NSTG 3
#define ROWB 144
#define STG_BYTES ((BM + BN) * ROWB)
#define SMEM_GEMM (NSTG * STG_BYTES)

__global__ __launch_bounds__(256, 2) void gemm_mma(
    const __half* __restrict__ A, const __half* __restrict__ B,
    const float* __restrict__ bias, float* __restrict__ C,
    __half* __restrict__ Oh, int N, int K, int epi, int cs)
{
    extern __shared__ char smem[];
    const uint32_t sb = smem_to_u32(smem);
    const int tid = threadIdx.x;
    const int bm = blockIdx.y * BM;
    const int bn = blockIdx.x * BN;
    const int total = K / BK;

    const int wid = tid >> 5, lane = tid & 31;
    const int wm = wid & 1, wn = wid >> 1;

    float acc[4][4][4];
    #pragma unroll
    for (int mi = 0; mi < 4; mi++)
        #pragma unroll
        for (int ni = 0; ni < 4; ni++)
            #pragma unroll
            for (int r = 0; r < 4; r++) acc[mi][ni][r] = 0.f;

    auto load_chunk = [&](int c) {
        int col = c*BK;
        uint32_t stA = sb + (c % NSTG) * STG_BYTES;
        uint32_t stB = stA + BM * ROWB;
        #pragma unroll
        for (int i = 0; i < 4; i++) {
            int s = tid + i*256;
            int row = s >> 3, seg = s & 7;
            cp16(stA + row*ROWB + seg*16, A + (size_t)(bm + row)*K + col + seg*8);
            cp16(stB + row*ROWB + seg*16, B + (size_t)(bn + row)*K + col + seg*8);
        }
        cp_commit();
    };

    load_chunk(0);
    load_chunk(1);

    for (int c = 0; c < total; c++) {
        if (c == total - 1) asm volatile("cp.async.wait_group 0;\n" ::: "memory");
        else                asm volatile("cp.async.wait_group 1;\n" ::: "memory");
        __syncthreads();
        if (c + 2 < total) load_chunk(c + 2);

        uint32_t stA = sb + (c % NSTG) * STG_BYTES;
        uint32_t stB = stA + BM * ROWB;
        #pragma unroll
        for (int ks = 0; ks < 4; ks++) {
            uint32_t a[4][4];
            #pragma unroll
            for (int mi = 0; mi < 4; mi++) {
                uint32_t addr = stA + (wm*64 + mi*16 + (lane & 15))*ROWB + ((lane >> 4)*16 + ks*32);
                asm volatile("ldmatrix.sync.aligned.m8n8.x4.shared.b16 {%0,%1,%2,%3}, [%4];"
                    : "=r"(a[mi][0]), "=r"(a[mi][1]), "=r"(a[mi][2]), "=r"(a[mi][3]) : "r"(addr));
            }
            uint32_t b[4][2];
            #pragma unroll
            for (int ni = 0; ni < 4; ni++) {
                uint32_t addr = stB + (wn*32 + ni*8 + (lane & 7))*ROWB + (((lane >> 3) & 1)*16 + ks*32);
                asm volatile("ldmatrix.sync.aligned.m8n8.x2.shared.b16 {%0,%1}, [%2];"
                    : "=r"(b[ni][0]), "=r"(b[ni][1]) : "r"(addr));
            }
            #pragma unroll
            for (int mi = 0; mi < 4; mi++)
                #pragma unroll
                for (int ni = 0; ni < 4; ni++) {
                    asm volatile(
                        "mma.sync.aligned.m16n8k16.row.col.f32.f16.f16.f32 "
                        "{%0,%1,%2,%3}, {%4,%5,%6,%7}, {%8,%9}, {%0,%1,%2,%3};"
                        : "+f"(acc[mi][ni][0]), "+f"(acc[mi][ni][1]),
                          "+f"(acc[mi][ni][2]), "+f"(acc[mi][ni][3])
                        : "r"(a[mi][0]), "r"(a[mi][1]), "r"(a[mi][2]), "r"(a[mi][3]),
                          "r"(b[ni][0]), "r"(b[ni][1]));
                }
        }
    }

    // ---- epilogue ----
    const int g = lane >> 2, tig = lane & 3;
    #pragma unroll
    for (int mi = 0; mi < 4; mi++) {
        #pragma unroll
        for (int ni = 0; ni < 4; ni++) {
            int r0 = bm + wm*64 + mi*16 + g;
            int cc = bn + wn*32 + ni*8 + tig*2;
            #pragma unroll
            for (int half = 0; half < 2; half++) {
                int r = r0 + half*8;
                float v0 = acc[mi][ni][half*2 + 0];
                float v1 = acc[mi][ni][half*2 + 1];
                if (epi == 0) {
                    float2 st; st.x = v0; st.y = v1;
                    *(float2*)&C[(size_t)r*cs + cc] = st;
                } else if (epi == 1) {
                    float2 bi  = *(const float2*)&bias[cc];
                    float2 res = *(const float2*)&C[(size_t)r*cs + cc];
                    float2 st; st.x = v0 + bi.x + res.x; st.y = v1 + bi.y + res.y;
                    *(float2*)&C[(size_t)r*cs + cc] = st;
                } else if (epi == 2) {
                    float2 bi = *(const float2*)&bias[cc];
                    float g0 = gelu_exact(v0 + bi.x);
                    float g1 = gelu_exact(v1 + bi.y);
                    *(__half2*)&Oh[(size_t)r*cs + cc] = __floats2half2_rn(g0, g1);
                } else {
                    *(__half2*)&Oh[(size_t)r*cs + cc] = __floats2half2_rn(v0, v1);
                }
            }
        }
    }
}

// ================= Host driver =================
extern "C" void kernel_launch(void* const* d_in, const int* in_sizes, int n_in,
                              void* d_out, int out_size) {
    const float* local_t  = (const float*)d_in[0];
    const float* region_t = (const float*)d_in[1];
    const float* emb      = (const float*)d_in[2];
    const float* attn_g   = (const float*)d_in[3];
    const float* attn_b   = (const float*)d_in[4];
    const float* wqkv     = (const float*)d_in[5];
    const float* wout     = (const float*)d_in[6];
    const float* bout     = (const float*)d_in[7];
    const float* mlp_g    = (const float*)d_in[8];
    const float* mlp_b    = (const float*)d_in[9];
    const float* w1       = (const float*)d_in[10];
    const float* b1       = (const float*)d_in[11];
    const float* w2       = (const float*)d_in[12];
    const float* b2       = (const float*)d_in[13];
    float* out = (float*)d_out;

    cudaFuncSetAttribute(gemm_mma, cudaFuncAttributeMaxDynamicSharedMemorySize, SMEM_GEMM);
    cudaFuncSetAttribute(attn_tc<NTOK>, cudaFuncAttributeMaxDynamicSharedMemorySize, ATTN_SMEM_65);
    cudaFuncSetAttribute(attn_tc<64>,   cudaFuncAttributeMaxDynamicSharedMemorySize, ATTN_SMEM_64);

    float *xw, *biasT;
    __half *h, *o, *m1, *hr, *orr, *qkv, *qkvr, *Wqkv, *Wout, *W1h, *W2h;
    cudaGetSymbolAddress((void**)&xw,   g_xw);
    cudaGetSymbolAddress((void**)&h,    g_h);
    cudaGetSymbolAddress((void**)&qkv,  g_qkv);
    cudaGetSymbolAddress((void**)&o,    g_o);
    cudaGetSymbolAddress((void**)&m1,   g_m1);
    cudaGetSymbolAddress((void**)&biasT,g_bias);
    cudaGetSymbolAddress((void**)&hr,   g_hr);
    cudaGetSymbolAddress((void**)&qkvr, g_qkvr);
    cudaGetSymbolAddress((void**)&orr,  g_or);
    cudaGetSymbolAddress((void**)&Wqkv, g_Wqkv);
    cudaGetSymbolAddress((void**)&Wout, g_Wout);
    cudaGetSymbolAddress((void**)&W1h,  g_W1h);
    cudaGetSymbolAddress((void**)&W2h,  g_W2h);

    pack_kernel<<<(NROWS*DIMV + 255)/256, 256>>>(local_t, region_t);
    wconv_all<<<(WTOT + BIAS_N + 255)/256, 256>>>(wqkv, wout, w1, w2, emb);

    for (int l = 0; l < DEPTH; l++) {
        __half* WqT = Wqkv + (size_t)l*SEG_QKV;
        __half* WoT = Wout + (size_t)l*SEG_OUT;
        __half* W1T = W1h + (size_t)l*SEG_W1;
        __half* W2T = W2h + (size_t)l*SEG_W2;
        const float* Bout = bout + (size_t)l*DIMV;
        const float* B1   = b1   + (size_t)l*4*DIMV;
        const float* B2   = b2   + (size_t)l*DIMV;
        const float* Ag   = attn_g + (size_t)l*DIMV;
        const float* Ab   = attn_b + (size_t)l*DIMV;
        const float* Mg   = mlp_g  + (size_t)l*DIMV;
        const float* Mb   = mlp_b  + (size_t)l*DIMV;

        // ---- region self-attention ----
        ln_half<<<NWIN, 128>>>(xw, NTOK*DIMV, Ag, Ab, hr);
        gemm_mma<<<dim3(3*DIMV/BN, NWIN/BM), 256, SMEM_GEMM>>>(
            hr, WqT, nullptr, nullptr, qkvr, 3*DIMV, DIMV, 3, 3*DIMV);
        attn_tc<64><<<NB, 256, ATTN_SMEM_64>>>(qkvr, nullptr, orr);
        gemm_mma<<<dim3(DIMV/BN, NWIN/BM), 256, SMEM_GEMM>>>(
            orr, WoT, Bout, xw, nullptr, DIMV, DIMV, 1, NTOK*DIMV);

        // ---- window attention ----
        ln_half<<<NROWS, 128>>>(xw, DIMV, Ag, Ab, h);
        gemm_mma<<<dim3(3*DIMV/BN, NROWS/BM), 256, SMEM_GEMM>>>(
            h, WqT, nullptr, nullptr, qkv, 3*DIMV, DIMV, 3, 3*DIMV);
        attn_tc<NTOK><<<NWIN, 256, ATTN_SMEM_65>>>(qkv, biasT, o);
        gemm_mma<<<dim3(DIMV/BN, NROWS/BM), 256, SMEM_GEMM>>>(
            o, WoT, Bout, xw, nullptr, DIMV, DIMV, 1, DIMV);

        // ---- MLP ----
        ln_half<<<NROWS, 128>>>(xw, DIMV, Mg, Mb, h);
        gemm_mma<<<dim3(4*DIMV/BN, NROWS/BM), 256, SMEM_GEMM>>>(
            h, W1T, B1, nullptr, m1, 4*DIMV, DIMV, 2, 4*DIMV);
        gemm_mma<<<dim3(DIMV/BN, NROWS/BM), 256, SMEM_GEMM>>>(
            m1, W2T, B2, xw, nullptr, DIMV, 4*DIMV, 1, DIMV);
    }

    unpack_kernel<<<(NROWS*DIMV + 255)/256, 256>>>(out);
}

// round 13
// speedup vs baseline: 3.4991x; 1.0109x over previous
#include <cuda_runtime.h>
#include <cuda_fp16.h>
#include <math.h>
#include <stdint.h>

// ---------------- Problem constants ----------------
#define DIMV    512
#define HEADS   16
#define DHEAD   32
#define NWIN    512          // B * RH * RW
#define NTOK    65           // 1 region + 64 local
#define NROWS   (NWIN*NTOK)  // 33280 (= 260 * 128)
#define NB      8
#define DEPTH   4
#define QSCALE  0.17677669529663687f
#define LOCAL_ELEMS (8*64*64*512)

// ---------------- helpers ----------------
__device__ __forceinline__ uint32_t smem_to_u32(const void* p) {
    uint32_t a;
    asm("{ .reg .u64 t; cvta.to.shared.u64 t, %1; cvt.u32.u64 %0, t; }" : "=r"(a) : "l"(p));
    return a;
}
__device__ __forceinline__ void cp16(uint32_t dst, const void* src) {
    asm volatile("cp.async.cg.shared.global [%0], [%1], 16;\n" :: "r"(dst), "l"(src));
}
__device__ __forceinline__ void cp_commit() { asm volatile("cp.async.commit_group;\n" ::: "memory"); }
__device__ __forceinline__ float gelu_exact(float x) {
    return 0.5f * x * (1.0f + erff(x * 0.70710678118654752f));
}
__device__ __forceinline__ uint32_t h2_u32(__half2 v) {
    return *(uint32_t*)&v;
}

// ================= Scratch (device globals) =================
__device__ __align__(16) float  g_xw  [NROWS*DIMV];
__device__ __align__(16) __half g_h   [NROWS*DIMV];
__device__ __align__(16) __half g_qkv [NROWS*3*DIMV];
__device__ __align__(16) __half g_o   [NROWS*DIMV];
__device__ __align__(16) __half g_m1  [NROWS*4*DIMV];
__device__ __align__(16) float  g_bias[HEADS*NTOK*NTOK];
__device__ __align__(16) __half g_hr  [NWIN*DIMV];
__device__ __align__(16) __half g_qkvr[NWIN*3*DIMV];
__device__ __align__(16) __half g_or  [NWIN*DIMV];
__device__ __align__(16) __half g_Wqkv[DEPTH*3*DIMV*DIMV];
__device__ __align__(16) __half g_Wout[DEPTH*DIMV*DIMV];
__device__ __align__(16) __half g_W1h [DEPTH*4*DIMV*DIMV];
__device__ __align__(16) __half g_W2h [DEPTH*DIMV*4*DIMV];

// ================= pack / unpack =================
__global__ void pack_kernel(const float* __restrict__ local_t, const float* __restrict__ region_t) {
    int idx = blockIdx.x * blockDim.x + threadIdx.x;
    if (idx >= NROWS*DIMV) return;
    int d = idx & 511, row = idx >> 9;
    int win = row / NTOK, t = row - win*NTOK;
    float v;
    if (t == 0) v = region_t[win*DIMV + d];
    else {
        int a = t - 1, p1 = a >> 3, p2 = a & 7;
        int b = win >> 6, rh = (win >> 3) & 7, rw = win & 7;
        v = local_t[(((b*64) + (rh*8 + p1))*64 + (rw*8 + p2))*DIMV + d];
    }
    g_xw[idx] = v;
}

__global__ void unpack_kernel(float* __restrict__ out) {
    int idx = blockIdx.x * blockDim.x + threadIdx.x;
    if (idx >= NROWS*DIMV) return;
    if (idx < LOCAL_ELEMS) {
        int d = idx & 511, p = idx >> 9;
        int col = p & 63, rowi = (p >> 6) & 63, b = p >> 12;
        int rh = rowi >> 3, p1 = rowi & 7, rw = col >> 3, p2 = col & 7;
        int win = b*64 + rh*8 + rw, t = 1 + p1*8 + p2;
        out[idx] = g_xw[(win*NTOK + t)*DIMV + d];
    } else {
        int r = idx - LOCAL_ELEMS, w = r >> 9, d = r & 511;
        out[idx] = g_xw[(w*NTOK)*DIMV + d];
    }
}

// ---- fused weight conversion + rel-pos bias ----
#define SEG_QKV (3*DIMV*DIMV)
#define SEG_OUT (DIMV*DIMV)
#define SEG_W1  (DIMV*4*DIMV)
#define SEG_W2  (4*DIMV*DIMV)
#define SEG_TOT (SEG_QKV+SEG_OUT+SEG_W1+SEG_W2)
#define WTOT    (DEPTH*SEG_TOT)
#define BIAS_N  (HEADS*NTOK*NTOK)

__global__ void wconv_all(const float* __restrict__ wqkv, const float* __restrict__ wout,
                          const float* __restrict__ w1, const float* __restrict__ w2,
                          const float* __restrict__ emb) {
    int idx = blockIdx.x * blockDim.x + threadIdx.x;
    if (idx < WTOT) {
        int l = idx / SEG_TOT;
        int r = idx - l*SEG_TOT;
        const float* W; __half* O; int K, N;
        if (r < SEG_QKV) {
            W = wqkv + (size_t)l*SEG_QKV; O = g_Wqkv + (size_t)l*SEG_QKV; K = DIMV; N = 3*DIMV;
        } else if (r < SEG_QKV + SEG_OUT) {
            r -= SEG_QKV;
            W = wout + (size_t)l*SEG_OUT; O = g_Wout + (size_t)l*SEG_OUT; K = DIMV; N = DIMV;
        } else if (r < SEG_QKV + SEG_OUT + SEG_W1) {
            r -= SEG_QKV + SEG_OUT;
            W = w1 + (size_t)l*SEG_W1; O = g_W1h + (size_t)l*SEG_W1; K = DIMV; N = 4*DIMV;
        } else {
            r -= SEG_QKV + SEG_OUT + SEG_W1;
            W = w2 + (size_t)l*SEG_W2; O = g_W2h + (size_t)l*SEG_W2; K = 4*DIMV; N = DIMV;
        }
        int n = r / K, k = r - n*K;
        O[(size_t)n*K + k] = __float2half_rn(W[(size_t)k*N + n]);
    } else {
        int r = idx - WTOT;
        if (r >= BIAS_N) return;
        int h = r / (NTOK*NTOK);
        int q = r - h*NTOK*NTOK;
        int i = q / NTOK, j = q - i*NTOK;
        float v = 0.f;
        if (i > 0 && j > 0) {
            int a = i - 1, b = j - 1;
            int r0 = (a >> 3) - (b >> 3) + 7;
            int r1 = (a & 7) - (b & 7) + 7;
            v = emb[(r0 + r1*15)*HEADS + h];
        }
        g_bias[r] = v;
    }
}

// ================= LayerNorm -> fp16, warp-per-row (8 rows / 256-thr block) =================
__global__ __launch_bounds__(256) void ln_half(const float* __restrict__ x, int instr,
                                               const float* __restrict__ g,
                                               const float* __restrict__ b,
                                               __half* __restrict__ y) {
    int w = threadIdx.x >> 5, lane = threadIdx.x & 31;
    int row = blockIdx.x*8 + w;
    const float4* xv = (const float4*)(x + (size_t)row*instr);
    float4 v[4];
    float s = 0.f, s2 = 0.f;
    #pragma unroll
    for (int i = 0; i < 4; i++) {
        v[i] = xv[lane + 32*i];
        s  += v[i].x + v[i].y + v[i].z + v[i].w;
        s2 += v[i].x*v[i].x + v[i].y*v[i].y + v[i].z*v[i].z + v[i].w*v[i].w;
    }
    #pragma unroll
    for (int off = 16; off; off >>= 1) {
        s  += __shfl_xor_sync(0xffffffffu, s,  off);
        s2 += __shfl_xor_sync(0xffffffffu, s2, off);
    }
    float mean = s * (1.f/512.f);
    float var  = s2 * (1.f/512.f) - mean*mean;
    float rstd = rsqrtf(var + 1e-3f);
    __half2* p = (__half2*)(y + (size_t)row*DIMV);
    #pragma unroll
    for (int i = 0; i < 4; i++) {
        float4 gg = ((const float4*)g)[lane + 32*i];
        float4 bb = ((const float4*)b)[lane + 32*i];
        __half2 o01 = __floats2half2_rn((v[i].x - mean)*rstd*gg.x + bb.x, (v[i].y - mean)*rstd*gg.y + bb.y);
        __half2 o23 = __floats2half2_rn((v[i].z - mean)*rstd*gg.z + bb.z, (v[i].w - mean)*rstd*gg.w + bb.w);
        p[(lane + 32*i)*2]     = o01;
        p[(lane + 32*i)*2 + 1] = o23;
    }
}

// ================= Tensor-core attention (R11 proven) =================
template<int NT>
__global__ __launch_bounds__(256) void attn_tc(const __half* __restrict__ qkv,
                                               const float* __restrict__ biasTab,
                                               __half* __restrict__ o) {
    constexpr int TOK_PAD = (NT + 15) & ~15;
    constexpr int ST = TOK_PAD / 8;
    constexpr int QB = TOK_PAD / 16;
    constexpr int KS = TOK_PAD / 16;
    constexpr int QROWB = 80, KROWB = 80, VROWB = TOK_PAD*2 + 16;
    constexpr int PW = TOK_PAD*QROWB + TOK_PAD*KROWB + 32*VROWB;
    extern __shared__ __align__(16) char smattn[];
    const int w = threadIdx.x >> 5, lane = threadIdx.x & 31;
    char* spq = smattn + w * PW;
    char* spk = spq + TOK_PAD*QROWB;
    char* spv = spk + TOK_PAD*KROWB;
    const uint32_t uq = smem_to_u32(spq);
    const uint32_t uk = smem_to_u32(spk);
    const uint32_t uv = smem_to_u32(spv);
    const int tokbase = blockIdx.x * NT;
    const int g = lane >> 2, tig = lane & 3;

    for (int hh = 0; hh < 2; hh++) {
        const int h = w*2 + hh;
        for (int p = lane; p < NT*16; p += 32) {
            int tok = p >> 4, d2 = p & 15;
            const __half2* src = (const __half2*)(qkv + (size_t)(tokbase + tok)*(3*DIMV) + h*DHEAD + d2*2);
            __half2 qv = src[0];
            float2 qf = __half22float2(qv);
            *(__half2*)(spq + tok*QROWB + d2*4) = __floats2half2_rn(qf.x*QSCALE, qf.y*QSCALE);
            *(__half2*)(spk + tok*KROWB + d2*4) = src[DIMV/2];
            __half2 vv = src[DIMV];
            *(__half*)(spv + (2*d2)*VROWB   + tok*2) = __low2half(vv);
            *(__half*)(spv + (2*d2+1)*VROWB + tok*2) = __high2half(vv);
        }
        if (TOK_PAD > NT) {
            for (int p = lane; p < 32*(TOK_PAD - NT); p += 32) {
                int d = p / (TOK_PAD - NT), c = p - d*(TOK_PAD - NT);
                *(__half*)(spv + d*VROWB + (NT + c)*2) = __ushort_as_half(0);
            }
        }
        __syncwarp();

        for (int qb = 0; qb < QB; qb++) {
            uint32_t afr[2][4];
            #pragma unroll
            for (int kk = 0; kk < 2; kk++) {
                uint32_t addr = uq + (qb*16 + (lane & 15))*QROWB + (lane >> 4)*16 + kk*32;
                asm volatile("ldmatrix.sync.aligned.m8n8.x4.shared.b16 {%0,%1,%2,%3}, [%4];"
                    : "=r"(afr[kk][0]), "=r"(afr[kk][1]), "=r"(afr[kk][2]), "=r"(afr[kk][3]) : "r"(addr));
            }
            float s[ST][4];
            #pragma unroll
            for (int t = 0; t < ST; t++) { s[t][0]=0.f; s[t][1]=0.f; s[t][2]=0.f; s[t][3]=0.f; }
            #pragma unroll
            for (int t = 0; t < ST; t++) {
                #pragma unroll
                for (int kk = 0; kk < 2; kk++) {
                    uint32_t b[2];
                    uint32_t addr = uk + (t*8 + (lane & 7))*KROWB + ((lane >> 3) & 1)*16 + kk*32;
                    asm volatile("ldmatrix.sync.aligned.m8n8.x2.shared.b16 {%0,%1}, [%2];"
                        : "=r"(b[0]), "=r"(b[1]) : "r"(addr));
                    asm volatile(
                        "mma.sync.aligned.m16n8k16.row.col.f32.f16.f16.f32 "
                        "{%0,%1,%2,%3}, {%4,%5,%6,%7}, {%8,%9}, {%0,%1,%2,%3};"
                        : "+f"(s[t][0]), "+f"(s[t][1]), "+f"(s[t][2]), "+f"(s[t][3])
                        : "r"(afr[kk][0]), "r"(afr[kk][1]), "r"(afr[kk][2]), "r"(afr[kk][3]),
                          "r"(b[0]), "r"(b[1]));
                }
            }
            const int row0 = qb*16 + g;
            #pragma unroll
            for (int t = 0; t < ST; t++) {
                int c0 = t*8 + tig*2;
                if (biasTab) {
                    if (row0 < NT) {
                        if (c0 < NT)     s[t][0] += biasTab[(h*NT + row0)*NT + c0];
                        if (c0 + 1 < NT) s[t][1] += biasTab[(h*NT + row0)*NT + c0 + 1];
                    }
                    if (row0 + 8 < NT) {
                        if (c0 < NT)     s[t][2] += biasTab[(h*NT + row0 + 8)*NT + c0];
                        if (c0 + 1 < NT) s[t][3] += biasTab[(h*NT + row0 + 8)*NT + c0 + 1];
                    }
                }
                if (c0 >= NT)     { s[t][0] = -1e30f; s[t][2] = -1e30f; }
                if (c0 + 1 >= NT) { s[t][1] = -1e30f; s[t][3] = -1e30f; }
            }
            float m0 = -1e30f, m1 = -1e30f;
            #pragma unroll
            for (int t = 0; t < ST; t++) {
                m0 = fmaxf(m0, fmaxf(s[t][0], s[t][1]));
                m1 = fmaxf(m1, fmaxf(s[t][2], s[t][3]));
            }
            m0 = fmaxf(m0, __shfl_xor_sync(0xffffffffu, m0, 1));
            m0 = fmaxf(m0, __shfl_xor_sync(0xffffffffu, m0, 2));
            m1 = fmaxf(m1, __shfl_xor_sync(0xffffffffu, m1, 1));
            m1 = fmaxf(m1, __shfl_xor_sync(0xffffffffu, m1, 2));
            float sum0 = 0.f, sum1 = 0.f;
            #pragma unroll
            for (int t = 0; t < ST; t++) {
                s[t][0] = __expf(s[t][0] - m0); s[t][1] = __expf(s[t][1] - m0);
                s[t][2] = __expf(s[t][2] - m1); s[t][3] = __expf(s[t][3] - m1);
                sum0 += s[t][0] + s[t][1];
                sum1 += s[t][2] + s[t][3];
            }
            sum0 += __shfl_xor_sync(0xffffffffu, sum0, 1);
            sum0 += __shfl_xor_sync(0xffffffffu, sum0, 2);
            sum1 += __shfl_xor_sync(0xffffffffu, sum1, 1);
            sum1 += __shfl_xor_sync(0xffffffffu, sum1, 2);
            float inv0 = 1.f / sum0, inv1 = 1.f / sum1;
            uint32_t pa[KS][4];
            #pragma unroll
            for (int ph = 0; ph < KS; ph++) {
                int t0 = 2*ph, t1 = 2*ph + 1;
                pa[ph][0] = h2_u32(__floats2half2_rn(s[t0][0]*inv0, s[t0][1]*inv0));
                pa[ph][1] = h2_u32(__floats2half2_rn(s[t0][2]*inv1, s[t0][3]*inv1));
                pa[ph][2] = h2_u32(__floats2half2_rn(s[t1][0]*inv0, s[t1][1]*inv0));
                pa[ph][3] = h2_u32(__floats2half2_rn(s[t1][2]*inv1, s[t1][3]*inv1));
            }
            float oa[4][4];
            #pragma unroll
            for (int nt = 0; nt < 4; nt++) { oa[nt][0]=0.f; oa[nt][1]=0.f; oa[nt][2]=0.f; oa[nt][3]=0.f; }
            #pragma unroll
            for (int ksi = 0; ksi < KS; ksi++) {
                #pragma unroll
                for (int nt = 0; nt < 4; nt++) {
                    uint32_t b[2];
                    uint32_t addr = uv + (nt*8 + (lane & 7))*VROWB + (ksi*16 + ((lane >> 3) & 1)*8)*2;
                    asm volatile("ldmatrix.sync.aligned.m8n8.x2.shared.b16 {%0,%1}, [%2];"
                        : "=r"(b[0]), "=r"(b[1]) : "r"(addr));
                    asm volatile(
                        "mma.sync.aligned.m16n8k16.row.col.f32.f16.f16.f32 "
                        "{%0,%1,%2,%3}, {%4,%5,%6,%7}, {%8,%9}, {%0,%1,%2,%3};"
                        : "+f"(oa[nt][0]), "+f"(oa[nt][1]), "+f"(oa[nt][2]), "+f"(oa[nt][3])
                        : "r"(pa[ksi][0]), "r"(pa[ksi][1]), "r"(pa[ksi][2]), "r"(pa[ksi][3]),
                          "r"(b[0]), "r"(b[1]));
                }
            }
            if (row0 < NT) {
                #pragma unroll
                for (int nt = 0; nt < 4; nt++)
                    *(__half2*)&o[(size_t)(tokbase + row0)*DIMV + h*DHEAD + nt*8 + tig*2] =
                        __floats2half2_rn(oa[nt][0], oa[nt][1]);
            }
            if (row0 + 8 < NT) {
                #pragma unroll
                for (int nt = 0; nt < 4; nt++)
                    *(__half2*)&o[(size_t)(tokbase + row0 + 8)*DIMV + h*DHEAD + nt*8 + tig*2] =
                        __floats2half2_rn(oa[nt][2], oa[nt][3]);
            }
        }
        __syncwarp();
    }
}

#define ATTN_SMEM_65 (8 * ((80*80) + (80*80) + 32*(80*2+16)))   // 147456
#define ATTN_SMEM_64 (8 * ((64*80) + (64*80) + 32*(64*2+16)))   // 118784

// ================= fp16 GEMM via mma.sync (R10/R11 proven: BK=64, 3-stage, 64x32 warps) =================
#define BM 128
#define BN 128
#define BK 64
#define NSTG 3
#define ROWB 144
#define STG_BYTES ((BM + BN) * ROWB)
#define SMEM_GEMM (NSTG * STG_BYTES)

__global__ __launch_bounds__(256, 2) void gemm_mma(
    const __half* __restrict__ A, const __half* __restrict__ B,
    const float* __restrict__ bias, float* __restrict__ C,
    __half* __restrict__ Oh, int N, int K, int epi, int cs)
{
    extern __shared__ char smem[];
    const uint32_t sb = smem_to_u32(smem);
    const int tid = threadIdx.x;
    const int bm = blockIdx.y * BM;
    const int bn = blockIdx.x * BN;
    const int total = K / BK;

    const int wid = tid >> 5, lane = tid & 31;
    const int wm = wid & 1, wn = wid >> 1;

    float acc[4][4][4];
    #pragma unroll
    for (int mi = 0; mi < 4; mi++)
        #pragma unroll
        for (int ni = 0; ni < 4; ni++)
            #pragma unroll
            for (int r = 0; r < 4; r++) acc[mi][ni][r] = 0.f;

    auto load_chunk = [&](int c) {
        int col = c*BK;
        uint32_t stA = sb + (c % NSTG) * STG_BYTES;
        uint32_t stB = stA + BM * ROWB;
        #pragma unroll
        for (int i = 0; i < 4; i++) {
            int s = tid + i*256;
            int row = s >> 3, seg = s & 7;
            cp16(stA + row*ROWB + seg*16, A + (size_t)(bm + row)*K + col + seg*8);
            cp16(stB + row*ROWB + seg*16, B + (size_t)(bn + row)*K + col + seg*8);
        }
        cp_commit();
    };

    load_chunk(0);
    load_chunk(1);

    for (int c = 0; c < total; c++) {
        if (c == total - 1) asm volatile("cp.async.wait_group 0;\n" ::: "memory");
        else                asm volatile("cp.async.wait_group 1;\n" ::: "memory");
        __syncthreads();
        if (c + 2 < total) load_chunk(c + 2);

        uint32_t stA = sb + (c % NSTG) * STG_BYTES;
        uint32_t stB = stA + BM * ROWB;
        #pragma unroll
        for (int ks = 0; ks < 4; ks++) {
            uint32_t a[4][4];
            #pragma unroll
            for (int mi = 0; mi < 4; mi++) {
                uint32_t addr = stA + (wm*64 + mi*16 + (lane & 15))*ROWB + ((lane >> 4)*16 + ks*32);
                asm volatile("ldmatrix.sync.aligned.m8n8.x4.shared.b16 {%0,%1,%2,%3}, [%4];"
                    : "=r"(a[mi][0]), "=r"(a[mi][1]), "=r"(a[mi][2]), "=r"(a[mi][3]) : "r"(addr));
            }
            uint32_t b[4][2];
            #pragma unroll
            for (int ni = 0; ni < 4; ni++) {
                uint32_t addr = stB + (wn*32 + ni*8 + (lane & 7))*ROWB + (((lane >> 3) & 1)*16 + ks*32);
                asm volatile("ldmatrix.sync.aligned.m8n8.x2.shared.b16 {%0,%1}, [%2];"
                    : "=r"(b[ni][0]), "=r"(b[ni][1]) : "r"(addr));
            }
            #pragma unroll
            for (int mi = 0; mi < 4; mi++)
                #pragma unroll
                for (int ni = 0; ni < 4; ni++) {
                    asm volatile(
                        "mma.sync.aligned.m16n8k16.row.col.f32.f16.f16.f32 "
                        "{%0,%1,%2,%3}, {%4,%5,%6,%7}, {%8,%9}, {%0,%1,%2,%3};"
                        : "+f"(acc[mi][ni][0]), "+f"(acc[mi][ni][1]),
                          "+f"(acc[mi][ni][2]), "+f"(acc[mi][ni][3])
                        : "r"(a[mi][0]), "r"(a[mi][1]), "r"(a[mi][2]), "r"(a[mi][3]),
                          "r"(b[ni][0]), "r"(b[ni][1]));
                }
        }
    }

    // ---- epilogue ----
    const int g = lane >> 2, tig = lane & 3;
    #pragma unroll
    for (int mi = 0; mi < 4; mi++) {
        #pragma unroll
        for (int ni = 0; ni < 4; ni++) {
            int r0 = bm + wm*64 + mi*16 + g;
            int cc = bn + wn*32 + ni*8 + tig*2;
            #pragma unroll
            for (int half = 0; half < 2; half++) {
                int r = r0 + half*8;
                float v0 = acc[mi][ni][half*2 + 0];
                float v1 = acc[mi][ni][half*2 + 1];
                if (epi == 0) {
                    float2 st; st.x = v0; st.y = v1;
                    *(float2*)&C[(size_t)r*cs + cc] = st;
                } else if (epi == 1) {
                    float2 bi  = *(const float2*)&bias[cc];
                    float2 res = *(const float2*)&C[(size_t)r*cs + cc];
                    float2 st; st.x = v0 + bi.x + res.x; st.y = v1 + bi.y + res.y;
                    *(float2*)&C[(size_t)r*cs + cc] = st;
                } else if (epi == 2) {
                    float2 bi = *(const float2*)&bias[cc];
                    float g0 = gelu_exact(v0 + bi.x);
                    float g1 = gelu_exact(v1 + bi.y);
                    *(__half2*)&Oh[(size_t)r*cs + cc] = __floats2half2_rn(g0, g1);
                } else {
                    *(__half2*)&Oh[(size_t)r*cs + cc] = __floats2half2_rn(v0, v1);
                }
            }
        }
    }
}

// ================= Host driver =================
extern "C" void kernel_launch(void* const* d_in, const int* in_sizes, int n_in,
                              void* d_out, int out_size) {
    const float* local_t  = (const float*)d_in[0];
    const float* region_t = (const float*)d_in[1];
    const float* emb      = (const float*)d_in[2];
    const float* attn_g   = (const float*)d_in[3];
    const float* attn_b   = (const float*)d_in[4];
    const float* wqkv     = (const float*)d_in[5];
    const float* wout     = (const float*)d_in[6];
    const float* bout     = (const float*)d_in[7];
    const float* mlp_g    = (const float*)d_in[8];
    const float* mlp_b    = (const float*)d_in[9];
    const float* w1       = (const float*)d_in[10];
    const float* b1       = (const float*)d_in[11];
    const float* w2       = (const float*)d_in[12];
    const float* b2       = (const float*)d_in[13];
    float* out = (float*)d_out;

    cudaFuncSetAttribute(gemm_mma, cudaFuncAttributeMaxDynamicSharedMemorySize, SMEM_GEMM);
    cudaFuncSetAttribute(attn_tc<NTOK>, cudaFuncAttributeMaxDynamicSharedMemorySize, ATTN_SMEM_65);
    cudaFuncSetAttribute(attn_tc<64>,   cudaFuncAttributeMaxDynamicSharedMemorySize, ATTN_SMEM_64);

    float *xw, *biasT;
    __half *h, *o, *m1, *hr, *orr, *qkv, *qkvr, *Wqkv, *Wout, *W1h, *W2h;
    cudaGetSymbolAddress((void**)&xw,   g_xw);
    cudaGetSymbolAddress((void**)&h,    g_h);
    cudaGetSymbolAddress((void**)&qkv,  g_qkv);
    cudaGetSymbolAddress((void**)&o,    g_o);
    cudaGetSymbolAddress((void**)&m1,   g_m1);
    cudaGetSymbolAddress((void**)&biasT,g_bias);
    cudaGetSymbolAddress((void**)&hr,   g_hr);
    cudaGetSymbolAddress((void**)&qkvr, g_qkvr);
    cudaGetSymbolAddress((void**)&orr,  g_or);
    cudaGetSymbolAddress((void**)&Wqkv, g_Wqkv);
    cudaGetSymbolAddress((void**)&Wout, g_Wout);
    cudaGetSymbolAddress((void**)&W1h,  g_W1h);
    cudaGetSymbolAddress((void**)&W2h,  g_W2h);

    pack_kernel<<<(NROWS*DIMV + 255)/256, 256>>>(local_t, region_t);
    wconv_all<<<(WTOT + BIAS_N + 255)/256, 256>>>(wqkv, wout, w1, w2, emb);

    for (int l = 0; l < DEPTH; l++) {
        __half* WqT = Wqkv + (size_t)l*SEG_QKV;
        __half* WoT = Wout + (size_t)l*SEG_OUT;
        __half* W1T = W1h + (size_t)l*SEG_W1;
        __half* W2T = W2h + (size_t)l*SEG_W2;
        const float* Bout = bout + (size_t)l*DIMV;
        const float* B1   = b1   + (size_t)l*4*DIMV;
        const float* B2   = b2   + (size_t)l*DIMV;
        const float* Ag   = attn_g + (size_t)l*DIMV;
        const float* Ab   = attn_b + (size_t)l*DIMV;
        const float* Mg   = mlp_g  + (size_t)l*DIMV;
        const float* Mb   = mlp_b  + (size_t)l*DIMV;

        // ---- region self-attention ----
        ln_half<<<NWIN/8, 256>>>(xw, NTOK*DIMV, Ag, Ab, hr);
        gemm_mma<<<dim3(3*DIMV/BN, NWIN/BM), 256, SMEM_GEMM>>>(
            hr, WqT, nullptr, nullptr, qkvr, 3*DIMV, DIMV, 3, 3*DIMV);
        attn_tc<64><<<NB, 256, ATTN_SMEM_64>>>(qkvr, nullptr, orr);
        gemm_mma<<<dim3(DIMV/BN, NWIN/BM), 256, SMEM_GEMM>>>(
            orr, WoT, Bout, xw, nullptr, DIMV, DIMV, 1, NTOK*DIMV);

        // ---- window attention ----
        ln_half<<<NROWS/8, 256>>>(xw, DIMV, Ag, Ab, h);
        gemm_mma<<<dim3(3*DIMV/BN, NROWS/BM), 256, SMEM_GEMM>>>(
            h, WqT, nullptr, nullptr, qkv, 3*DIMV, DIMV, 3, 3*DIMV);
        attn_tc<NTOK><<<NWIN, 256, ATTN_SMEM_65>>>(qkv, biasT, o);
        gemm_mma<<<dim3(DIMV/BN, NROWS/BM), 256, SMEM_GEMM>>>(
            o, WoT, Bout, xw, nullptr, DIMV, DIMV, 1, DIMV);

        // ---- MLP ----
        ln_half<<<NROWS/8, 256>>>(xw, DIMV, Mg, Mb, h);
        gemm_mma<<<dim3(4*DIMV/BN, NROWS/BM), 256, SMEM_GEMM>>>(
            h, W1T, B1, nullptr, m1, 4*DIMV, DIMV, 2, 4*DIMV);
        gemm_mma<<<dim3(DIMV/BN, NROWS/BM), 256, SMEM_GEMM>>>(
            m1, W2T, B2, xw, nullptr, DIMV, 4*DIMV, 1, DIMV);
    }

    unpack_kernel<<<(NROWS*DIMV + 255)/256, 256>>>(out);
}